// round 1
// baseline (speedup 1.0000x reference)
#include <cuda_runtime.h>
#include <math.h>

#define B_  4
#define S_  1024
#define D_  768
#define H_  12
#define L_  6
#define DF_ 3072
#define DH_ 64
#define NT_ (B_*S_)        // 4096 rows
#define D3_ (3*D_)         // 2304

// ---------------- scratch (static device globals; no allocation) -------------
static __device__ float g_h[NT_*D_];
static __device__ float g_a[NT_*D_];
static __device__ float g_qkv[NT_*D3_];
static __device__ float g_scores[(size_t)B_*H_*S_*S_];   // [48,1024,1024] ~201MB
static __device__ float g_o[NT_*D_];
static __device__ float g_mlp[NT_*DF_];

// ---------------- embedding --------------------------------------------------
__global__ void embed_kernel(const int* __restrict__ ids, const int* __restrict__ rfi,
                             const float* __restrict__ wte, const float* __restrict__ wte_rf,
                             const float* __restrict__ wpe, float* __restrict__ out) {
    int row = blockIdx.x;
    int s = row & (S_ - 1);
    const float* e1 = wte    + (size_t)ids[row] * D_;
    const float* e2 = wte_rf + (size_t)rfi[row] * D_;
    const float* e3 = wpe    + (size_t)s * D_;
    float* o = out + (size_t)row * D_;
    for (int d = threadIdx.x; d < D_; d += blockDim.x)
        o[d] = e1[d] + e2[d] + e3[d];
}

// ---------------- layernorm (two-pass, matches reference) --------------------
__global__ void ln_kernel(const float* __restrict__ x, const float* __restrict__ g,
                          const float* __restrict__ b, float* __restrict__ y) {
    int row = blockIdx.x;
    int t = threadIdx.x;                       // 256 threads, 3 elems each (D=768)
    const float* xr = x + (size_t)row * D_;
    float v0 = xr[t], v1 = xr[t + 256], v2 = xr[t + 512];
    __shared__ float red[256];
    red[t] = v0 + v1 + v2;
    __syncthreads();
    for (int o = 128; o > 0; o >>= 1) { if (t < o) red[t] += red[t + o]; __syncthreads(); }
    float mu = red[0] * (1.0f / D_);
    __syncthreads();
    float d0 = v0 - mu, d1 = v1 - mu, d2 = v2 - mu;
    red[t] = d0*d0 + d1*d1 + d2*d2;
    __syncthreads();
    for (int o = 128; o > 0; o >>= 1) { if (t < o) red[t] += red[t + o]; __syncthreads(); }
    float inv = rsqrtf(red[0] * (1.0f / D_) + 1e-5f);
    float* yr = y + (size_t)row * D_;
    yr[t]       = d0 * inv * g[t]       + b[t];
    yr[t + 256] = d1 * inv * g[t + 256] + b[t + 256];
    yr[t + 512] = d2 * inv * g[t + 512] + b[t + 512];
}

// ---------------- generic SGEMM: C = act(A@W + bias) (+resid) ----------------
__device__ __forceinline__ float gelu_f(float x) {
    const float c = 0.7978845608028654f;
    return 0.5f * x * (1.0f + tanhf(c * (x + 0.044715f * x * x * x)));
}

template<bool GELU, bool RESID>
__global__ void gemm_kernel(const float* __restrict__ A, const float* __restrict__ W,
                            const float* __restrict__ bias, const float* __restrict__ resid,
                            float* __restrict__ C, int M, int N, int K) {
    __shared__ float As[16][64];
    __shared__ float Bs[16][64];
    int tid = threadIdx.x;
    int tx = tid & 15, ty = tid >> 4;
    int m0 = blockIdx.y << 6, n0 = blockIdx.x << 6;
    float acc[4][4] = {};
    int ar = tid >> 2, ac4 = (tid & 3) << 2;    // A: 64 rows x 16 cols, float4 per thread
    int br = tid >> 4, bc4 = (tid & 15) << 2;   // W: 16 rows x 64 cols
    const float* Ap = A + (size_t)(m0 + ar) * K + ac4;
    const float* Wp = W + (size_t)br * N + n0 + bc4;
    for (int k0 = 0; k0 < K; k0 += 16) {
        float4 av = *(const float4*)(Ap + k0);
        As[ac4+0][ar] = av.x; As[ac4+1][ar] = av.y; As[ac4+2][ar] = av.z; As[ac4+3][ar] = av.w;
        float4 bv = *(const float4*)(Wp + (size_t)k0 * N);
        *(float4*)&Bs[br][bc4] = bv;
        __syncthreads();
        #pragma unroll
        for (int kk = 0; kk < 16; kk++) {
            float a[4], bb[4];
            *(float4*)a  = *(const float4*)&As[kk][ty << 2];
            *(float4*)bb = *(const float4*)&Bs[kk][tx << 2];
            #pragma unroll
            for (int i = 0; i < 4; i++)
                #pragma unroll
                for (int j = 0; j < 4; j++)
                    acc[i][j] += a[i] * bb[j];
        }
        __syncthreads();
    }
    #pragma unroll
    for (int i = 0; i < 4; i++) {
        int m = m0 + (ty << 2) + i;
        #pragma unroll
        for (int j = 0; j < 4; j++) {
            int n = n0 + (tx << 2) + j;
            float v = acc[i][j] + bias[n];
            if (GELU)  v = gelu_f(v);
            if (RESID) v += resid[(size_t)m * N + n];
            C[(size_t)m * N + n] = v;
        }
    }
}

// ---------------- attention: scores = mask(Q @ K^T / 8) ----------------------
__global__ void attn_score_kernel(const float* __restrict__ qkv, float* __restrict__ scores) {
    int bh = blockIdx.z;
    int b = bh / H_, h = bh % H_;
    int m0 = blockIdx.y << 6;   // q tile
    int n0 = blockIdx.x << 6;   // k tile
    float* C = scores + (size_t)bh * S_ * S_;
    int tid = threadIdx.x;
    int tx = tid & 15, ty = tid >> 4;
    if (n0 > m0 + 63) {         // fully masked tile: write -1e4 and exit
        #pragma unroll
        for (int i = 0; i < 4; i++) {
            int m = m0 + (ty << 2) + i;
            float4 val = make_float4(-1e4f, -1e4f, -1e4f, -1e4f);
            *(float4*)&C[(size_t)m * S_ + n0 + (tx << 2)] = val;
        }
        return;
    }
    const float* Q  = qkv + (size_t)b * S_ * D3_ + (size_t)h * DH_;
    const float* Kp = qkv + (size_t)b * S_ * D3_ + D_ + (size_t)h * DH_;
    __shared__ float As[16][64];
    __shared__ float Bs[16][64];
    float acc[4][4] = {};
    int ar = tid >> 2, ac4 = (tid & 3) << 2;
    int bc = tid >> 2, br4 = (tid & 3) << 2;   // trans-B load: addr = (n0+bc)*ld + k + br4
    for (int k0 = 0; k0 < DH_; k0 += 16) {
        float4 av = *(const float4*)&Q[(size_t)(m0 + ar) * D3_ + k0 + ac4];
        As[ac4+0][ar] = av.x; As[ac4+1][ar] = av.y; As[ac4+2][ar] = av.z; As[ac4+3][ar] = av.w;
        float4 bv = *(const float4*)&Kp[(size_t)(n0 + bc) * D3_ + k0 + br4];
        Bs[br4+0][bc] = bv.x; Bs[br4+1][bc] = bv.y; Bs[br4+2][bc] = bv.z; Bs[br4+3][bc] = bv.w;
        __syncthreads();
        #pragma unroll
        for (int kk = 0; kk < 16; kk++) {
            float a[4], bb[4];
            *(float4*)a  = *(const float4*)&As[kk][ty << 2];
            *(float4*)bb = *(const float4*)&Bs[kk][tx << 2];
            #pragma unroll
            for (int i = 0; i < 4; i++)
                #pragma unroll
                for (int j = 0; j < 4; j++)
                    acc[i][j] += a[i] * bb[j];
        }
        __syncthreads();
    }
    #pragma unroll
    for (int i = 0; i < 4; i++) {
        int m = m0 + (ty << 2) + i;
        #pragma unroll
        for (int j = 0; j < 4; j++) {
            int n = n0 + (tx << 2) + j;
            C[(size_t)m * S_ + n] = (n <= m) ? acc[i][j] * 0.125f : -1e4f;
        }
    }
}

// ---------------- softmax over last dim (1024) -------------------------------
__global__ void softmax_kernel(float* __restrict__ scores) {
    int row = blockIdx.x;                       // B*H*S rows
    float* x = scores + (size_t)row * S_;
    int t = threadIdx.x;
    float v[4];
    float mx = -1e30f;
    #pragma unroll
    for (int i = 0; i < 4; i++) { v[i] = x[t + (i << 8)]; mx = fmaxf(mx, v[i]); }
    __shared__ float red[256];
    red[t] = mx;
    __syncthreads();
    for (int o = 128; o > 0; o >>= 1) { if (t < o) red[t] = fmaxf(red[t], red[t + o]); __syncthreads(); }
    mx = red[0];
    __syncthreads();
    float s = 0.f;
    #pragma unroll
    for (int i = 0; i < 4; i++) { v[i] = expf(v[i] - mx); s += v[i]; }
    red[t] = s;
    __syncthreads();
    for (int o = 128; o > 0; o >>= 1) { if (t < o) red[t] += red[t + o]; __syncthreads(); }
    float inv = 1.0f / red[0];
    #pragma unroll
    for (int i = 0; i < 4; i++) x[t + (i << 8)] = v[i] * inv;
}

// ---------------- attention: O = P @ V (causal K-loop truncation) ------------
__global__ void attn_pv_kernel(const float* __restrict__ qkv, const float* __restrict__ scores,
                               float* __restrict__ out) {
    int bh = blockIdx.z;
    int b = bh / H_, h = bh % H_;
    int m0 = blockIdx.y << 6;
    const float* P = scores + (size_t)bh * S_ * S_;
    const float* V = qkv + (size_t)b * S_ * D3_ + 2 * D_ + (size_t)h * DH_;
    float* C = out + (size_t)b * S_ * D_ + (size_t)h * DH_;
    __shared__ float As[16][64];
    __shared__ float Bs[16][64];
    int tid = threadIdx.x;
    int tx = tid & 15, ty = tid >> 4;
    float acc[4][4] = {};
    int ar = tid >> 2, ac4 = (tid & 3) << 2;
    int br = tid >> 4, bc4 = (tid & 15) << 2;
    int kend = m0 + 64;    // probs are exactly 0 beyond the causal boundary
    for (int k0 = 0; k0 < kend; k0 += 16) {
        float4 av = *(const float4*)&P[(size_t)(m0 + ar) * S_ + k0 + ac4];
        As[ac4+0][ar] = av.x; As[ac4+1][ar] = av.y; As[ac4+2][ar] = av.z; As[ac4+3][ar] = av.w;
        float4 bv = *(const float4*)&V[(size_t)(k0 + br) * D3_ + bc4];
        *(float4*)&Bs[br][bc4] = bv;
        __syncthreads();
        #pragma unroll
        for (int kk = 0; kk < 16; kk++) {
            float a[4], bb[4];
            *(float4*)a  = *(const float4*)&As[kk][ty << 2];
            *(float4*)bb = *(const float4*)&Bs[kk][tx << 2];
            #pragma unroll
            for (int i = 0; i < 4; i++)
                #pragma unroll
                for (int j = 0; j < 4; j++)
                    acc[i][j] += a[i] * bb[j];
        }
        __syncthreads();
    }
    #pragma unroll
    for (int i = 0; i < 4; i++) {
        int m = m0 + (ty << 2) + i;
        #pragma unroll
        for (int j = 0; j < 4; j++)
            C[(size_t)m * D_ + (tx << 2) + j] = acc[i][j];
    }
}

// ---------------- host orchestration -----------------------------------------
extern "C" void kernel_launch(void* const* d_in, const int* in_sizes, int n_in,
                              void* d_out, int out_size) {
    const int*   ids    = (const int*)d_in[0];
    const int*   rfi    = (const int*)d_in[1];
    const float* wte    = (const float*)d_in[2];
    const float* wte_rf = (const float*)d_in[3];
    const float* wpe    = (const float*)d_in[4];
    const float* ln1_g  = (const float*)d_in[5];
    const float* ln1_b  = (const float*)d_in[6];
    const float* attn_w = (const float*)d_in[7];
    const float* attn_b = (const float*)d_in[8];
    const float* proj_w = (const float*)d_in[9];
    const float* proj_b = (const float*)d_in[10];
    const float* ln2_g  = (const float*)d_in[11];
    const float* ln2_b  = (const float*)d_in[12];
    const float* fc_w   = (const float*)d_in[13];
    const float* fc_b   = (const float*)d_in[14];
    const float* fc2_w  = (const float*)d_in[15];
    const float* fc2_b  = (const float*)d_in[16];
    const float* lnf_g  = (const float*)d_in[17];
    const float* lnf_b  = (const float*)d_in[18];
    float* out = (float*)d_out;

    float *h, *a, *qkv, *sc, *o, *mlp;
    cudaGetSymbolAddress((void**)&h,   g_h);
    cudaGetSymbolAddress((void**)&a,   g_a);
    cudaGetSymbolAddress((void**)&qkv, g_qkv);
    cudaGetSymbolAddress((void**)&sc,  g_scores);
    cudaGetSymbolAddress((void**)&o,   g_o);
    cudaGetSymbolAddress((void**)&mlp, g_mlp);

    embed_kernel<<<NT_, 256>>>(ids, rfi, wte, wte_rf, wpe, h);

    for (int l = 0; l < L_; l++) {
        ln_kernel<<<NT_, 256>>>(h, ln1_g + l * D_, ln1_b + l * D_, a);
        gemm_kernel<false, false><<<dim3(D3_/64, NT_/64), 256>>>(
            a, attn_w + (size_t)l * D_ * D3_, attn_b + l * D3_, nullptr, qkv, NT_, D3_, D_);
        attn_score_kernel<<<dim3(S_/64, S_/64, B_*H_), 256>>>(qkv, sc);
        softmax_kernel<<<B_*H_*S_, 256>>>(sc);
        attn_pv_kernel<<<dim3(1, S_/64, B_*H_), 256>>>(qkv, sc, o);
        gemm_kernel<false, true><<<dim3(D_/64, NT_/64), 256>>>(
            o, proj_w + (size_t)l * D_ * D_, proj_b + l * D_, h, h, NT_, D_, D_);
        ln_kernel<<<NT_, 256>>>(h, ln2_g + l * D_, ln2_b + l * D_, a);
        gemm_kernel<true, false><<<dim3(DF_/64, NT_/64), 256>>>(
            a, fc_w + (size_t)l * D_ * DF_, fc_b + l * DF_, nullptr, mlp, NT_, DF_, D_);
        gemm_kernel<false, true><<<dim3(D_/64, NT_/64), 256>>>(
            mlp, fc2_w + (size_t)l * DF_ * D_, fc2_b + l * D_, h, h, NT_, D_, DF_);
    }
    ln_kernel<<<NT_, 256>>>(h, lnf_g, lnf_b, out);
}

// round 3
// speedup vs baseline: 1.8536x; 1.8536x over previous
#include <cuda_runtime.h>
#include <cuda_bf16.h>
#include <math.h>
#include <stdint.h>

#define B_  4
#define S_  1024
#define D_  768
#define H_  12
#define L_  6
#define DF_ 3072
#define DH_ 64
#define NT_ (B_*S_)        // 4096
#define D3_ (3*D_)         // 2304

// ---------------- scratch (static device globals) ----------------------------
static __device__ float g_h[NT_*D_];
static __device__ float g_qkv[NT_*D3_];
static __device__ float g_scores[(size_t)B_*H_*S_*S_];
static __device__ __nv_bfloat16 g_ah[NT_*D_],  g_al[NT_*D_];
static __device__ __nv_bfloat16 g_mh[NT_*DF_], g_ml[NT_*DF_];
static __device__ __nv_bfloat16 g_oh[NT_*D_],  g_ol[NT_*D_];
static __device__ __nv_bfloat16 t_attn_h[(size_t)L_*D3_*D_], t_attn_l[(size_t)L_*D3_*D_];
static __device__ __nv_bfloat16 t_proj_h[(size_t)L_*D_*D_],  t_proj_l[(size_t)L_*D_*D_];
static __device__ __nv_bfloat16 t_fc_h[(size_t)L_*DF_*D_],   t_fc_l[(size_t)L_*DF_*D_];
static __device__ __nv_bfloat16 t_fc2_h[(size_t)L_*D_*DF_],  t_fc2_l[(size_t)L_*D_*DF_];

// ---------------- helpers ----------------------------------------------------
__device__ __forceinline__ uint32_t smem_u32(const void* p) {
    uint32_t a;
    asm("{ .reg .u64 t; cvta.to.shared.u64 t, %1; cvt.u32.u64 %0, t; }" : "=r"(a) : "l"(p));
    return a;
}
__device__ __forceinline__ float gelu_f(float x) {
    const float c = 0.7978845608028654f;
    return 0.5f * x * (1.0f + tanhf(c * (x + 0.044715f * x * x * x)));
}
__device__ __forceinline__ void split_bf(float v, __nv_bfloat16& hi, __nv_bfloat16& lo) {
    hi = __float2bfloat16(v);
    lo = __float2bfloat16(v - __bfloat162float(hi));
}

#define CP16(dst, src) \
    asm volatile("cp.async.cg.shared.global [%0], [%1], 16;" :: "r"(dst), "l"(src))
#define CP_COMMIT() asm volatile("cp.async.commit_group;")
#define CP_WAIT(n)  asm volatile("cp.async.wait_group %0;" :: "n"(n))

#define LDSM_X4(r0, r1, r2, r3, a) \
    asm volatile("ldmatrix.sync.aligned.m8n8.x4.shared.b16 {%0,%1,%2,%3}, [%4];" \
                 : "=r"(r0), "=r"(r1), "=r"(r2), "=r"(r3) : "r"(a))
#define LDSM_X2(r0, r1, a) \
    asm volatile("ldmatrix.sync.aligned.m8n8.x2.shared.b16 {%0,%1}, [%2];" \
                 : "=r"(r0), "=r"(r1) : "r"(a))
#define MMA16816(d, a0, a1, a2, a3, b0, b1) \
    asm volatile("mma.sync.aligned.m16n8k16.row.col.f32.bf16.bf16.f32 " \
                 "{%0,%1,%2,%3},{%4,%5,%6,%7},{%8,%9},{%0,%1,%2,%3};" \
                 : "+f"((d)[0]), "+f"((d)[1]), "+f"((d)[2]), "+f"((d)[3]) \
                 : "r"(a0), "r"(a1), "r"(a2), "r"(a3), "r"(b0), "r"(b1))

// smem tile geometry: 128 rows x 32 bf16, stride 40 elems (80B) -> LDSM/STS conflict-free
#define TSTRIDE 80            // bytes per row
#define MATBYTES 10240        // 128*80
#define STAGEBYTES 40960      // 4 matrices (Ah, Al, Bh, Bl)
#define SMEM_GEMM (2*STAGEBYTES)

// ---------------- embedding --------------------------------------------------
__global__ void embed_kernel(const int* __restrict__ ids, const int* __restrict__ rfi,
                             const float* __restrict__ wte, const float* __restrict__ wte_rf,
                             const float* __restrict__ wpe, float* __restrict__ out) {
    int row = blockIdx.x;
    int s = row & (S_ - 1);
    const float* e1 = wte    + (size_t)ids[row] * D_;
    const float* e2 = wte_rf + (size_t)rfi[row] * D_;
    const float* e3 = wpe    + (size_t)s * D_;
    float* o = out + (size_t)row * D_;
    for (int d = threadIdx.x; d < D_; d += blockDim.x)
        o[d] = e1[d] + e2[d] + e3[d];
}

// ---------------- weight transpose + bf16 hi/lo split ------------------------
__global__ void wsplit_kernel(const float* __restrict__ W, __nv_bfloat16* __restrict__ Oh,
                              __nv_bfloat16* __restrict__ Ol, int K, int N) {
    __shared__ float t[32][33];
    int l = blockIdx.z;
    const float* Wl = W + (size_t)l * K * N;
    __nv_bfloat16* OhL = Oh + (size_t)l * K * N;
    __nv_bfloat16* OlL = Ol + (size_t)l * K * N;
    int n0 = blockIdx.x * 32, k0 = blockIdx.y * 32;
    int tx = threadIdx.x, ty = threadIdx.y;    // (32,8)
    for (int i = ty; i < 32; i += 8)
        t[i][tx] = Wl[(size_t)(k0 + i) * N + n0 + tx];
    __syncthreads();
    for (int i = ty; i < 32; i += 8) {
        float v = t[tx][i];
        __nv_bfloat16 hi, lo; split_bf(v, hi, lo);
        size_t idx = (size_t)(n0 + i) * K + k0 + tx;
        OhL[idx] = hi; OlL[idx] = lo;
    }
}

// ---------------- layernorm --------------------------------------------------
template<bool BF>
__global__ void ln_kernel(const float* __restrict__ x, const float* __restrict__ g,
                          const float* __restrict__ b, float* __restrict__ y,
                          __nv_bfloat16* __restrict__ yh, __nv_bfloat16* __restrict__ yl) {
    int row = blockIdx.x;
    int t = threadIdx.x;
    const float* xr = x + (size_t)row * D_;
    float v0 = xr[t], v1 = xr[t + 256], v2 = xr[t + 512];
    __shared__ float red[256];
    red[t] = v0 + v1 + v2;
    __syncthreads();
    for (int o = 128; o > 0; o >>= 1) { if (t < o) red[t] += red[t + o]; __syncthreads(); }
    float mu = red[0] * (1.0f / D_);
    __syncthreads();
    float d0 = v0 - mu, d1 = v1 - mu, d2 = v2 - mu;
    red[t] = d0*d0 + d1*d1 + d2*d2;
    __syncthreads();
    for (int o = 128; o > 0; o >>= 1) { if (t < o) red[t] += red[t + o]; __syncthreads(); }
    float inv = rsqrtf(red[0] * (1.0f / D_) + 1e-5f);
    float r0 = d0 * inv * g[t]       + b[t];
    float r1 = d1 * inv * g[t + 256] + b[t + 256];
    float r2 = d2 * inv * g[t + 512] + b[t + 512];
    if (BF) {
        __nv_bfloat16 hi, lo;
        size_t base = (size_t)row * D_;
        split_bf(r0, hi, lo); yh[base + t]       = hi; yl[base + t]       = lo;
        split_bf(r1, hi, lo); yh[base + t + 256] = hi; yl[base + t + 256] = lo;
        split_bf(r2, hi, lo); yh[base + t + 512] = hi; yl[base + t + 512] = lo;
    } else {
        float* yr = y + (size_t)row * D_;
        yr[t] = r0; yr[t + 256] = r1; yr[t + 512] = r2;
    }
}

// ---------------- mma.sync GEMM: C = epi(A@B^T + bias) -----------------------
// A: [M,K] bf16 hi/lo row-major. B: [N,K] bf16 hi/lo row-major.
// Split precision: acc = Ah*Bh + Ah*Bl + Al*Bh  (fp32 accumulate).
// EPI 0: Cf = acc + bias.  EPI 1: Cf = acc + bias + resid.
// EPI 2: Ch/Cl = split(gelu(acc + bias)).
template<int EPI>
__global__ void __launch_bounds__(256, 1)
gemm_mma(const __nv_bfloat16* __restrict__ Ah, const __nv_bfloat16* __restrict__ Al,
         const __nv_bfloat16* __restrict__ Bh, const __nv_bfloat16* __restrict__ Bl,
         const float* __restrict__ bias, const float* __restrict__ resid,
         float* __restrict__ Cf, __nv_bfloat16* __restrict__ Ch, __nv_bfloat16* __restrict__ Cl,
         int M, int N, int K) {
    extern __shared__ char smem[];
    uint32_t sbase = smem_u32(smem);
    int tid = threadIdx.x;
    int wid = tid >> 5, lane = tid & 31;
    int wm = wid >> 2, wn = wid & 3;           // warp grid 2x4, warp tile 64x32
    int m0 = blockIdx.y << 7, n0 = blockIdx.x << 7;
    int ldb = K * 2;                            // row bytes in global

    const char* srcs[4];
    srcs[0] = (const char*)(Ah + (size_t)m0 * K);
    srcs[1] = (const char*)(Al + (size_t)m0 * K);
    srcs[2] = (const char*)(Bh + (size_t)n0 * K);
    srcs[3] = (const char*)(Bl + (size_t)n0 * K);

    float acc[4][4][4] = {};
    int nk = K >> 5;

    // prefetch helper (inlined twice)
#define PREFETCH(c, s)                                                        \
    {                                                                         \
        size_t ko = (size_t)(c) << 6; /* c*32 elems * 2B */                   \
        uint32_t stb = sbase + (s) * STAGEBYTES;                              \
        _Pragma("unroll")                                                     \
        for (int j = 0; j < 8; j++) {                                         \
            int q = tid + j * 256;                                            \
            int mat = q >> 9, w = q & 511, row = w >> 2, cc = w & 3;          \
            uint32_t dst = stb + mat * MATBYTES + row * TSTRIDE + cc * 16;    \
            const char* sp = srcs[mat] + (size_t)row * ldb + ko + cc * 16;    \
            CP16(dst, sp);                                                    \
        }                                                                     \
        CP_COMMIT();                                                          \
    }

    PREFETCH(0, 0);

    // ldmatrix address components (constant across k loop)
    int aRow = wm * 64 + (lane & 7) + ((lane >> 3) & 1) * 8;   // + mi*16
    uint32_t aKoff = ((lane >> 4) & 1) * 16;                    // + kk*32
    int lb = lane & 15;
    int bRow = wn * 32 + (lb & 7);                              // + nj*8
    uint32_t bKoff = ((lb >> 3) & 1) * 16;                      // + kk*32

    for (int c = 0; c < nk; c++) {
        int s = c & 1;
        if (c + 1 < nk) PREFETCH(c + 1, s ^ 1);
        if (c + 1 < nk) { CP_WAIT(1); } else { CP_WAIT(0); }
        __syncthreads();

        uint32_t stb = sbase + s * STAGEBYTES;
        #pragma unroll
        for (int kk = 0; kk < 2; kk++) {
            uint32_t ah[4][4], al[4][4], bh[4][2], bl[4][2];
            #pragma unroll
            for (int mi = 0; mi < 4; mi++) {
                uint32_t addr = stb + (aRow + mi * 16) * TSTRIDE + kk * 32 + aKoff;
                LDSM_X4(ah[mi][0], ah[mi][1], ah[mi][2], ah[mi][3], addr);
                LDSM_X4(al[mi][0], al[mi][1], al[mi][2], al[mi][3], addr + MATBYTES);
            }
            #pragma unroll
            for (int nj = 0; nj < 4; nj++) {
                uint32_t addr = stb + 2 * MATBYTES + (bRow + nj * 8) * TSTRIDE + kk * 32 + bKoff;
                LDSM_X2(bh[nj][0], bh[nj][1], addr);
                LDSM_X2(bl[nj][0], bl[nj][1], addr + MATBYTES);
            }
            #pragma unroll
            for (int mi = 0; mi < 4; mi++)
                #pragma unroll
                for (int nj = 0; nj < 4; nj++) {
                    MMA16816(acc[mi][nj], ah[mi][0], ah[mi][1], ah[mi][2], ah[mi][3],
                             bh[nj][0], bh[nj][1]);
                    MMA16816(acc[mi][nj], ah[mi][0], ah[mi][1], ah[mi][2], ah[mi][3],
                             bl[nj][0], bl[nj][1]);
                    MMA16816(acc[mi][nj], al[mi][0], al[mi][1], al[mi][2], al[mi][3],
                             bh[nj][0], bh[nj][1]);
                }
        }
        __syncthreads();
    }

    // -------- epilogue: direct register -> gmem --------
    int rbase = m0 + wm * 64 + (lane >> 2);
    int cbase = n0 + wn * 32 + (lane & 3) * 2;
    #pragma unroll
    for (int mi = 0; mi < 4; mi++) {
        #pragma unroll
        for (int nj = 0; nj < 4; nj++) {
            int r = rbase + mi * 16;
            int col = cbase + nj * 8;
            float b0 = bias[col], b1 = bias[col + 1];
            float v00 = acc[mi][nj][0] + b0, v01 = acc[mi][nj][1] + b1;
            float v10 = acc[mi][nj][2] + b0, v11 = acc[mi][nj][3] + b1;
            size_t i0 = (size_t)r * N + col;
            size_t i1 = (size_t)(r + 8) * N + col;
            if (EPI == 0) {
                *(float2*)&Cf[i0] = make_float2(v00, v01);
                *(float2*)&Cf[i1] = make_float2(v10, v11);
            } else if (EPI == 1) {
                float2 r0 = *(const float2*)&resid[i0];
                float2 r1 = *(const float2*)&resid[i1];
                *(float2*)&Cf[i0] = make_float2(v00 + r0.x, v01 + r0.y);
                *(float2*)&Cf[i1] = make_float2(v10 + r1.x, v11 + r1.y);
            } else {
                v00 = gelu_f(v00); v01 = gelu_f(v01);
                v10 = gelu_f(v10); v11 = gelu_f(v11);
                __nv_bfloat16 h0, l0, h1, l1;
                split_bf(v00, h0, l0); split_bf(v01, h1, l1);
                __nv_bfloat162 hp, lp;
                hp.x = h0; hp.y = h1; lp.x = l0; lp.y = l1;
                *(__nv_bfloat162*)&Ch[i0] = hp;
                *(__nv_bfloat162*)&Cl[i0] = lp;
                split_bf(v10, h0, l0); split_bf(v11, h1, l1);
                hp.x = h0; hp.y = h1; lp.x = l0; lp.y = l1;
                *(__nv_bfloat162*)&Ch[i1] = hp;
                *(__nv_bfloat162*)&Cl[i1] = lp;
            }
        }
    }
#undef PREFETCH
}

// ---------------- attention: scores = mask(Q @ K^T / 8) ----------------------
__global__ void attn_score_kernel(const float* __restrict__ qkv, float* __restrict__ scores) {
    int bh = blockIdx.z;
    int b = bh / H_, h = bh % H_;
    int m0 = blockIdx.y << 6;
    int n0 = blockIdx.x << 6;
    float* C = scores + (size_t)bh * S_ * S_;
    int tid = threadIdx.x;
    int tx = tid & 15, ty = tid >> 4;
    if (n0 > m0 + 63) {
        #pragma unroll
        for (int i = 0; i < 4; i++) {
            int m = m0 + (ty << 2) + i;
            float4 val = make_float4(-1e4f, -1e4f, -1e4f, -1e4f);
            *(float4*)&C[(size_t)m * S_ + n0 + (tx << 2)] = val;
        }
        return;
    }
    const float* Q  = qkv + (size_t)b * S_ * D3_ + (size_t)h * DH_;
    const float* Kp = qkv + (size_t)b * S_ * D3_ + D_ + (size_t)h * DH_;
    __shared__ float As[16][64];
    __shared__ float Bs[16][64];
    float acc[4][4] = {};
    int ar = tid >> 2, ac4 = (tid & 3) << 2;
    int bc = tid >> 2, br4 = (tid & 3) << 2;
    for (int k0 = 0; k0 < DH_; k0 += 16) {
        float4 av = *(const float4*)&Q[(size_t)(m0 + ar) * D3_ + k0 + ac4];
        As[ac4+0][ar] = av.x; As[ac4+1][ar] = av.y; As[ac4+2][ar] = av.z; As[ac4+3][ar] = av.w;
        float4 bv = *(const float4*)&Kp[(size_t)(n0 + bc) * D3_ + k0 + br4];
        Bs[br4+0][bc] = bv.x; Bs[br4+1][bc] = bv.y; Bs[br4+2][bc] = bv.z; Bs[br4+3][bc] = bv.w;
        __syncthreads();
        #pragma unroll
        for (int kk = 0; kk < 16; kk++) {
            float a[4], bb[4];
            *(float4*)a  = *(const float4*)&As[kk][ty << 2];
            *(float4*)bb = *(const float4*)&Bs[kk][tx << 2];
            #pragma unroll
            for (int i = 0; i < 4; i++)
                #pragma unroll
                for (int j = 0; j < 4; j++)
                    acc[i][j] += a[i] * bb[j];
        }
        __syncthreads();
    }
    #pragma unroll
    for (int i = 0; i < 4; i++) {
        int m = m0 + (ty << 2) + i;
        #pragma unroll
        for (int j = 0; j < 4; j++) {
            int n = n0 + (tx << 2) + j;
            C[(size_t)m * S_ + n] = (n <= m) ? acc[i][j] * 0.125f : -1e4f;
        }
    }
}

// ---------------- softmax ----------------------------------------------------
__global__ void softmax_kernel(float* __restrict__ scores) {
    int row = blockIdx.x;
    float* x = scores + (size_t)row * S_;
    int t = threadIdx.x;
    float v[4];
    float mx = -1e30f;
    #pragma unroll
    for (int i = 0; i < 4; i++) { v[i] = x[t + (i << 8)]; mx = fmaxf(mx, v[i]); }
    __shared__ float red[256];
    red[t] = mx;
    __syncthreads();
    for (int o = 128; o > 0; o >>= 1) { if (t < o) red[t] = fmaxf(red[t], red[t + o]); __syncthreads(); }
    mx = red[0];
    __syncthreads();
    float s = 0.f;
    #pragma unroll
    for (int i = 0; i < 4; i++) { v[i] = expf(v[i] - mx); s += v[i]; }
    red[t] = s;
    __syncthreads();
    for (int o = 128; o > 0; o >>= 1) { if (t < o) red[t] += red[t + o]; __syncthreads(); }
    float inv = 1.0f / red[0];
    #pragma unroll
    for (int i = 0; i < 4; i++) x[t + (i << 8)] = v[i] * inv;
}

// ---------------- attention: O = P @ V (writes bf16 hi/lo) -------------------
__global__ void attn_pv_kernel(const float* __restrict__ qkv, const float* __restrict__ scores,
                               __nv_bfloat16* __restrict__ oh, __nv_bfloat16* __restrict__ ol) {
    int bh = blockIdx.z;
    int b = bh / H_, h = bh % H_;
    int m0 = blockIdx.y << 6;
    const float* P = scores + (size_t)bh * S_ * S_;
    const float* V = qkv + (size_t)b * S_ * D3_ + 2 * D_ + (size_t)h * DH_;
    __shared__ float As[16][64];
    __shared__ float Bs[16][64];
    int tid = threadIdx.x;
    int tx = tid & 15, ty = tid >> 4;
    float acc[4][4] = {};
    int ar = tid >> 2, ac4 = (tid & 3) << 2;
    int br = tid >> 4, bc4 = (tid & 15) << 2;
    int kend = m0 + 64;
    for (int k0 = 0; k0 < kend; k0 += 16) {
        float4 av = *(const float4*)&P[(size_t)(m0 + ar) * S_ + k0 + ac4];
        As[ac4+0][ar] = av.x; As[ac4+1][ar] = av.y; As[ac4+2][ar] = av.z; As[ac4+3][ar] = av.w;
        float4 bv = *(const float4*)&V[(size_t)(k0 + br) * D3_ + bc4];
        *(float4*)&Bs[br][bc4] = bv;
        __syncthreads();
        #pragma unroll
        for (int kk = 0; kk < 16; kk++) {
            float a[4], bb[4];
            *(float4*)a  = *(const float4*)&As[kk][ty << 2];
            *(float4*)bb = *(const float4*)&Bs[kk][tx << 2];
            #pragma unroll
            for (int i = 0; i < 4; i++)
                #pragma unroll
                for (int j = 0; j < 4; j++)
                    acc[i][j] += a[i] * bb[j];
        }
        __syncthreads();
    }
    #pragma unroll
    for (int i = 0; i < 4; i++) {
        int m = m0 + (ty << 2) + i;
        #pragma unroll
        for (int j = 0; j < 4; j++) {
            size_t idx = (size_t)(b * S_ + m) * D_ + h * DH_ + (tx << 2) + j;
            __nv_bfloat16 hi, lo; split_bf(acc[i][j], hi, lo);
            oh[idx] = hi; ol[idx] = lo;
        }
    }
}

// ---------------- host orchestration -----------------------------------------
extern "C" void kernel_launch(void* const* d_in, const int* in_sizes, int n_in,
                              void* d_out, int out_size) {
    const int*   ids    = (const int*)d_in[0];
    const int*   rfi    = (const int*)d_in[1];
    const float* wte    = (const float*)d_in[2];
    const float* wte_rf = (const float*)d_in[3];
    const float* wpe    = (const float*)d_in[4];
    const float* ln1_g  = (const float*)d_in[5];
    const float* ln1_b  = (const float*)d_in[6];
    const float* attn_w = (const float*)d_in[7];
    const float* attn_b = (const float*)d_in[8];
    const float* proj_w = (const float*)d_in[9];
    const float* proj_b = (const float*)d_in[10];
    const float* ln2_g  = (const float*)d_in[11];
    const float* ln2_b  = (const float*)d_in[12];
    const float* fc_w   = (const float*)d_in[13];
    const float* fc_b   = (const float*)d_in[14];
    const float* fc2_w  = (const float*)d_in[15];
    const float* fc2_b  = (const float*)d_in[16];
    const float* lnf_g  = (const float*)d_in[17];
    const float* lnf_b  = (const float*)d_in[18];
    float* out = (float*)d_out;

    float *h, *qkv, *sc;
    __nv_bfloat16 *ah, *al, *mh, *ml, *oh, *ol;
    __nv_bfloat16 *tah, *tal, *tph, *tpl, *tfh, *tfl, *t2h, *t2l;
    cudaGetSymbolAddress((void**)&h,   g_h);
    cudaGetSymbolAddress((void**)&qkv, g_qkv);
    cudaGetSymbolAddress((void**)&sc,  g_scores);
    cudaGetSymbolAddress((void**)&ah,  g_ah);  cudaGetSymbolAddress((void**)&al,  g_al);
    cudaGetSymbolAddress((void**)&mh,  g_mh);  cudaGetSymbolAddress((void**)&ml,  g_ml);
    cudaGetSymbolAddress((void**)&oh,  g_oh);  cudaGetSymbolAddress((void**)&ol,  g_ol);
    cudaGetSymbolAddress((void**)&tah, t_attn_h); cudaGetSymbolAddress((void**)&tal, t_attn_l);
    cudaGetSymbolAddress((void**)&tph, t_proj_h); cudaGetSymbolAddress((void**)&tpl, t_proj_l);
    cudaGetSymbolAddress((void**)&tfh, t_fc_h);   cudaGetSymbolAddress((void**)&tfl, t_fc_l);
    cudaGetSymbolAddress((void**)&t2h, t_fc2_h);  cudaGetSymbolAddress((void**)&t2l, t_fc2_l);

    cudaFuncSetAttribute(gemm_mma<0>, cudaFuncAttributeMaxDynamicSharedMemorySize, SMEM_GEMM);
    cudaFuncSetAttribute(gemm_mma<1>, cudaFuncAttributeMaxDynamicSharedMemorySize, SMEM_GEMM);
    cudaFuncSetAttribute(gemm_mma<2>, cudaFuncAttributeMaxDynamicSharedMemorySize, SMEM_GEMM);

    dim3 wblk(32, 8);
    wsplit_kernel<<<dim3(D3_/32, D_/32, L_), wblk>>>(attn_w, tah, tal, D_, D3_);
    wsplit_kernel<<<dim3(D_/32,  D_/32, L_), wblk>>>(proj_w, tph, tpl, D_, D_);
    wsplit_kernel<<<dim3(DF_/32, D_/32, L_), wblk>>>(fc_w,   tfh, tfl, D_, DF_);
    wsplit_kernel<<<dim3(D_/32, DF_/32, L_), wblk>>>(fc2_w,  t2h, t2l, DF_, D_);

    embed_kernel<<<NT_, 256>>>(ids, rfi, wte, wte_rf, wpe, h);

    for (int l = 0; l < L_; l++) {
        ln_kernel<true><<<NT_, 256>>>(h, ln1_g + l * D_, ln1_b + l * D_, nullptr, ah, al);
        gemm_mma<0><<<dim3(D3_/128, NT_/128), 256, SMEM_GEMM>>>(
            ah, al, tah + (size_t)l * D3_ * D_, tal + (size_t)l * D3_ * D_,
            attn_b + l * D3_, nullptr, qkv, nullptr, nullptr, NT_, D3_, D_);
        attn_score_kernel<<<dim3(S_/64, S_/64, B_*H_), 256>>>(qkv, sc);
        softmax_kernel<<<B_*H_*S_, 256>>>(sc);
        attn_pv_kernel<<<dim3(1, S_/64, B_*H_), 256>>>(qkv, sc, oh, ol);
        gemm_mma<1><<<dim3(D_/128, NT_/128), 256, SMEM_GEMM>>>(
            oh, ol, tph + (size_t)l * D_ * D_, tpl + (size_t)l * D_ * D_,
            proj_b + l * D_, h, h, nullptr, nullptr, NT_, D_, D_);
        ln_kernel<true><<<NT_, 256>>>(h, ln2_g + l * D_, ln2_b + l * D_, nullptr, ah, al);
        gemm_mma<2><<<dim3(DF_/128, NT_/128), 256, SMEM_GEMM>>>(
            ah, al, tfh + (size_t)l * DF_ * D_, tfl + (size_t)l * DF_ * D_,
            fc_b + l * DF_, nullptr, nullptr, mh, ml, NT_, DF_, D_);
        gemm_mma<1><<<dim3(D_/128, NT_/128), 256, SMEM_GEMM>>>(
            mh, ml, t2h + (size_t)l * D_ * DF_, t2l + (size_t)l * D_ * DF_,
            fc2_b + l * D_, h, h, nullptr, nullptr, NT_, D_, DF_);
    }
    ln_kernel<false><<<NT_, 256>>>(h, lnf_g, lnf_b, out, nullptr, nullptr);
}

// round 4
// speedup vs baseline: 2.4923x; 1.3446x over previous
#include <cuda_runtime.h>
#include <cuda_bf16.h>
#include <math.h>
#include <stdint.h>

#define B_  4
#define S_  1024
#define D_  768
#define H_  12
#define L_  6
#define DF_ 3072
#define DH_ 64
#define NT_ (B_*S_)        // 4096
#define D3_ (3*D_)         // 2304

// ---------------- scratch (static device globals) ----------------------------
static __device__ float g_h[NT_*D_];
static __device__ __nv_bfloat16 g_ah[NT_*D_],  g_al[NT_*D_];
static __device__ __nv_bfloat16 g_mh[NT_*DF_], g_ml[NT_*DF_];
static __device__ __nv_bfloat16 g_oh[NT_*D_],  g_ol[NT_*D_];
static __device__ __nv_bfloat16 g_qh[NT_*D_],  g_ql[NT_*D_];
static __device__ __nv_bfloat16 g_kh[NT_*D_],  g_kl[NT_*D_];
static __device__ __nv_bfloat16 g_vh[NT_*D_],  g_vl[NT_*D_];
static __device__ __nv_bfloat16 t_attn_h[(size_t)L_*D3_*D_], t_attn_l[(size_t)L_*D3_*D_];
static __device__ __nv_bfloat16 t_proj_h[(size_t)L_*D_*D_],  t_proj_l[(size_t)L_*D_*D_];
static __device__ __nv_bfloat16 t_fc_h[(size_t)L_*DF_*D_],   t_fc_l[(size_t)L_*DF_*D_];
static __device__ __nv_bfloat16 t_fc2_h[(size_t)L_*D_*DF_],  t_fc2_l[(size_t)L_*D_*DF_];

// ---------------- helpers ----------------------------------------------------
__device__ __forceinline__ uint32_t smem_u32(const void* p) {
    uint32_t a;
    asm("{ .reg .u64 t; cvta.to.shared.u64 t, %1; cvt.u32.u64 %0, t; }" : "=r"(a) : "l"(p));
    return a;
}
__device__ __forceinline__ float gelu_f(float x) {
    const float c = 0.7978845608028654f;
    return 0.5f * x * (1.0f + tanhf(c * (x + 0.044715f * x * x * x)));
}
__device__ __forceinline__ void split_bf(float v, __nv_bfloat16& hi, __nv_bfloat16& lo) {
    hi = __float2bfloat16(v);
    lo = __float2bfloat16(v - __bfloat162float(hi));
}
__device__ __forceinline__ void pack_split(float x, float y, uint32_t& hp, uint32_t& lp) {
    __nv_bfloat16 hx, lx, hy, ly;
    split_bf(x, hx, lx); split_bf(y, hy, ly);
    __nv_bfloat162 h2; h2.x = hx; h2.y = hy;
    __nv_bfloat162 l2; l2.x = lx; l2.y = ly;
    hp = *(uint32_t*)&h2; lp = *(uint32_t*)&l2;
}

#define CP16(dst, src) \
    asm volatile("cp.async.cg.shared.global [%0], [%1], 16;" :: "r"(dst), "l"(src))
#define CP_COMMIT() asm volatile("cp.async.commit_group;")
#define CP_WAIT(n)  asm volatile("cp.async.wait_group %0;" :: "n"(n))

#define LDSM_X4(r0, r1, r2, r3, a) \
    asm volatile("ldmatrix.sync.aligned.m8n8.x4.shared.b16 {%0,%1,%2,%3}, [%4];" \
                 : "=r"(r0), "=r"(r1), "=r"(r2), "=r"(r3) : "r"(a))
#define LDSM_X2(r0, r1, a) \
    asm volatile("ldmatrix.sync.aligned.m8n8.x2.shared.b16 {%0,%1}, [%2];" \
                 : "=r"(r0), "=r"(r1) : "r"(a))
#define LDSM_X2_T(r0, r1, a) \
    asm volatile("ldmatrix.sync.aligned.m8n8.x2.trans.shared.b16 {%0,%1}, [%2];" \
                 : "=r"(r0), "=r"(r1) : "r"(a))
#define MMA16816(d, a0, a1, a2, a3, b0, b1) \
    asm volatile("mma.sync.aligned.m16n8k16.row.col.f32.bf16.bf16.f32 " \
                 "{%0,%1,%2,%3},{%4,%5,%6,%7},{%8,%9},{%0,%1,%2,%3};" \
                 : "+f"((d)[0]), "+f"((d)[1]), "+f"((d)[2]), "+f"((d)[3]) \
                 : "r"(a0), "r"(a1), "r"(a2), "r"(a3), "r"(b0), "r"(b1))

// gemm smem tile geometry: 128 rows x 32 bf16, stride 80B
#define TSTRIDE 80
#define MATBYTES 10240
#define STAGEBYTES 40960
#define SMEM_GEMM (2*STAGEBYTES)

// flash smem: rows of 64 bf16 (128B) padded to 144B
#define FSTR 144
#define QOFF_H 0
#define QOFF_L 9216
#define KOFF_H 18432
#define KOFF_L 36864
#define VOFF_H 55296
#define VOFF_L 73728
#define SMEM_FLASH 92160

// ---------------- embedding --------------------------------------------------
__global__ void embed_kernel(const int* __restrict__ ids, const int* __restrict__ rfi,
                             const float* __restrict__ wte, const float* __restrict__ wte_rf,
                             const float* __restrict__ wpe, float* __restrict__ out) {
    int row = blockIdx.x;
    int s = row & (S_ - 1);
    const float* e1 = wte    + (size_t)ids[row] * D_;
    const float* e2 = wte_rf + (size_t)rfi[row] * D_;
    const float* e3 = wpe    + (size_t)s * D_;
    float* o = out + (size_t)row * D_;
    for (int d = threadIdx.x; d < D_; d += blockDim.x)
        o[d] = e1[d] + e2[d] + e3[d];
}

// ---------------- weight transpose + bf16 hi/lo split ------------------------
__global__ void wsplit_kernel(const float* __restrict__ W, __nv_bfloat16* __restrict__ Oh,
                              __nv_bfloat16* __restrict__ Ol, int K, int N) {
    __shared__ float t[32][33];
    int l = blockIdx.z;
    const float* Wl = W + (size_t)l * K * N;
    __nv_bfloat16* OhL = Oh + (size_t)l * K * N;
    __nv_bfloat16* OlL = Ol + (size_t)l * K * N;
    int n0 = blockIdx.x * 32, k0 = blockIdx.y * 32;
    int tx = threadIdx.x, ty = threadIdx.y;    // (32,8)
    for (int i = ty; i < 32; i += 8)
        t[i][tx] = Wl[(size_t)(k0 + i) * N + n0 + tx];
    __syncthreads();
    for (int i = ty; i < 32; i += 8) {
        float v = t[tx][i];
        __nv_bfloat16 hi, lo; split_bf(v, hi, lo);
        size_t idx = (size_t)(n0 + i) * K + k0 + tx;
        OhL[idx] = hi; OlL[idx] = lo;
    }
}

// ---------------- layernorm --------------------------------------------------
template<bool BF>
__global__ void ln_kernel(const float* __restrict__ x, const float* __restrict__ g,
                          const float* __restrict__ b, float* __restrict__ y,
                          __nv_bfloat16* __restrict__ yh, __nv_bfloat16* __restrict__ yl) {
    int row = blockIdx.x;
    int t = threadIdx.x;
    const float* xr = x + (size_t)row * D_;
    float v0 = xr[t], v1 = xr[t + 256], v2 = xr[t + 512];
    __shared__ float red[256];
    red[t] = v0 + v1 + v2;
    __syncthreads();
    for (int o = 128; o > 0; o >>= 1) { if (t < o) red[t] += red[t + o]; __syncthreads(); }
    float mu = red[0] * (1.0f / D_);
    __syncthreads();
    float d0 = v0 - mu, d1 = v1 - mu, d2 = v2 - mu;
    red[t] = d0*d0 + d1*d1 + d2*d2;
    __syncthreads();
    for (int o = 128; o > 0; o >>= 1) { if (t < o) red[t] += red[t + o]; __syncthreads(); }
    float inv = rsqrtf(red[0] * (1.0f / D_) + 1e-5f);
    float r0 = d0 * inv * g[t]       + b[t];
    float r1 = d1 * inv * g[t + 256] + b[t + 256];
    float r2 = d2 * inv * g[t + 512] + b[t + 512];
    if (BF) {
        __nv_bfloat16 hi, lo;
        size_t base = (size_t)row * D_;
        split_bf(r0, hi, lo); yh[base + t]       = hi; yl[base + t]       = lo;
        split_bf(r1, hi, lo); yh[base + t + 256] = hi; yl[base + t + 256] = lo;
        split_bf(r2, hi, lo); yh[base + t + 512] = hi; yl[base + t + 512] = lo;
    } else {
        float* yr = y + (size_t)row * D_;
        yr[t] = r0; yr[t + 256] = r1; yr[t + 512] = r2;
    }
}

// ---------------- mma.sync GEMM ----------------------------------------------
// acc = Ah*Bh + Ah*Bl + Al*Bh (fp32 accumulate)
// EPI 0: Cf = acc+bias.  EPI 1: Cf = acc+bias+resid.
// EPI 2: Ch/Cl = split(gelu(acc+bias)).  EPI 3: head-major split Q/K/V write.
template<int EPI>
__global__ void __launch_bounds__(256, 1)
gemm_mma(const __nv_bfloat16* __restrict__ Ah, const __nv_bfloat16* __restrict__ Al,
         const __nv_bfloat16* __restrict__ Bh, const __nv_bfloat16* __restrict__ Bl,
         const float* __restrict__ bias, const float* __restrict__ resid,
         float* __restrict__ Cf, __nv_bfloat16* __restrict__ Ch, __nv_bfloat16* __restrict__ Cl,
         __nv_bfloat16* __restrict__ Qh_, __nv_bfloat16* __restrict__ Ql_,
         __nv_bfloat16* __restrict__ Kh_, __nv_bfloat16* __restrict__ Kl_,
         __nv_bfloat16* __restrict__ Vh_, __nv_bfloat16* __restrict__ Vl_,
         int M, int N, int K) {
    extern __shared__ char smem[];
    uint32_t sbase = smem_u32(smem);
    int tid = threadIdx.x;
    int wid = tid >> 5, lane = tid & 31;
    int wm = wid >> 2, wn = wid & 3;           // warp grid 2x4, warp tile 64x32
    int m0 = blockIdx.y << 7, n0 = blockIdx.x << 7;
    int ldb = K * 2;

    const char* srcs[4];
    srcs[0] = (const char*)(Ah + (size_t)m0 * K);
    srcs[1] = (const char*)(Al + (size_t)m0 * K);
    srcs[2] = (const char*)(Bh + (size_t)n0 * K);
    srcs[3] = (const char*)(Bl + (size_t)n0 * K);

    float acc[4][4][4] = {};
    int nk = K >> 5;

#define PREFETCH(c, s)                                                        \
    {                                                                         \
        size_t ko = (size_t)(c) << 6;                                         \
        uint32_t stb = sbase + (s) * STAGEBYTES;                              \
        _Pragma("unroll")                                                     \
        for (int j = 0; j < 8; j++) {                                         \
            int q = tid + j * 256;                                            \
            int mat = q >> 9, w = q & 511, row = w >> 2, cc = w & 3;          \
            uint32_t dst = stb + mat * MATBYTES + row * TSTRIDE + cc * 16;    \
            const char* sp = srcs[mat] + (size_t)row * ldb + ko + cc * 16;    \
            CP16(dst, sp);                                                    \
        }                                                                     \
        CP_COMMIT();                                                          \
    }

    PREFETCH(0, 0);

    int aRow = wm * 64 + (lane & 7) + ((lane >> 3) & 1) * 8;
    uint32_t aKoff = ((lane >> 4) & 1) * 16;
    int lb = lane & 15;
    int bRow = wn * 32 + (lb & 7);
    uint32_t bKoff = ((lb >> 3) & 1) * 16;

    for (int c = 0; c < nk; c++) {
        int s = c & 1;
        if (c + 1 < nk) PREFETCH(c + 1, s ^ 1);
        if (c + 1 < nk) { CP_WAIT(1); } else { CP_WAIT(0); }
        __syncthreads();

        uint32_t stb = sbase + s * STAGEBYTES;
        #pragma unroll
        for (int kk = 0; kk < 2; kk++) {
            uint32_t ah[4][4], al[4][4], bh[4][2], bl[4][2];
            #pragma unroll
            for (int mi = 0; mi < 4; mi++) {
                uint32_t addr = stb + (aRow + mi * 16) * TSTRIDE + kk * 32 + aKoff;
                LDSM_X4(ah[mi][0], ah[mi][1], ah[mi][2], ah[mi][3], addr);
                LDSM_X4(al[mi][0], al[mi][1], al[mi][2], al[mi][3], addr + MATBYTES);
            }
            #pragma unroll
            for (int nj = 0; nj < 4; nj++) {
                uint32_t addr = stb + 2 * MATBYTES + (bRow + nj * 8) * TSTRIDE + kk * 32 + bKoff;
                LDSM_X2(bh[nj][0], bh[nj][1], addr);
                LDSM_X2(bl[nj][0], bl[nj][1], addr + MATBYTES);
            }
            #pragma unroll
            for (int mi = 0; mi < 4; mi++)
                #pragma unroll
                for (int nj = 0; nj < 4; nj++) {
                    MMA16816(acc[mi][nj], ah[mi][0], ah[mi][1], ah[mi][2], ah[mi][3],
                             bh[nj][0], bh[nj][1]);
                    MMA16816(acc[mi][nj], ah[mi][0], ah[mi][1], ah[mi][2], ah[mi][3],
                             bl[nj][0], bl[nj][1]);
                    MMA16816(acc[mi][nj], al[mi][0], al[mi][1], al[mi][2], al[mi][3],
                             bh[nj][0], bh[nj][1]);
                }
        }
        __syncthreads();
    }

    int rbase = m0 + wm * 64 + (lane >> 2);
    int cbase = n0 + wn * 32 + (lane & 3) * 2;
    #pragma unroll
    for (int mi = 0; mi < 4; mi++) {
        #pragma unroll
        for (int nj = 0; nj < 4; nj++) {
            int r = rbase + mi * 16;
            int col = cbase + nj * 8;
            float b0 = bias[col], b1 = bias[col + 1];
            float v00 = acc[mi][nj][0] + b0, v01 = acc[mi][nj][1] + b1;
            float v10 = acc[mi][nj][2] + b0, v11 = acc[mi][nj][3] + b1;
            size_t i0 = (size_t)r * N + col;
            size_t i1 = (size_t)(r + 8) * N + col;
            if (EPI == 0) {
                *(float2*)&Cf[i0] = make_float2(v00, v01);
                *(float2*)&Cf[i1] = make_float2(v10, v11);
            } else if (EPI == 1) {
                float2 r0 = *(const float2*)&resid[i0];
                float2 r1 = *(const float2*)&resid[i1];
                *(float2*)&Cf[i0] = make_float2(v00 + r0.x, v01 + r0.y);
                *(float2*)&Cf[i1] = make_float2(v10 + r1.x, v11 + r1.y);
            } else if (EPI == 2) {
                v00 = gelu_f(v00); v01 = gelu_f(v01);
                v10 = gelu_f(v10); v11 = gelu_f(v11);
                uint32_t hp, lp;
                pack_split(v00, v01, hp, lp);
                *(uint32_t*)&Ch[i0] = hp; *(uint32_t*)&Cl[i0] = lp;
                pack_split(v10, v11, hp, lp);
                *(uint32_t*)&Ch[i1] = hp; *(uint32_t*)&Cl[i1] = lp;
            } else {
                // EPI 3: head-major split write of q/k/v
                int which = col / D_;
                int hh = (col % D_) / DH_;
                int dd = col % DH_;
                __nv_bfloat16* dh_ = which == 0 ? Qh_ : (which == 1 ? Kh_ : Vh_);
                __nv_bfloat16* dl_ = which == 0 ? Ql_ : (which == 1 ? Kl_ : Vl_);
                int bi = r >> 10, si = r & 1023;
                size_t j0 = (((size_t)(bi * H_ + hh)) * S_ + si) * DH_ + dd;
                size_t j1 = j0 + 8 * DH_;
                uint32_t hp, lp;
                pack_split(v00, v01, hp, lp);
                *(uint32_t*)&dh_[j0] = hp; *(uint32_t*)&dl_[j0] = lp;
                pack_split(v10, v11, hp, lp);
                *(uint32_t*)&dh_[j1] = hp; *(uint32_t*)&dl_[j1] = lp;
            }
        }
    }
#undef PREFETCH
}

// ---------------- fused flash attention --------------------------------------
// grid (S/64, B*H), 128 threads (4 warps). 64 q-rows/CTA, KV tiles of 128.
__global__ void __launch_bounds__(128, 1)
flash_kernel(const __nv_bfloat16* __restrict__ qh, const __nv_bfloat16* __restrict__ ql,
             const __nv_bfloat16* __restrict__ kh, const __nv_bfloat16* __restrict__ kl,
             const __nv_bfloat16* __restrict__ vh, const __nv_bfloat16* __restrict__ vl,
             __nv_bfloat16* __restrict__ oh, __nv_bfloat16* __restrict__ ol) {
    extern __shared__ char fsm[];
    uint32_t sb = smem_u32(fsm);
    int bh = blockIdx.y;
    int q0 = blockIdx.x << 6;
    int tid = threadIdx.x, wid = tid >> 5, lane = tid & 31;

    {   // Q tile load (64 rows x 128B), hi+lo
        const char* srcH = (const char*)(qh + ((size_t)bh * S_ + q0) * DH_);
        const char* srcL = (const char*)(ql + ((size_t)bh * S_ + q0) * DH_);
        #pragma unroll
        for (int i = tid; i < 512; i += 128) {
            int r = i >> 3, c = (i & 7) << 4;
            CP16(sb + QOFF_H + r * FSTR + c, srcH + r * 128 + c);
            CP16(sb + QOFF_L + r * FSTR + c, srcL + r * 128 + c);
        }
        CP_COMMIT();
    }

    float m0 = -1e30f, m1 = -1e30f, l0 = 0.f, l1 = 0.f;
    float oacc[8][4];
    #pragma unroll
    for (int d = 0; d < 8; d++)
        oacc[d][0] = oacc[d][1] = oacc[d][2] = oacc[d][3] = 0.f;

    int rA = q0 + wid * 16 + (lane >> 2);
    int nj = (q0 >> 7) + 1;

    uint32_t aAddrBase = sb + (wid * 16 + (lane & 15)) * FSTR + (((lane >> 4) & 1) << 4);
    uint32_t bRowOff = (uint32_t)((lane & 7) * FSTR) + (((lane >> 3) & 1) << 4);

    for (int j = 0; j < nj; j++) {
        __syncthreads();
        {   // K/V tile load (128 rows x 128B) x4 matrices
            const char* kH = (const char*)(kh + ((size_t)bh * S_ + (j << 7)) * DH_);
            const char* kL = (const char*)(kl + ((size_t)bh * S_ + (j << 7)) * DH_);
            const char* vH = (const char*)(vh + ((size_t)bh * S_ + (j << 7)) * DH_);
            const char* vL = (const char*)(vl + ((size_t)bh * S_ + (j << 7)) * DH_);
            #pragma unroll
            for (int i = tid; i < 1024; i += 128) {
                int r = i >> 3, c = (i & 7) << 4;
                uint32_t so = r * FSTR + c;
                size_t go = (size_t)r * 128 + c;
                CP16(sb + KOFF_H + so, kH + go);
                CP16(sb + KOFF_L + so, kL + go);
                CP16(sb + VOFF_H + so, vH + go);
                CP16(sb + VOFF_L + so, vL + go);
            }
            CP_COMMIT();
            CP_WAIT(0);
        }
        __syncthreads();

        // --- S = Q @ K^T (split precision, 3 passes) ---
        float sf[16][4];
        #pragma unroll
        for (int nt = 0; nt < 16; nt++)
            sf[nt][0] = sf[nt][1] = sf[nt][2] = sf[nt][3] = 0.f;

        #pragma unroll
        for (int kc = 0; kc < 4; kc++) {
            uint32_t qa = aAddrBase + kc * 32;
            uint32_t q_h0,q_h1,q_h2,q_h3, q_l0,q_l1,q_l2,q_l3;
            LDSM_X4(q_h0,q_h1,q_h2,q_h3, qa + QOFF_H);
            LDSM_X4(q_l0,q_l1,q_l2,q_l3, qa + QOFF_L);
            #pragma unroll
            for (int nt = 0; nt < 16; nt++) {
                uint32_t ka = sb + KOFF_H + nt * 8 * FSTR + bRowOff + kc * 32;
                uint32_t k_h0,k_h1, k_l0,k_l1;
                LDSM_X2(k_h0,k_h1, ka);
                LDSM_X2(k_l0,k_l1, ka + 18432);
                MMA16816(sf[nt], q_h0,q_h1,q_h2,q_h3, k_h0,k_h1);
                MMA16816(sf[nt], q_h0,q_h1,q_h2,q_h3, k_l0,k_l1);
                MMA16816(sf[nt], q_l0,q_l1,q_l2,q_l3, k_h0,k_h1);
            }
        }

        // --- masking + online softmax ---
        int cb = (j << 7) + (lane & 3) * 2;
        float mx0 = -1e30f, mx1 = -1e30f;
        #pragma unroll
        for (int nt = 0; nt < 16; nt++) {
            int c0 = cb + nt * 8;
            sf[nt][0] = (c0     <= rA)     ? sf[nt][0] * 0.125f : -1e30f;
            sf[nt][1] = (c0 + 1 <= rA)     ? sf[nt][1] * 0.125f : -1e30f;
            sf[nt][2] = (c0     <= rA + 8) ? sf[nt][2] * 0.125f : -1e30f;
            sf[nt][3] = (c0 + 1 <= rA + 8) ? sf[nt][3] * 0.125f : -1e30f;
            mx0 = fmaxf(mx0, fmaxf(sf[nt][0], sf[nt][1]));
            mx1 = fmaxf(mx1, fmaxf(sf[nt][2], sf[nt][3]));
        }
        mx0 = fmaxf(mx0, __shfl_xor_sync(0xffffffffu, mx0, 1));
        mx0 = fmaxf(mx0, __shfl_xor_sync(0xffffffffu, mx0, 2));
        mx1 = fmaxf(mx1, __shfl_xor_sync(0xffffffffu, mx1, 1));
        mx1 = fmaxf(mx1, __shfl_xor_sync(0xffffffffu, mx1, 2));
        float mn0 = fmaxf(m0, mx0), mn1 = fmaxf(m1, mx1);
        float sc0 = expf(m0 - mn0), sc1 = expf(m1 - mn1);
        m0 = mn0; m1 = mn1;
        l0 *= sc0; l1 *= sc1;
        #pragma unroll
        for (int d = 0; d < 8; d++) {
            oacc[d][0] *= sc0; oacc[d][1] *= sc0;
            oacc[d][2] *= sc1; oacc[d][3] *= sc1;
        }
        float s0 = 0.f, s1 = 0.f;
        uint32_t ph[16][2], pl[16][2];
        #pragma unroll
        for (int nt = 0; nt < 16; nt++) {
            float p0 = expf(sf[nt][0] - m0), p1 = expf(sf[nt][1] - m0);
            float p2 = expf(sf[nt][2] - m1), p3 = expf(sf[nt][3] - m1);
            s0 += p0 + p1; s1 += p2 + p3;
            pack_split(p0, p1, ph[nt][0], pl[nt][0]);
            pack_split(p2, p3, ph[nt][1], pl[nt][1]);
        }
        s0 += __shfl_xor_sync(0xffffffffu, s0, 1);
        s0 += __shfl_xor_sync(0xffffffffu, s0, 2);
        s1 += __shfl_xor_sync(0xffffffffu, s1, 1);
        s1 += __shfl_xor_sync(0xffffffffu, s1, 2);
        l0 += s0; l1 += s1;

        // --- O += P @ V (split precision, 3 passes) ---
        #pragma unroll
        for (int kc = 0; kc < 8; kc++) {
            uint32_t va = sb + VOFF_H + (kc * 16 + (lane & 15)) * FSTR;
            #pragma unroll
            for (int dt = 0; dt < 8; dt++) {
                uint32_t v_h0,v_h1, v_l0,v_l1;
                LDSM_X2_T(v_h0,v_h1, va + dt * 16);
                LDSM_X2_T(v_l0,v_l1, va + 18432 + dt * 16);
                MMA16816(oacc[dt], ph[2*kc][0], ph[2*kc][1], ph[2*kc+1][0], ph[2*kc+1][1], v_h0, v_h1);
                MMA16816(oacc[dt], ph[2*kc][0], ph[2*kc][1], ph[2*kc+1][0], ph[2*kc+1][1], v_l0, v_l1);
                MMA16816(oacc[dt], pl[2*kc][0], pl[2*kc][1], pl[2*kc+1][0], pl[2*kc+1][1], v_h0, v_h1);
            }
        }
    }

    // --- finalize ---
    float inv0 = 1.f / l0, inv1 = 1.f / l1;
    int bb = bh / H_, hH = bh % H_;
    size_t baseA = ((size_t)bb * S_ + rA) * D_ + hH * DH_;
    size_t baseB = baseA + 8 * D_;
    #pragma unroll
    for (int dt = 0; dt < 8; dt++) {
        int c = dt * 8 + (lane & 3) * 2;
        uint32_t hp, lp;
        pack_split(oacc[dt][0] * inv0, oacc[dt][1] * inv0, hp, lp);
        *(uint32_t*)&oh[baseA + c] = hp;
        *(uint32_t*)&ol[baseA + c] = lp;
        pack_split(oacc[dt][2] * inv1, oacc[dt][3] * inv1, hp, lp);
        *(uint32_t*)&oh[baseB + c] = hp;
        *(uint32_t*)&ol[baseB + c] = lp;
    }
}

// ---------------- host orchestration -----------------------------------------
extern "C" void kernel_launch(void* const* d_in, const int* in_sizes, int n_in,
                              void* d_out, int out_size) {
    const int*   ids    = (const int*)d_in[0];
    const int*   rfi    = (const int*)d_in[1];
    const float* wte    = (const float*)d_in[2];
    const float* wte_rf = (const float*)d_in[3];
    const float* wpe    = (const float*)d_in[4];
    const float* ln1_g  = (const float*)d_in[5];
    const float* ln1_b  = (const float*)d_in[6];
    const float* attn_w = (const float*)d_in[7];
    const float* attn_b = (const float*)d_in[8];
    const float* proj_w = (const float*)d_in[9];
    const float* proj_b = (const float*)d_in[10];
    const float* ln2_g  = (const float*)d_in[11];
    const float* ln2_b  = (const float*)d_in[12];
    const float* fc_w   = (const float*)d_in[13];
    const float* fc_b   = (const float*)d_in[14];
    const float* fc2_w  = (const float*)d_in[15];
    const float* fc2_b  = (const float*)d_in[16];
    const float* lnf_g  = (const float*)d_in[17];
    const float* lnf_b  = (const float*)d_in[18];
    float* out = (float*)d_out;

    float *h;
    __nv_bfloat16 *ah, *al, *mh, *ml, *oh, *ol;
    __nv_bfloat16 *qh, *ql, *kh, *kl, *vh, *vl;
    __nv_bfloat16 *tah, *tal, *tph, *tpl, *tfh, *tfl, *t2h, *t2l;
    cudaGetSymbolAddress((void**)&h,   g_h);
    cudaGetSymbolAddress((void**)&ah,  g_ah);  cudaGetSymbolAddress((void**)&al,  g_al);
    cudaGetSymbolAddress((void**)&mh,  g_mh);  cudaGetSymbolAddress((void**)&ml,  g_ml);
    cudaGetSymbolAddress((void**)&oh,  g_oh);  cudaGetSymbolAddress((void**)&ol,  g_ol);
    cudaGetSymbolAddress((void**)&qh,  g_qh);  cudaGetSymbolAddress((void**)&ql,  g_ql);
    cudaGetSymbolAddress((void**)&kh,  g_kh);  cudaGetSymbolAddress((void**)&kl,  g_kl);
    cudaGetSymbolAddress((void**)&vh,  g_vh);  cudaGetSymbolAddress((void**)&vl,  g_vl);
    cudaGetSymbolAddress((void**)&tah, t_attn_h); cudaGetSymbolAddress((void**)&tal, t_attn_l);
    cudaGetSymbolAddress((void**)&tph, t_proj_h); cudaGetSymbolAddress((void**)&tpl, t_proj_l);
    cudaGetSymbolAddress((void**)&tfh, t_fc_h);   cudaGetSymbolAddress((void**)&tfl, t_fc_l);
    cudaGetSymbolAddress((void**)&t2h, t_fc2_h);  cudaGetSymbolAddress((void**)&t2l, t_fc2_l);

    cudaFuncSetAttribute(gemm_mma<1>, cudaFuncAttributeMaxDynamicSharedMemorySize, SMEM_GEMM);
    cudaFuncSetAttribute(gemm_mma<2>, cudaFuncAttributeMaxDynamicSharedMemorySize, SMEM_GEMM);
    cudaFuncSetAttribute(gemm_mma<3>, cudaFuncAttributeMaxDynamicSharedMemorySize, SMEM_GEMM);
    cudaFuncSetAttribute(flash_kernel, cudaFuncAttributeMaxDynamicSharedMemorySize, SMEM_FLASH);

    dim3 wblk(32, 8);
    wsplit_kernel<<<dim3(D3_/32, D_/32, L_), wblk>>>(attn_w, tah, tal, D_, D3_);
    wsplit_kernel<<<dim3(D_/32,  D_/32, L_), wblk>>>(proj_w, tph, tpl, D_, D_);
    wsplit_kernel<<<dim3(DF_/32, D_/32, L_), wblk>>>(fc_w,   tfh, tfl, D_, DF_);
    wsplit_kernel<<<dim3(D_/32, DF_/32, L_), wblk>>>(fc2_w,  t2h, t2l, DF_, D_);

    embed_kernel<<<NT_, 256>>>(ids, rfi, wte, wte_rf, wpe, h);

    for (int l = 0; l < L_; l++) {
        ln_kernel<true><<<NT_, 256>>>(h, ln1_g + l * D_, ln1_b + l * D_, nullptr, ah, al);
        gemm_mma<3><<<dim3(D3_/128, NT_/128), 256, SMEM_GEMM>>>(
            ah, al, tah + (size_t)l * D3_ * D_, tal + (size_t)l * D3_ * D_,
            attn_b + l * D3_, nullptr, nullptr, nullptr, nullptr,
            qh, ql, kh, kl, vh, vl, NT_, D3_, D_);
        flash_kernel<<<dim3(S_/64, B_*H_), 128, SMEM_FLASH>>>(qh, ql, kh, kl, vh, vl, oh, ol);
        gemm_mma<1><<<dim3(D_/128, NT_/128), 256, SMEM_GEMM>>>(
            oh, ol, tph + (size_t)l * D_ * D_, tpl + (size_t)l * D_ * D_,
            proj_b + l * D_, h, h, nullptr, nullptr,
            nullptr, nullptr, nullptr, nullptr, nullptr, nullptr, NT_, D_, D_);
        ln_kernel<true><<<NT_, 256>>>(h, ln2_g + l * D_, ln2_b + l * D_, nullptr, ah, al);
        gemm_mma<2><<<dim3(DF_/128, NT_/128), 256, SMEM_GEMM>>>(
            ah, al, tfh + (size_t)l * DF_ * D_, tfl + (size_t)l * DF_ * D_,
            fc_b + l * DF_, nullptr, nullptr, mh, ml,
            nullptr, nullptr, nullptr, nullptr, nullptr, nullptr, NT_, DF_, D_);
        gemm_mma<1><<<dim3(D_/128, NT_/128), 256, SMEM_GEMM>>>(
            mh, ml, t2h + (size_t)l * D_ * DF_, t2l + (size_t)l * D_ * DF_,
            fc2_b + l * D_, h, h, nullptr, nullptr,
            nullptr, nullptr, nullptr, nullptr, nullptr, nullptr, NT_, D_, DF_);
    }
    ln_kernel<false><<<NT_, 256>>>(h, lnf_g, lnf_b, out, nullptr, nullptr);
}

// round 5
// speedup vs baseline: 2.7602x; 1.1075x over previous
#include <cuda_runtime.h>
#include <cuda_bf16.h>
#include <math.h>
#include <stdint.h>

#define B_  4
#define S_  1024
#define D_  768
#define H_  12
#define L_  6
#define DF_ 3072
#define DH_ 64
#define NT_ (B_*S_)        // 4096
#define D3_ (3*D_)         // 2304

// ---------------- scratch (static device globals) ----------------------------
static __device__ float g_h[NT_*D_];
static __device__ __nv_bfloat16 g_ah[NT_*D_],  g_al[NT_*D_];
static __device__ __nv_bfloat16 g_mh[NT_*DF_], g_ml[NT_*DF_];
static __device__ __nv_bfloat16 g_oh[NT_*D_],  g_ol[NT_*D_];
static __device__ __nv_bfloat16 g_qh[NT_*D_],  g_ql[NT_*D_];
static __device__ __nv_bfloat16 g_kh[NT_*D_],  g_kl[NT_*D_];
static __device__ __nv_bfloat16 g_vh[NT_*D_],  g_vl[NT_*D_];
static __device__ __nv_bfloat16 t_attn_h[(size_t)L_*D3_*D_], t_attn_l[(size_t)L_*D3_*D_];
static __device__ __nv_bfloat16 t_proj_h[(size_t)L_*D_*D_],  t_proj_l[(size_t)L_*D_*D_];
static __device__ __nv_bfloat16 t_fc_h[(size_t)L_*DF_*D_],   t_fc_l[(size_t)L_*DF_*D_];
static __device__ __nv_bfloat16 t_fc2_h[(size_t)L_*D_*DF_],  t_fc2_l[(size_t)L_*D_*DF_];

// ---------------- helpers ----------------------------------------------------
__device__ __forceinline__ uint32_t smem_u32(const void* p) {
    uint32_t a;
    asm("{ .reg .u64 t; cvta.to.shared.u64 t, %1; cvt.u32.u64 %0, t; }" : "=r"(a) : "l"(p));
    return a;
}
__device__ __forceinline__ float gelu_f(float x) {
    const float c = 0.7978845608028654f;
    return 0.5f * x * (1.0f + tanhf(c * (x + 0.044715f * x * x * x)));
}
__device__ __forceinline__ void split_bf(float v, __nv_bfloat16& hi, __nv_bfloat16& lo) {
    hi = __float2bfloat16(v);
    lo = __float2bfloat16(v - __bfloat162float(hi));
}
__device__ __forceinline__ void pack_split(float x, float y, uint32_t& hp, uint32_t& lp) {
    __nv_bfloat16 hx, lx, hy, ly;
    split_bf(x, hx, lx); split_bf(y, hy, ly);
    __nv_bfloat162 h2; h2.x = hx; h2.y = hy;
    __nv_bfloat162 l2; l2.x = lx; l2.y = ly;
    hp = *(uint32_t*)&h2; lp = *(uint32_t*)&l2;
}

#define CP16(dst, src) \
    asm volatile("cp.async.cg.shared.global [%0], [%1], 16;" :: "r"(dst), "l"(src))
#define CP_COMMIT() asm volatile("cp.async.commit_group;")
#define CP_WAIT(n)  asm volatile("cp.async.wait_group %0;" :: "n"(n))

#define LDSM_X4(r0, r1, r2, r3, a) \
    asm volatile("ldmatrix.sync.aligned.m8n8.x4.shared.b16 {%0,%1,%2,%3}, [%4];" \
                 : "=r"(r0), "=r"(r1), "=r"(r2), "=r"(r3) : "r"(a))
#define LDSM_X2(r0, r1, a) \
    asm volatile("ldmatrix.sync.aligned.m8n8.x2.shared.b16 {%0,%1}, [%2];" \
                 : "=r"(r0), "=r"(r1) : "r"(a))
#define LDSM_X2_T(r0, r1, a) \
    asm volatile("ldmatrix.sync.aligned.m8n8.x2.trans.shared.b16 {%0,%1}, [%2];" \
                 : "=r"(r0), "=r"(r1) : "r"(a))
#define MMA16816(d, a0, a1, a2, a3, b0, b1) \
    asm volatile("mma.sync.aligned.m16n8k16.row.col.f32.bf16.bf16.f32 " \
                 "{%0,%1,%2,%3},{%4,%5,%6,%7},{%8,%9},{%0,%1,%2,%3};" \
                 : "+f"((d)[0]), "+f"((d)[1]), "+f"((d)[2]), "+f"((d)[3]) \
                 : "r"(a0), "r"(a1), "r"(a2), "r"(a3), "r"(b0), "r"(b1))

// gemm smem tile geometry: 128 rows x 32 bf16, stride 80B
#define TSTRIDE 80
#define MATBYTES 10240
#define STAGEBYTES 40960
#define SMEM_GEMM (2*STAGEBYTES)

// flash smem: rows of 64 bf16 (128B) padded to 144B
#define FSTR 144
#define QOFF_H 0
#define QOFF_L 9216
#define KOFF_H 18432
#define KOFF_L 36864
#define VOFF_H 55296
#define VOFF_L 73728
#define SMEM_FLASH 92160

// ---------------- embedding --------------------------------------------------
__global__ void embed_kernel(const int* __restrict__ ids, const int* __restrict__ rfi,
                             const float* __restrict__ wte, const float* __restrict__ wte_rf,
                             const float* __restrict__ wpe, float* __restrict__ out) {
    int row = blockIdx.x;
    int s = row & (S_ - 1);
    const float* e1 = wte    + (size_t)ids[row] * D_;
    const float* e2 = wte_rf + (size_t)rfi[row] * D_;
    const float* e3 = wpe    + (size_t)s * D_;
    float* o = out + (size_t)row * D_;
    for (int d = threadIdx.x; d < D_; d += blockDim.x)
        o[d] = e1[d] + e2[d] + e3[d];
}

// ---------------- weight transpose + bf16 hi/lo split ------------------------
__global__ void wsplit_kernel(const float* __restrict__ W, __nv_bfloat16* __restrict__ Oh,
                              __nv_bfloat16* __restrict__ Ol, int K, int N) {
    __shared__ float t[32][33];
    int l = blockIdx.z;
    const float* Wl = W + (size_t)l * K * N;
    __nv_bfloat16* OhL = Oh + (size_t)l * K * N;
    __nv_bfloat16* OlL = Ol + (size_t)l * K * N;
    int n0 = blockIdx.x * 32, k0 = blockIdx.y * 32;
    int tx = threadIdx.x, ty = threadIdx.y;    // (32,8)
    for (int i = ty; i < 32; i += 8)
        t[i][tx] = Wl[(size_t)(k0 + i) * N + n0 + tx];
    __syncthreads();
    for (int i = ty; i < 32; i += 8) {
        float v = t[tx][i];
        __nv_bfloat16 hi, lo; split_bf(v, hi, lo);
        size_t idx = (size_t)(n0 + i) * K + k0 + tx;
        OhL[idx] = hi; OlL[idx] = lo;
    }
}

// ---------------- layernorm --------------------------------------------------
template<bool BF>
__global__ void ln_kernel(const float* __restrict__ x, const float* __restrict__ g,
                          const float* __restrict__ b, float* __restrict__ y,
                          __nv_bfloat16* __restrict__ yh, __nv_bfloat16* __restrict__ yl) {
    int row = blockIdx.x;
    int t = threadIdx.x;
    const float* xr = x + (size_t)row * D_;
    float v0 = xr[t], v1 = xr[t + 256], v2 = xr[t + 512];
    __shared__ float red[256];
    red[t] = v0 + v1 + v2;
    __syncthreads();
    for (int o = 128; o > 0; o >>= 1) { if (t < o) red[t] += red[t + o]; __syncthreads(); }
    float mu = red[0] * (1.0f / D_);
    __syncthreads();
    float d0 = v0 - mu, d1 = v1 - mu, d2 = v2 - mu;
    red[t] = d0*d0 + d1*d1 + d2*d2;
    __syncthreads();
    for (int o = 128; o > 0; o >>= 1) { if (t < o) red[t] += red[t + o]; __syncthreads(); }
    float inv = rsqrtf(red[0] * (1.0f / D_) + 1e-5f);
    float r0 = d0 * inv * g[t]       + b[t];
    float r1 = d1 * inv * g[t + 256] + b[t + 256];
    float r2 = d2 * inv * g[t + 512] + b[t + 512];
    if (BF) {
        __nv_bfloat16 hi, lo;
        size_t base = (size_t)row * D_;
        split_bf(r0, hi, lo); yh[base + t]       = hi; yl[base + t]       = lo;
        split_bf(r1, hi, lo); yh[base + t + 256] = hi; yl[base + t + 256] = lo;
        split_bf(r2, hi, lo); yh[base + t + 512] = hi; yl[base + t + 512] = lo;
    } else {
        float* yr = y + (size_t)row * D_;
        yr[t] = r0; yr[t + 256] = r1; yr[t + 512] = r2;
    }
}

// ---------------- mma.sync GEMM ----------------------------------------------
// acc = Ah*Bh + Ah*Bl + Al*Bh (fp32 accumulate)
// EPI 0: Cf = acc+bias.  EPI 1: Cf = acc+bias+resid.
// EPI 2: Ch/Cl = split(gelu(acc+bias)).  EPI 3: head-major split Q/K/V write.
template<int EPI>
__global__ void __launch_bounds__(256, 2)
gemm_mma(const __nv_bfloat16* __restrict__ Ah, const __nv_bfloat16* __restrict__ Al,
         const __nv_bfloat16* __restrict__ Bh, const __nv_bfloat16* __restrict__ Bl,
         const float* __restrict__ bias, const float* __restrict__ resid,
         float* __restrict__ Cf, __nv_bfloat16* __restrict__ Ch, __nv_bfloat16* __restrict__ Cl,
         __nv_bfloat16* __restrict__ Qh_, __nv_bfloat16* __restrict__ Ql_,
         __nv_bfloat16* __restrict__ Kh_, __nv_bfloat16* __restrict__ Kl_,
         __nv_bfloat16* __restrict__ Vh_, __nv_bfloat16* __restrict__ Vl_,
         int M, int N, int K) {
    extern __shared__ char smem[];
    uint32_t sbase = smem_u32(smem);
    int tid = threadIdx.x;
    int wid = tid >> 5, lane = tid & 31;
    int wm = wid >> 2, wn = wid & 3;           // warp grid 2x4, warp tile 64x32
    int m0 = blockIdx.y << 7, n0 = blockIdx.x << 7;
    int ldb = K * 2;

    const char* srcs[4];
    srcs[0] = (const char*)(Ah + (size_t)m0 * K);
    srcs[1] = (const char*)(Al + (size_t)m0 * K);
    srcs[2] = (const char*)(Bh + (size_t)n0 * K);
    srcs[3] = (const char*)(Bl + (size_t)n0 * K);

    float acc[4][4][4] = {};
    int nk = K >> 5;

#define PREFETCH(c, s)                                                        \
    {                                                                         \
        size_t ko = (size_t)(c) << 6;                                         \
        uint32_t stb = sbase + (s) * STAGEBYTES;                              \
        _Pragma("unroll")                                                     \
        for (int j = 0; j < 8; j++) {                                         \
            int q = tid + j * 256;                                            \
            int mat = q >> 9, w = q & 511, row = w >> 2, cc = w & 3;          \
            uint32_t dst = stb + mat * MATBYTES + row * TSTRIDE + cc * 16;    \
            const char* sp = srcs[mat] + (size_t)row * ldb + ko + cc * 16;    \
            CP16(dst, sp);                                                    \
        }                                                                     \
        CP_COMMIT();                                                          \
    }

    PREFETCH(0, 0);

    int aRow = wm * 64 + (lane & 7) + ((lane >> 3) & 1) * 8;
    uint32_t aKoff = ((lane >> 4) & 1) * 16;
    int lb = lane & 15;
    int bRow = wn * 32 + (lb & 7);
    uint32_t bKoff = ((lb >> 3) & 1) * 16;

    for (int c = 0; c < nk; c++) {
        int s = c & 1;
        if (c + 1 < nk) PREFETCH(c + 1, s ^ 1);
        if (c + 1 < nk) { CP_WAIT(1); } else { CP_WAIT(0); }
        __syncthreads();

        uint32_t stb = sbase + s * STAGEBYTES;
        #pragma unroll
        for (int kk = 0; kk < 2; kk++) {
            uint32_t bh[4][2], bl[4][2];
            #pragma unroll
            for (int nj = 0; nj < 4; nj++) {
                uint32_t addr = stb + 2 * MATBYTES + (bRow + nj * 8) * TSTRIDE + kk * 32 + bKoff;
                LDSM_X2(bh[nj][0], bh[nj][1], addr);
                LDSM_X2(bl[nj][0], bl[nj][1], addr + MATBYTES);
            }
            uint32_t af[4][4];
            // pass 1+2: Ah x (Bh, Bl)
            #pragma unroll
            for (int mi = 0; mi < 4; mi++) {
                uint32_t addr = stb + (aRow + mi * 16) * TSTRIDE + kk * 32 + aKoff;
                LDSM_X4(af[mi][0], af[mi][1], af[mi][2], af[mi][3], addr);
            }
            #pragma unroll
            for (int mi = 0; mi < 4; mi++)
                #pragma unroll
                for (int nj = 0; nj < 4; nj++) {
                    MMA16816(acc[mi][nj], af[mi][0], af[mi][1], af[mi][2], af[mi][3],
                             bh[nj][0], bh[nj][1]);
                    MMA16816(acc[mi][nj], af[mi][0], af[mi][1], af[mi][2], af[mi][3],
                             bl[nj][0], bl[nj][1]);
                }
            // pass 3: Al x Bh (Al overwrites Ah's registers)
            #pragma unroll
            for (int mi = 0; mi < 4; mi++) {
                uint32_t addr = stb + MATBYTES + (aRow + mi * 16) * TSTRIDE + kk * 32 + aKoff;
                LDSM_X4(af[mi][0], af[mi][1], af[mi][2], af[mi][3], addr);
            }
            #pragma unroll
            for (int mi = 0; mi < 4; mi++)
                #pragma unroll
                for (int nj = 0; nj < 4; nj++)
                    MMA16816(acc[mi][nj], af[mi][0], af[mi][1], af[mi][2], af[mi][3],
                             bh[nj][0], bh[nj][1]);
        }
        __syncthreads();
    }

    int rbase = m0 + wm * 64 + (lane >> 2);
    int cbase = n0 + wn * 32 + (lane & 3) * 2;
    #pragma unroll
    for (int mi = 0; mi < 4; mi++) {
        #pragma unroll
        for (int nj = 0; nj < 4; nj++) {
            int r = rbase + mi * 16;
            int col = cbase + nj * 8;
            float b0 = bias[col], b1 = bias[col + 1];
            float v00 = acc[mi][nj][0] + b0, v01 = acc[mi][nj][1] + b1;
            float v10 = acc[mi][nj][2] + b0, v11 = acc[mi][nj][3] + b1;
            size_t i0 = (size_t)r * N + col;
            size_t i1 = (size_t)(r + 8) * N + col;
            if (EPI == 0) {
                *(float2*)&Cf[i0] = make_float2(v00, v01);
                *(float2*)&Cf[i1] = make_float2(v10, v11);
            } else if (EPI == 1) {
                float2 r0 = *(const float2*)&resid[i0];
                float2 r1 = *(const float2*)&resid[i1];
                *(float2*)&Cf[i0] = make_float2(v00 + r0.x, v01 + r0.y);
                *(float2*)&Cf[i1] = make_float2(v10 + r1.x, v11 + r1.y);
            } else if (EPI == 2) {
                v00 = gelu_f(v00); v01 = gelu_f(v01);
                v10 = gelu_f(v10); v11 = gelu_f(v11);
                uint32_t hp, lp;
                pack_split(v00, v01, hp, lp);
                *(uint32_t*)&Ch[i0] = hp; *(uint32_t*)&Cl[i0] = lp;
                pack_split(v10, v11, hp, lp);
                *(uint32_t*)&Ch[i1] = hp; *(uint32_t*)&Cl[i1] = lp;
            } else {
                // EPI 3: head-major split write of q/k/v
                int which = col / D_;
                int hh = (col % D_) / DH_;
                int dd = col % DH_;
                __nv_bfloat16* dh_ = which == 0 ? Qh_ : (which == 1 ? Kh_ : Vh_);
                __nv_bfloat16* dl_ = which == 0 ? Ql_ : (which == 1 ? Kl_ : Vl_);
                int bi = r >> 10, si = r & 1023;
                size_t j0 = (((size_t)(bi * H_ + hh)) * S_ + si) * DH_ + dd;
                size_t j1 = j0 + 8 * DH_;
                uint32_t hp, lp;
                pack_split(v00, v01, hp, lp);
                *(uint32_t*)&dh_[j0] = hp; *(uint32_t*)&dl_[j0] = lp;
                pack_split(v10, v11, hp, lp);
                *(uint32_t*)&dh_[j1] = hp; *(uint32_t*)&dl_[j1] = lp;
            }
        }
    }
#undef PREFETCH
}

// ---------------- fused flash attention --------------------------------------
// grid (S/64, B*H), 128 threads (4 warps). 64 q-rows/CTA, KV tiles of 128.
__global__ void __launch_bounds__(128)
flash_kernel(const __nv_bfloat16* __restrict__ qh, const __nv_bfloat16* __restrict__ ql,
             const __nv_bfloat16* __restrict__ kh, const __nv_bfloat16* __restrict__ kl,
             const __nv_bfloat16* __restrict__ vh, const __nv_bfloat16* __restrict__ vl,
             __nv_bfloat16* __restrict__ oh, __nv_bfloat16* __restrict__ ol) {
    extern __shared__ char fsm[];
    uint32_t sb = smem_u32(fsm);
    int bh = blockIdx.y;
    int q0 = blockIdx.x << 6;
    int tid = threadIdx.x, wid = tid >> 5, lane = tid & 31;

    {   // Q tile load (64 rows x 128B), hi+lo
        const char* srcH = (const char*)(qh + ((size_t)bh * S_ + q0) * DH_);
        const char* srcL = (const char*)(ql + ((size_t)bh * S_ + q0) * DH_);
        #pragma unroll
        for (int i = tid; i < 512; i += 128) {
            int r = i >> 3, c = (i & 7) << 4;
            CP16(sb + QOFF_H + r * FSTR + c, srcH + r * 128 + c);
            CP16(sb + QOFF_L + r * FSTR + c, srcL + r * 128 + c);
        }
        CP_COMMIT();
    }

    float m0 = -1e30f, m1 = -1e30f, l0 = 0.f, l1 = 0.f;
    float oacc[8][4];
    #pragma unroll
    for (int d = 0; d < 8; d++)
        oacc[d][0] = oacc[d][1] = oacc[d][2] = oacc[d][3] = 0.f;

    int rA = q0 + wid * 16 + (lane >> 2);
    int nj = (q0 >> 7) + 1;

    uint32_t aAddrBase = sb + (wid * 16 + (lane & 15)) * FSTR + (((lane >> 4) & 1) << 4);
    uint32_t bRowOff = (uint32_t)((lane & 7) * FSTR) + (((lane >> 3) & 1) << 4);

    for (int j = 0; j < nj; j++) {
        __syncthreads();
        {   // K/V tile load (128 rows x 128B) x4 matrices
            const char* kH = (const char*)(kh + ((size_t)bh * S_ + (j << 7)) * DH_);
            const char* kL = (const char*)(kl + ((size_t)bh * S_ + (j << 7)) * DH_);
            const char* vH = (const char*)(vh + ((size_t)bh * S_ + (j << 7)) * DH_);
            const char* vL = (const char*)(vl + ((size_t)bh * S_ + (j << 7)) * DH_);
            #pragma unroll
            for (int i = tid; i < 1024; i += 128) {
                int r = i >> 3, c = (i & 7) << 4;
                uint32_t so = r * FSTR + c;
                size_t go = (size_t)r * 128 + c;
                CP16(sb + KOFF_H + so, kH + go);
                CP16(sb + KOFF_L + so, kL + go);
                CP16(sb + VOFF_H + so, vH + go);
                CP16(sb + VOFF_L + so, vL + go);
            }
            CP_COMMIT();
            CP_WAIT(0);
        }
        __syncthreads();

        // --- S = Q @ K^T (split precision, 3 passes) ---
        float sf[16][4];
        #pragma unroll
        for (int nt = 0; nt < 16; nt++)
            sf[nt][0] = sf[nt][1] = sf[nt][2] = sf[nt][3] = 0.f;

        #pragma unroll
        for (int kc = 0; kc < 4; kc++) {
            uint32_t qa = aAddrBase + kc * 32;
            uint32_t q_h0,q_h1,q_h2,q_h3, q_l0,q_l1,q_l2,q_l3;
            LDSM_X4(q_h0,q_h1,q_h2,q_h3, qa + QOFF_H);
            LDSM_X4(q_l0,q_l1,q_l2,q_l3, qa + QOFF_L);
            #pragma unroll
            for (int nt = 0; nt < 16; nt++) {
                uint32_t ka = sb + KOFF_H + nt * 8 * FSTR + bRowOff + kc * 32;
                uint32_t k_h0,k_h1, k_l0,k_l1;
                LDSM_X2(k_h0,k_h1, ka);
                LDSM_X2(k_l0,k_l1, ka + 18432);
                MMA16816(sf[nt], q_h0,q_h1,q_h2,q_h3, k_h0,k_h1);
                MMA16816(sf[nt], q_h0,q_h1,q_h2,q_h3, k_l0,k_l1);
                MMA16816(sf[nt], q_l0,q_l1,q_l2,q_l3, k_h0,k_h1);
            }
        }

        // --- masking + online softmax ---
        int cb = (j << 7) + (lane & 3) * 2;
        float mx0 = -1e30f, mx1 = -1e30f;
        #pragma unroll
        for (int nt = 0; nt < 16; nt++) {
            int c0 = cb + nt * 8;
            sf[nt][0] = (c0     <= rA)     ? sf[nt][0] * 0.125f : -1e30f;
            sf[nt][1] = (c0 + 1 <= rA)     ? sf[nt][1] * 0.125f : -1e30f;
            sf[nt][2] = (c0     <= rA + 8) ? sf[nt][2] * 0.125f : -1e30f;
            sf[nt][3] = (c0 + 1 <= rA + 8) ? sf[nt][3] * 0.125f : -1e30f;
            mx0 = fmaxf(mx0, fmaxf(sf[nt][0], sf[nt][1]));
            mx1 = fmaxf(mx1, fmaxf(sf[nt][2], sf[nt][3]));
        }
        mx0 = fmaxf(mx0, __shfl_xor_sync(0xffffffffu, mx0, 1));
        mx0 = fmaxf(mx0, __shfl_xor_sync(0xffffffffu, mx0, 2));
        mx1 = fmaxf(mx1, __shfl_xor_sync(0xffffffffu, mx1, 1));
        mx1 = fmaxf(mx1, __shfl_xor_sync(0xffffffffu, mx1, 2));
        float mn0 = fmaxf(m0, mx0), mn1 = fmaxf(m1, mx1);
        float sc0 = expf(m0 - mn0), sc1 = expf(m1 - mn1);
        m0 = mn0; m1 = mn1;
        l0 *= sc0; l1 *= sc1;
        #pragma unroll
        for (int d = 0; d < 8; d++) {
            oacc[d][0] *= sc0; oacc[d][1] *= sc0;
            oacc[d][2] *= sc1; oacc[d][3] *= sc1;
        }
        float s0 = 0.f, s1 = 0.f;
        uint32_t ph[16][2], pl[16][2];
        #pragma unroll
        for (int nt = 0; nt < 16; nt++) {
            float p0 = expf(sf[nt][0] - m0), p1 = expf(sf[nt][1] - m0);
            float p2 = expf(sf[nt][2] - m1), p3 = expf(sf[nt][3] - m1);
            s0 += p0 + p1; s1 += p2 + p3;
            pack_split(p0, p1, ph[nt][0], pl[nt][0]);
            pack_split(p2, p3, ph[nt][1], pl[nt][1]);
        }
        s0 += __shfl_xor_sync(0xffffffffu, s0, 1);
        s0 += __shfl_xor_sync(0xffffffffu, s0, 2);
        s1 += __shfl_xor_sync(0xffffffffu, s1, 1);
        s1 += __shfl_xor_sync(0xffffffffu, s1, 2);
        l0 += s0; l1 += s1;

        // --- O += P @ V (split precision, 3 passes) ---
        #pragma unroll
        for (int kc = 0; kc < 8; kc++) {
            uint32_t va = sb + VOFF_H + (kc * 16 + (lane & 15)) * FSTR;
            #pragma unroll
            for (int dt = 0; dt < 8; dt++) {
                uint32_t v_h0,v_h1, v_l0,v_l1;
                LDSM_X2_T(v_h0,v_h1, va + dt * 16);
                LDSM_X2_T(v_l0,v_l1, va + 18432 + dt * 16);
                MMA16816(oacc[dt], ph[2*kc][0], ph[2*kc][1], ph[2*kc+1][0], ph[2*kc+1][1], v_h0, v_h1);
                MMA16816(oacc[dt], ph[2*kc][0], ph[2*kc][1], ph[2*kc+1][0], ph[2*kc+1][1], v_l0, v_l1);
                MMA16816(oacc[dt], pl[2*kc][0], pl[2*kc][1], pl[2*kc+1][0], pl[2*kc+1][1], v_h0, v_h1);
            }
        }
    }

    // --- finalize ---
    float inv0 = 1.f / l0, inv1 = 1.f / l1;
    int bb = bh / H_, hH = bh % H_;
    size_t baseA = ((size_t)bb * S_ + rA) * D_ + hH * DH_;
    size_t baseB = baseA + 8 * D_;
    #pragma unroll
    for (int dt = 0; dt < 8; dt++) {
        int c = dt * 8 + (lane & 3) * 2;
        uint32_t hp, lp;
        pack_split(oacc[dt][0] * inv0, oacc[dt][1] * inv0, hp, lp);
        *(uint32_t*)&oh[baseA + c] = hp;
        *(uint32_t*)&ol[baseA + c] = lp;
        pack_split(oacc[dt][2] * inv1, oacc[dt][3] * inv1, hp, lp);
        *(uint32_t*)&oh[baseB + c] = hp;
        *(uint32_t*)&ol[baseB + c] = lp;
    }
}

// ---------------- host orchestration -----------------------------------------
extern "C" void kernel_launch(void* const* d_in, const int* in_sizes, int n_in,
                              void* d_out, int out_size) {
    const int*   ids    = (const int*)d_in[0];
    const int*   rfi    = (const int*)d_in[1];
    const float* wte    = (const float*)d_in[2];
    const float* wte_rf = (const float*)d_in[3];
    const float* wpe    = (const float*)d_in[4];
    const float* ln1_g  = (const float*)d_in[5];
    const float* ln1_b  = (const float*)d_in[6];
    const float* attn_w = (const float*)d_in[7];
    const float* attn_b = (const float*)d_in[8];
    const float* proj_w = (const float*)d_in[9];
    const float* proj_b = (const float*)d_in[10];
    const float* ln2_g  = (const float*)d_in[11];
    const float* ln2_b  = (const float*)d_in[12];
    const float* fc_w   = (const float*)d_in[13];
    const float* fc_b   = (const float*)d_in[14];
    const float* fc2_w  = (const float*)d_in[15];
    const float* fc2_b  = (const float*)d_in[16];
    const float* lnf_g  = (const float*)d_in[17];
    const float* lnf_b  = (const float*)d_in[18];
    float* out = (float*)d_out;

    float *h;
    __nv_bfloat16 *ah, *al, *mh, *ml, *oh, *ol;
    __nv_bfloat16 *qh, *ql, *kh, *kl, *vh, *vl;
    __nv_bfloat16 *tah, *tal, *tph, *tpl, *tfh, *tfl, *t2h, *t2l;
    cudaGetSymbolAddress((void**)&h,   g_h);
    cudaGetSymbolAddress((void**)&ah,  g_ah);  cudaGetSymbolAddress((void**)&al,  g_al);
    cudaGetSymbolAddress((void**)&mh,  g_mh);  cudaGetSymbolAddress((void**)&ml,  g_ml);
    cudaGetSymbolAddress((void**)&oh,  g_oh);  cudaGetSymbolAddress((void**)&ol,  g_ol);
    cudaGetSymbolAddress((void**)&qh,  g_qh);  cudaGetSymbolAddress((void**)&ql,  g_ql);
    cudaGetSymbolAddress((void**)&kh,  g_kh);  cudaGetSymbolAddress((void**)&kl,  g_kl);
    cudaGetSymbolAddress((void**)&vh,  g_vh);  cudaGetSymbolAddress((void**)&vl,  g_vl);
    cudaGetSymbolAddress((void**)&tah, t_attn_h); cudaGetSymbolAddress((void**)&tal, t_attn_l);
    cudaGetSymbolAddress((void**)&tph, t_proj_h); cudaGetSymbolAddress((void**)&tpl, t_proj_l);
    cudaGetSymbolAddress((void**)&tfh, t_fc_h);   cudaGetSymbolAddress((void**)&tfl, t_fc_l);
    cudaGetSymbolAddress((void**)&t2h, t_fc2_h);  cudaGetSymbolAddress((void**)&t2l, t_fc2_l);

    cudaFuncSetAttribute(gemm_mma<1>, cudaFuncAttributeMaxDynamicSharedMemorySize, SMEM_GEMM);
    cudaFuncSetAttribute(gemm_mma<2>, cudaFuncAttributeMaxDynamicSharedMemorySize, SMEM_GEMM);
    cudaFuncSetAttribute(gemm_mma<3>, cudaFuncAttributeMaxDynamicSharedMemorySize, SMEM_GEMM);
    cudaFuncSetAttribute(flash_kernel, cudaFuncAttributeMaxDynamicSharedMemorySize, SMEM_FLASH);

    dim3 wblk(32, 8);
    wsplit_kernel<<<dim3(D3_/32, D_/32, L_), wblk>>>(attn_w, tah, tal, D_, D3_);
    wsplit_kernel<<<dim3(D_/32,  D_/32, L_), wblk>>>(proj_w, tph, tpl, D_, D_);
    wsplit_kernel<<<dim3(DF_/32, D_/32, L_), wblk>>>(fc_w,   tfh, tfl, D_, DF_);
    wsplit_kernel<<<dim3(D_/32, DF_/32, L_), wblk>>>(fc2_w,  t2h, t2l, DF_, D_);

    embed_kernel<<<NT_, 256>>>(ids, rfi, wte, wte_rf, wpe, h);

    for (int l = 0; l < L_; l++) {
        ln_kernel<true><<<NT_, 256>>>(h, ln1_g + l * D_, ln1_b + l * D_, nullptr, ah, al);
        gemm_mma<3><<<dim3(D3_/128, NT_/128), 256, SMEM_GEMM>>>(
            ah, al, tah + (size_t)l * D3_ * D_, tal + (size_t)l * D3_ * D_,
            attn_b + l * D3_, nullptr, nullptr, nullptr, nullptr,
            qh, ql, kh, kl, vh, vl, NT_, D3_, D_);
        flash_kernel<<<dim3(S_/64, B_*H_), 128, SMEM_FLASH>>>(qh, ql, kh, kl, vh, vl, oh, ol);
        gemm_mma<1><<<dim3(D_/128, NT_/128), 256, SMEM_GEMM>>>(
            oh, ol, tph + (size_t)l * D_ * D_, tpl + (size_t)l * D_ * D_,
            proj_b + l * D_, h, h, nullptr, nullptr,
            nullptr, nullptr, nullptr, nullptr, nullptr, nullptr, NT_, D_, D_);
        ln_kernel<true><<<NT_, 256>>>(h, ln2_g + l * D_, ln2_b + l * D_, nullptr, ah, al);
        gemm_mma<2><<<dim3(DF_/128, NT_/128), 256, SMEM_GEMM>>>(
            ah, al, tfh + (size_t)l * DF_ * D_, tfl + (size_t)l * DF_ * D_,
            fc_b + l * DF_, nullptr, nullptr, mh, ml,
            nullptr, nullptr, nullptr, nullptr, nullptr, nullptr, NT_, DF_, D_);
        gemm_mma<1><<<dim3(D_/128, NT_/128), 256, SMEM_GEMM>>>(
            mh, ml, t2h + (size_t)l * D_ * DF_, t2l + (size_t)l * D_ * DF_,
            fc2_b + l * D_, h, h, nullptr, nullptr,
            nullptr, nullptr, nullptr, nullptr, nullptr, nullptr, NT_, D_, DF_);
    }
    ln_kernel<false><<<NT_, 256>>>(h, lnf_g, lnf_b, out, nullptr, nullptr);
}

// round 6
// speedup vs baseline: 2.7705x; 1.0037x over previous
#include <cuda_runtime.h>
#include <cuda_bf16.h>
#include <math.h>
#include <stdint.h>

#define B_  4
#define S_  1024
#define D_  768
#define H_  12
#define L_  6
#define DF_ 3072
#define DH_ 64
#define NT_ (B_*S_)        // 4096
#define D3_ (3*D_)         // 2304

// ---------------- scratch (static device globals) ----------------------------
static __device__ float g_h[NT_*D_];
static __device__ __nv_bfloat16 g_ah[NT_*D_],  g_al[NT_*D_];
static __device__ __nv_bfloat16 g_mh[NT_*DF_], g_ml[NT_*DF_];
static __device__ __nv_bfloat16 g_oh[NT_*D_],  g_ol[NT_*D_];
static __device__ __nv_bfloat16 g_qh[NT_*D_],  g_ql[NT_*D_];
static __device__ __nv_bfloat16 g_kh[NT_*D_],  g_kl[NT_*D_];
static __device__ __nv_bfloat16 g_vh[NT_*D_],  g_vl[NT_*D_];
static __device__ __nv_bfloat16 t_attn_h[(size_t)L_*D3_*D_], t_attn_l[(size_t)L_*D3_*D_];
static __device__ __nv_bfloat16 t_proj_h[(size_t)L_*D_*D_],  t_proj_l[(size_t)L_*D_*D_];
static __device__ __nv_bfloat16 t_fc_h[(size_t)L_*DF_*D_],   t_fc_l[(size_t)L_*DF_*D_];
static __device__ __nv_bfloat16 t_fc2_h[(size_t)L_*D_*DF_],  t_fc2_l[(size_t)L_*D_*DF_];

// ---------------- helpers ----------------------------------------------------
__device__ __forceinline__ uint32_t smem_u32(const void* p) {
    uint32_t a;
    asm("{ .reg .u64 t; cvta.to.shared.u64 t, %1; cvt.u32.u64 %0, t; }" : "=r"(a) : "l"(p));
    return a;
}
__device__ __forceinline__ float gelu_f(float x) {
    const float c = 0.7978845608028654f;
    return 0.5f * x * (1.0f + tanhf(c * (x + 0.044715f * x * x * x)));
}
__device__ __forceinline__ void split_bf(float v, __nv_bfloat16& hi, __nv_bfloat16& lo) {
    hi = __float2bfloat16(v);
    lo = __float2bfloat16(v - __bfloat162float(hi));
}
__device__ __forceinline__ void pack_split(float x, float y, uint32_t& hp, uint32_t& lp) {
    __nv_bfloat16 hx, lx, hy, ly;
    split_bf(x, hx, lx); split_bf(y, hy, ly);
    __nv_bfloat162 h2; h2.x = hx; h2.y = hy;
    __nv_bfloat162 l2; l2.x = lx; l2.y = ly;
    hp = *(uint32_t*)&h2; lp = *(uint32_t*)&l2;
}

#define CP16(dst, src) \
    asm volatile("cp.async.cg.shared.global [%0], [%1], 16;" :: "r"(dst), "l"(src))
#define CP_COMMIT() asm volatile("cp.async.commit_group;")
#define CP_WAIT(n)  asm volatile("cp.async.wait_group %0;" :: "n"(n))

#define LDSM_X4(r0, r1, r2, r3, a) \
    asm volatile("ldmatrix.sync.aligned.m8n8.x4.shared.b16 {%0,%1,%2,%3}, [%4];" \
                 : "=r"(r0), "=r"(r1), "=r"(r2), "=r"(r3) : "r"(a))
#define LDSM_X2(r0, r1, a) \
    asm volatile("ldmatrix.sync.aligned.m8n8.x2.shared.b16 {%0,%1}, [%2];" \
                 : "=r"(r0), "=r"(r1) : "r"(a))
#define LDSM_X2_T(r0, r1, a) \
    asm volatile("ldmatrix.sync.aligned.m8n8.x2.trans.shared.b16 {%0,%1}, [%2];" \
                 : "=r"(r0), "=r"(r1) : "r"(a))
#define MMA16816(d, a0, a1, a2, a3, b0, b1) \
    asm volatile("mma.sync.aligned.m16n8k16.row.col.f32.bf16.bf16.f32 " \
                 "{%0,%1,%2,%3},{%4,%5,%6,%7},{%8,%9},{%0,%1,%2,%3};" \
                 : "+f"((d)[0]), "+f"((d)[1]), "+f"((d)[2]), "+f"((d)[3]) \
                 : "r"(a0), "r"(a1), "r"(a2), "r"(a3), "r"(b0), "r"(b1))

// gemm smem tile geometry: 128 rows x 32 bf16, stride 80B
#define TSTRIDE 80
#define MATBYTES 10240
#define STAGEBYTES 40960
#define SMEM_GEMM (2*STAGEBYTES)

// flash smem: rows of 64 bf16 (128B) padded to 144B
#define FSTR 144
#define QOFF_H 0
#define QOFF_L 9216
#define KOFF_H 18432
#define KOFF_L 36864
#define VOFF_H 55296
#define VOFF_L 73728
#define SMEM_FLASH 92160

// ---------------- fused weight transpose + split (all 4 weight sets) ---------
// 1D grid over all tiles of all layers.
// Per layer: attn 72x24=1728, proj 24x24=576, fc 96x24=2304, fc2 24x96=2304.
#define TILES_PER_LAYER 6912
__global__ void wsplit_all_kernel(const float* __restrict__ attn_w, const float* __restrict__ proj_w,
                                  const float* __restrict__ fc_w,   const float* __restrict__ fc2_w,
                                  __nv_bfloat16* __restrict__ tah, __nv_bfloat16* __restrict__ tal,
                                  __nv_bfloat16* __restrict__ tph, __nv_bfloat16* __restrict__ tpl,
                                  __nv_bfloat16* __restrict__ tfh, __nv_bfloat16* __restrict__ tfl,
                                  __nv_bfloat16* __restrict__ t2h, __nv_bfloat16* __restrict__ t2l) {
    __shared__ float t[32][33];
    int bid = blockIdx.x;
    int l = bid / TILES_PER_LAYER;
    int r = bid % TILES_PER_LAYER;
    const float* W; __nv_bfloat16 *Oh, *Ol; int K, N, tile;
    if (r < 1728)      { W = attn_w; Oh = tah; Ol = tal; K = D_;  N = D3_; tile = r; }
    else if (r < 2304) { W = proj_w; Oh = tph; Ol = tpl; K = D_;  N = D_;  tile = r - 1728; }
    else if (r < 4608) { W = fc_w;   Oh = tfh; Ol = tfl; K = D_;  N = DF_; tile = r - 2304; }
    else               { W = fc2_w;  Oh = t2h; Ol = t2l; K = DF_; N = D_;  tile = r - 4608; }
    int nx = N >> 5;
    int n0 = (tile % nx) << 5, k0 = (tile / nx) << 5;
    const float* Wl = W + (size_t)l * K * N;
    __nv_bfloat16* OhL = Oh + (size_t)l * K * N;
    __nv_bfloat16* OlL = Ol + (size_t)l * K * N;
    int tx = threadIdx.x, ty = threadIdx.y;    // (32,8)
    for (int i = ty; i < 32; i += 8)
        t[i][tx] = Wl[(size_t)(k0 + i) * N + n0 + tx];
    __syncthreads();
    for (int i = ty; i < 32; i += 8) {
        float v = t[tx][i];
        __nv_bfloat16 hi, lo; split_bf(v, hi, lo);
        size_t idx = (size_t)(n0 + i) * K + k0 + tx;
        OhL[idx] = hi; OlL[idx] = lo;
    }
}

// ---------------- fused embedding + layer-0 ln1 -------------------------------
__global__ void embed_ln_kernel(const int* __restrict__ ids, const int* __restrict__ rfi,
                                const float* __restrict__ wte, const float* __restrict__ wte_rf,
                                const float* __restrict__ wpe,
                                const float* __restrict__ g, const float* __restrict__ b,
                                float* __restrict__ h,
                                __nv_bfloat16* __restrict__ yh, __nv_bfloat16* __restrict__ yl) {
    int row = blockIdx.x;
    int s = row & (S_ - 1);
    int t = threadIdx.x;
    const float* e1 = wte    + (size_t)ids[row] * D_;
    const float* e2 = wte_rf + (size_t)rfi[row] * D_;
    const float* e3 = wpe    + (size_t)s * D_;
    float v0 = e1[t]       + e2[t]       + e3[t];
    float v1 = e1[t + 256] + e2[t + 256] + e3[t + 256];
    float v2 = e1[t + 512] + e2[t + 512] + e3[t + 512];
    float* hr = h + (size_t)row * D_;
    hr[t] = v0; hr[t + 256] = v1; hr[t + 512] = v2;
    __shared__ float red[256];
    red[t] = v0 + v1 + v2;
    __syncthreads();
    for (int o = 128; o > 0; o >>= 1) { if (t < o) red[t] += red[t + o]; __syncthreads(); }
    float mu = red[0] * (1.0f / D_);
    __syncthreads();
    float d0 = v0 - mu, d1 = v1 - mu, d2 = v2 - mu;
    red[t] = d0*d0 + d1*d1 + d2*d2;
    __syncthreads();
    for (int o = 128; o > 0; o >>= 1) { if (t < o) red[t] += red[t + o]; __syncthreads(); }
    float inv = rsqrtf(red[0] * (1.0f / D_) + 1e-5f);
    float r0 = d0 * inv * g[t]       + b[t];
    float r1 = d1 * inv * g[t + 256] + b[t + 256];
    float r2 = d2 * inv * g[t + 512] + b[t + 512];
    __nv_bfloat16 hi, lo;
    size_t base = (size_t)row * D_;
    split_bf(r0, hi, lo); yh[base + t]       = hi; yl[base + t]       = lo;
    split_bf(r1, hi, lo); yh[base + t + 256] = hi; yl[base + t + 256] = lo;
    split_bf(r2, hi, lo); yh[base + t + 512] = hi; yl[base + t + 512] = lo;
}

// ---------------- layernorm --------------------------------------------------
template<bool BF>
__global__ void ln_kernel(const float* __restrict__ x, const float* __restrict__ g,
                          const float* __restrict__ b, float* __restrict__ y,
                          __nv_bfloat16* __restrict__ yh, __nv_bfloat16* __restrict__ yl) {
    int row = blockIdx.x;
    int t = threadIdx.x;
    const float* xr = x + (size_t)row * D_;
    float v0 = xr[t], v1 = xr[t + 256], v2 = xr[t + 512];
    __shared__ float red[256];
    red[t] = v0 + v1 + v2;
    __syncthreads();
    for (int o = 128; o > 0; o >>= 1) { if (t < o) red[t] += red[t + o]; __syncthreads(); }
    float mu = red[0] * (1.0f / D_);
    __syncthreads();
    float d0 = v0 - mu, d1 = v1 - mu, d2 = v2 - mu;
    red[t] = d0*d0 + d1*d1 + d2*d2;
    __syncthreads();
    for (int o = 128; o > 0; o >>= 1) { if (t < o) red[t] += red[t + o]; __syncthreads(); }
    float inv = rsqrtf(red[0] * (1.0f / D_) + 1e-5f);
    float r0 = d0 * inv * g[t]       + b[t];
    float r1 = d1 * inv * g[t + 256] + b[t + 256];
    float r2 = d2 * inv * g[t + 512] + b[t + 512];
    if (BF) {
        __nv_bfloat16 hi, lo;
        size_t base = (size_t)row * D_;
        split_bf(r0, hi, lo); yh[base + t]       = hi; yl[base + t]       = lo;
        split_bf(r1, hi, lo); yh[base + t + 256] = hi; yl[base + t + 256] = lo;
        split_bf(r2, hi, lo); yh[base + t + 512] = hi; yl[base + t + 512] = lo;
    } else {
        float* yr = y + (size_t)row * D_;
        yr[t] = r0; yr[t + 256] = r1; yr[t + 512] = r2;
    }
}

// ---------------- mma.sync GEMM ----------------------------------------------
template<int EPI>
__global__ void __launch_bounds__(256, 2)
gemm_mma(const __nv_bfloat16* __restrict__ Ah, const __nv_bfloat16* __restrict__ Al,
         const __nv_bfloat16* __restrict__ Bh, const __nv_bfloat16* __restrict__ Bl,
         const float* __restrict__ bias, const float* __restrict__ resid,
         float* __restrict__ Cf, __nv_bfloat16* __restrict__ Ch, __nv_bfloat16* __restrict__ Cl,
         __nv_bfloat16* __restrict__ Qh_, __nv_bfloat16* __restrict__ Ql_,
         __nv_bfloat16* __restrict__ Kh_, __nv_bfloat16* __restrict__ Kl_,
         __nv_bfloat16* __restrict__ Vh_, __nv_bfloat16* __restrict__ Vl_,
         int M, int N, int K) {
    extern __shared__ char smem[];
    uint32_t sbase = smem_u32(smem);
    int tid = threadIdx.x;
    int wid = tid >> 5, lane = tid & 31;
    int wm = wid >> 2, wn = wid & 3;
    int m0 = blockIdx.y << 7, n0 = blockIdx.x << 7;
    int ldb = K * 2;

    const char* srcs[4];
    srcs[0] = (const char*)(Ah + (size_t)m0 * K);
    srcs[1] = (const char*)(Al + (size_t)m0 * K);
    srcs[2] = (const char*)(Bh + (size_t)n0 * K);
    srcs[3] = (const char*)(Bl + (size_t)n0 * K);

    float acc[4][4][4] = {};
    int nk = K >> 5;

#define PREFETCH(c, s)                                                        \
    {                                                                         \
        size_t ko = (size_t)(c) << 6;                                         \
        uint32_t stb = sbase + (s) * STAGEBYTES;                              \
        _Pragma("unroll")                                                     \
        for (int j = 0; j < 8; j++) {                                         \
            int q = tid + j * 256;                                            \
            int mat = q >> 9, w = q & 511, row = w >> 2, cc = w & 3;          \
            uint32_t dst = stb + mat * MATBYTES + row * TSTRIDE + cc * 16;    \
            const char* sp = srcs[mat] + (size_t)row * ldb + ko + cc * 16;    \
            CP16(dst, sp);                                                    \
        }                                                                     \
        CP_COMMIT();                                                          \
    }

    PREFETCH(0, 0);

    int aRow = wm * 64 + (lane & 7) + ((lane >> 3) & 1) * 8;
    uint32_t aKoff = ((lane >> 4) & 1) * 16;
    int lb = lane & 15;
    int bRow = wn * 32 + (lb & 7);
    uint32_t bKoff = ((lb >> 3) & 1) * 16;

    for (int c = 0; c < nk; c++) {
        int s = c & 1;
        if (c + 1 < nk) PREFETCH(c + 1, s ^ 1);
        if (c + 1 < nk) { CP_WAIT(1); } else { CP_WAIT(0); }
        __syncthreads();

        uint32_t stb = sbase + s * STAGEBYTES;
        #pragma unroll
        for (int kk = 0; kk < 2; kk++) {
            uint32_t bh[4][2], bl[4][2];
            #pragma unroll
            for (int nj = 0; nj < 4; nj++) {
                uint32_t addr = stb + 2 * MATBYTES + (bRow + nj * 8) * TSTRIDE + kk * 32 + bKoff;
                LDSM_X2(bh[nj][0], bh[nj][1], addr);
                LDSM_X2(bl[nj][0], bl[nj][1], addr + MATBYTES);
            }
            uint32_t af[4][4];
            #pragma unroll
            for (int mi = 0; mi < 4; mi++) {
                uint32_t addr = stb + (aRow + mi * 16) * TSTRIDE + kk * 32 + aKoff;
                LDSM_X4(af[mi][0], af[mi][1], af[mi][2], af[mi][3], addr);
            }
            #pragma unroll
            for (int mi = 0; mi < 4; mi++)
                #pragma unroll
                for (int nj = 0; nj < 4; nj++) {
                    MMA16816(acc[mi][nj], af[mi][0], af[mi][1], af[mi][2], af[mi][3],
                             bh[nj][0], bh[nj][1]);
                    MMA16816(acc[mi][nj], af[mi][0], af[mi][1], af[mi][2], af[mi][3],
                             bl[nj][0], bl[nj][1]);
                }
            #pragma unroll
            for (int mi = 0; mi < 4; mi++) {
                uint32_t addr = stb + MATBYTES + (aRow + mi * 16) * TSTRIDE + kk * 32 + aKoff;
                LDSM_X4(af[mi][0], af[mi][1], af[mi][2], af[mi][3], addr);
            }
            #pragma unroll
            for (int mi = 0; mi < 4; mi++)
                #pragma unroll
                for (int nj = 0; nj < 4; nj++)
                    MMA16816(acc[mi][nj], af[mi][0], af[mi][1], af[mi][2], af[mi][3],
                             bh[nj][0], bh[nj][1]);
        }
        __syncthreads();
    }

    int rbase = m0 + wm * 64 + (lane >> 2);
    int cbase = n0 + wn * 32 + (lane & 3) * 2;
    #pragma unroll
    for (int mi = 0; mi < 4; mi++) {
        #pragma unroll
        for (int nj = 0; nj < 4; nj++) {
            int r = rbase + mi * 16;
            int col = cbase + nj * 8;
            float b0 = bias[col], b1 = bias[col + 1];
            float v00 = acc[mi][nj][0] + b0, v01 = acc[mi][nj][1] + b1;
            float v10 = acc[mi][nj][2] + b0, v11 = acc[mi][nj][3] + b1;
            size_t i0 = (size_t)r * N + col;
            size_t i1 = (size_t)(r + 8) * N + col;
            if (EPI == 0) {
                *(float2*)&Cf[i0] = make_float2(v00, v01);
                *(float2*)&Cf[i1] = make_float2(v10, v11);
            } else if (EPI == 1) {
                float2 r0 = *(const float2*)&resid[i0];
                float2 r1 = *(const float2*)&resid[i1];
                *(float2*)&Cf[i0] = make_float2(v00 + r0.x, v01 + r0.y);
                *(float2*)&Cf[i1] = make_float2(v10 + r1.x, v11 + r1.y);
            } else if (EPI == 2) {
                v00 = gelu_f(v00); v01 = gelu_f(v01);
                v10 = gelu_f(v10); v11 = gelu_f(v11);
                uint32_t hp, lp;
                pack_split(v00, v01, hp, lp);
                *(uint32_t*)&Ch[i0] = hp; *(uint32_t*)&Cl[i0] = lp;
                pack_split(v10, v11, hp, lp);
                *(uint32_t*)&Ch[i1] = hp; *(uint32_t*)&Cl[i1] = lp;
            } else {
                int which = col / D_;
                int hh = (col % D_) / DH_;
                int dd = col % DH_;
                __nv_bfloat16* dh_ = which == 0 ? Qh_ : (which == 1 ? Kh_ : Vh_);
                __nv_bfloat16* dl_ = which == 0 ? Ql_ : (which == 1 ? Kl_ : Vl_);
                int bi = r >> 10, si = r & 1023;
                size_t j0 = (((size_t)(bi * H_ + hh)) * S_ + si) * DH_ + dd;
                size_t j1 = j0 + 8 * DH_;
                uint32_t hp, lp;
                pack_split(v00, v01, hp, lp);
                *(uint32_t*)&dh_[j0] = hp; *(uint32_t*)&dl_[j0] = lp;
                pack_split(v10, v11, hp, lp);
                *(uint32_t*)&dh_[j1] = hp; *(uint32_t*)&dl_[j1] = lp;
            }
        }
    }
#undef PREFETCH
}

// ---------------- fused flash attention --------------------------------------
// grid (S/64, B*H), 128 threads. q-tiles processed high-causal-length-first.
__global__ void __launch_bounds__(128)
flash_kernel(const __nv_bfloat16* __restrict__ qh, const __nv_bfloat16* __restrict__ ql,
             const __nv_bfloat16* __restrict__ kh, const __nv_bfloat16* __restrict__ kl,
             const __nv_bfloat16* __restrict__ vh, const __nv_bfloat16* __restrict__ vl,
             __nv_bfloat16* __restrict__ oh, __nv_bfloat16* __restrict__ ol) {
    extern __shared__ char fsm[];
    uint32_t sb = smem_u32(fsm);
    int bh = blockIdx.y;
    int q0 = (gridDim.x - 1 - blockIdx.x) << 6;   // long CTAs first
    int tid = threadIdx.x, wid = tid >> 5, lane = tid & 31;

    {   // Q tile load
        const char* srcH = (const char*)(qh + ((size_t)bh * S_ + q0) * DH_);
        const char* srcL = (const char*)(ql + ((size_t)bh * S_ + q0) * DH_);
        #pragma unroll
        for (int i = tid; i < 512; i += 128) {
            int r = i >> 3, c = (i & 7) << 4;
            CP16(sb + QOFF_H + r * FSTR + c, srcH + r * 128 + c);
            CP16(sb + QOFF_L + r * FSTR + c, srcL + r * 128 + c);
        }
        CP_COMMIT();
    }

    float m0 = -1e30f, m1 = -1e30f, l0 = 0.f, l1 = 0.f;
    float oacc[8][4];
    #pragma unroll
    for (int d = 0; d < 8; d++)
        oacc[d][0] = oacc[d][1] = oacc[d][2] = oacc[d][3] = 0.f;

    int rA = q0 + wid * 16 + (lane >> 2);
    int nj = (q0 >> 7) + 1;

    uint32_t aAddrBase = sb + (wid * 16 + (lane & 15)) * FSTR + (((lane >> 4) & 1) << 4);
    uint32_t bRowOff = (uint32_t)((lane & 7) * FSTR) + (((lane >> 3) & 1) << 4);

    for (int j = 0; j < nj; j++) {
        __syncthreads();
        {
            const char* kH = (const char*)(kh + ((size_t)bh * S_ + (j << 7)) * DH_);
            const char* kL = (const char*)(kl + ((size_t)bh * S_ + (j << 7)) * DH_);
            const char* vH = (const char*)(vh + ((size_t)bh * S_ + (j << 7)) * DH_);
            const char* vL = (const char*)(vl + ((size_t)bh * S_ + (j << 7)) * DH_);
            #pragma unroll
            for (int i = tid; i < 1024; i += 128) {
                int r = i >> 3, c = (i & 7) << 4;
                uint32_t so = r * FSTR + c;
                size_t go = (size_t)r * 128 + c;
                CP16(sb + KOFF_H + so, kH + go);
                CP16(sb + KOFF_L + so, kL + go);
                CP16(sb + VOFF_H + so, vH + go);
                CP16(sb + VOFF_L + so, vL + go);
            }
            CP_COMMIT();
            CP_WAIT(0);
        }
        __syncthreads();

        float sf[16][4];
        #pragma unroll
        for (int nt = 0; nt < 16; nt++)
            sf[nt][0] = sf[nt][1] = sf[nt][2] = sf[nt][3] = 0.f;

        #pragma unroll
        for (int kc = 0; kc < 4; kc++) {
            uint32_t qa = aAddrBase + kc * 32;
            uint32_t q_h0,q_h1,q_h2,q_h3, q_l0,q_l1,q_l2,q_l3;
            LDSM_X4(q_h0,q_h1,q_h2,q_h3, qa + QOFF_H);
            LDSM_X4(q_l0,q_l1,q_l2,q_l3, qa + QOFF_L);
            #pragma unroll
            for (int nt = 0; nt < 16; nt++) {
                uint32_t ka = sb + KOFF_H + nt * 8 * FSTR + bRowOff + kc * 32;
                uint32_t k_h0,k_h1, k_l0,k_l1;
                LDSM_X2(k_h0,k_h1, ka);
                LDSM_X2(k_l0,k_l1, ka + 18432);
                MMA16816(sf[nt], q_h0,q_h1,q_h2,q_h3, k_h0,k_h1);
                MMA16816(sf[nt], q_h0,q_h1,q_h2,q_h3, k_l0,k_l1);
                MMA16816(sf[nt], q_l0,q_l1,q_l2,q_l3, k_h0,k_h1);
            }
        }

        int cb = (j << 7) + (lane & 3) * 2;
        float mx0 = -1e30f, mx1 = -1e30f;
        #pragma unroll
        for (int nt = 0; nt < 16; nt++) {
            int c0 = cb + nt * 8;
            sf[nt][0] = (c0     <= rA)     ? sf[nt][0] * 0.125f : -1e30f;
            sf[nt][1] = (c0 + 1 <= rA)     ? sf[nt][1] * 0.125f : -1e30f;
            sf[nt][2] = (c0     <= rA + 8) ? sf[nt][2] * 0.125f : -1e30f;
            sf[nt][3] = (c0 + 1 <= rA + 8) ? sf[nt][3] * 0.125f : -1e30f;
            mx0 = fmaxf(mx0, fmaxf(sf[nt][0], sf[nt][1]));
            mx1 = fmaxf(mx1, fmaxf(sf[nt][2], sf[nt][3]));
        }
        mx0 = fmaxf(mx0, __shfl_xor_sync(0xffffffffu, mx0, 1));
        mx0 = fmaxf(mx0, __shfl_xor_sync(0xffffffffu, mx0, 2));
        mx1 = fmaxf(mx1, __shfl_xor_sync(0xffffffffu, mx1, 1));
        mx1 = fmaxf(mx1, __shfl_xor_sync(0xffffffffu, mx1, 2));
        float mn0 = fmaxf(m0, mx0), mn1 = fmaxf(m1, mx1);
        float sc0 = expf(m0 - mn0), sc1 = expf(m1 - mn1);
        m0 = mn0; m1 = mn1;
        l0 *= sc0; l1 *= sc1;
        #pragma unroll
        for (int d = 0; d < 8; d++) {
            oacc[d][0] *= sc0; oacc[d][1] *= sc0;
            oacc[d][2] *= sc1; oacc[d][3] *= sc1;
        }
        float s0 = 0.f, s1 = 0.f;
        uint32_t ph[16][2], pl[16][2];
        #pragma unroll
        for (int nt = 0; nt < 16; nt++) {
            float p0 = expf(sf[nt][0] - m0), p1 = expf(sf[nt][1] - m0);
            float p2 = expf(sf[nt][2] - m1), p3 = expf(sf[nt][3] - m1);
            s0 += p0 + p1; s1 += p2 + p3;
            pack_split(p0, p1, ph[nt][0], pl[nt][0]);
            pack_split(p2, p3, ph[nt][1], pl[nt][1]);
        }
        s0 += __shfl_xor_sync(0xffffffffu, s0, 1);
        s0 += __shfl_xor_sync(0xffffffffu, s0, 2);
        s1 += __shfl_xor_sync(0xffffffffu, s1, 1);
        s1 += __shfl_xor_sync(0xffffffffu, s1, 2);
        l0 += s0; l1 += s1;

        #pragma unroll
        for (int kc = 0; kc < 8; kc++) {
            uint32_t va = sb + VOFF_H + (kc * 16 + (lane & 15)) * FSTR;
            #pragma unroll
            for (int dt = 0; dt < 8; dt++) {
                uint32_t v_h0,v_h1, v_l0,v_l1;
                LDSM_X2_T(v_h0,v_h1, va + dt * 16);
                LDSM_X2_T(v_l0,v_l1, va + 18432 + dt * 16);
                MMA16816(oacc[dt], ph[2*kc][0], ph[2*kc][1], ph[2*kc+1][0], ph[2*kc+1][1], v_h0, v_h1);
                MMA16816(oacc[dt], ph[2*kc][0], ph[2*kc][1], ph[2*kc+1][0], ph[2*kc+1][1], v_l0, v_l1);
                MMA16816(oacc[dt], pl[2*kc][0], pl[2*kc][1], pl[2*kc+1][0], pl[2*kc+1][1], v_h0, v_h1);
            }
        }
    }

    float inv0 = 1.f / l0, inv1 = 1.f / l1;
    int bb = bh / H_, hH = bh % H_;
    size_t baseA = ((size_t)bb * S_ + rA) * D_ + hH * DH_;
    size_t baseB = baseA + 8 * D_;
    #pragma unroll
    for (int dt = 0; dt < 8; dt++) {
        int c = dt * 8 + (lane & 3) * 2;
        uint32_t hp, lp;
        pack_split(oacc[dt][0] * inv0, oacc[dt][1] * inv0, hp, lp);
        *(uint32_t*)&oh[baseA + c] = hp;
        *(uint32_t*)&ol[baseA + c] = lp;
        pack_split(oacc[dt][2] * inv1, oacc[dt][3] * inv1, hp, lp);
        *(uint32_t*)&oh[baseB + c] = hp;
        *(uint32_t*)&ol[baseB + c] = lp;
    }
}

// ---------------- host orchestration -----------------------------------------
extern "C" void kernel_launch(void* const* d_in, const int* in_sizes, int n_in,
                              void* d_out, int out_size) {
    const int*   ids    = (const int*)d_in[0];
    const int*   rfi    = (const int*)d_in[1];
    const float* wte    = (const float*)d_in[2];
    const float* wte_rf = (const float*)d_in[3];
    const float* wpe    = (const float*)d_in[4];
    const float* ln1_g  = (const float*)d_in[5];
    const float* ln1_b  = (const float*)d_in[6];
    const float* attn_w = (const float*)d_in[7];
    const float* attn_b = (const float*)d_in[8];
    const float* proj_w = (const float*)d_in[9];
    const float* proj_b = (const float*)d_in[10];
    const float* ln2_g  = (const float*)d_in[11];
    const float* ln2_b  = (const float*)d_in[12];
    const float* fc_w   = (const float*)d_in[13];
    const float* fc_b   = (const float*)d_in[14];
    const float* fc2_w  = (const float*)d_in[15];
    const float* fc2_b  = (const float*)d_in[16];
    const float* lnf_g  = (const float*)d_in[17];
    const float* lnf_b  = (const float*)d_in[18];
    float* out = (float*)d_out;

    float *h;
    __nv_bfloat16 *ah, *al, *mh, *ml, *oh, *ol;
    __nv_bfloat16 *qh, *ql, *kh, *kl, *vh, *vl;
    __nv_bfloat16 *tah, *tal, *tph, *tpl, *tfh, *tfl, *t2h, *t2l;
    cudaGetSymbolAddress((void**)&h,   g_h);
    cudaGetSymbolAddress((void**)&ah,  g_ah);  cudaGetSymbolAddress((void**)&al,  g_al);
    cudaGetSymbolAddress((void**)&mh,  g_mh);  cudaGetSymbolAddress((void**)&ml,  g_ml);
    cudaGetSymbolAddress((void**)&oh,  g_oh);  cudaGetSymbolAddress((void**)&ol,  g_ol);
    cudaGetSymbolAddress((void**)&qh,  g_qh);  cudaGetSymbolAddress((void**)&ql,  g_ql);
    cudaGetSymbolAddress((void**)&kh,  g_kh);  cudaGetSymbolAddress((void**)&kl,  g_kl);
    cudaGetSymbolAddress((void**)&vh,  g_vh);  cudaGetSymbolAddress((void**)&vl,  g_vl);
    cudaGetSymbolAddress((void**)&tah, t_attn_h); cudaGetSymbolAddress((void**)&tal, t_attn_l);
    cudaGetSymbolAddress((void**)&tph, t_proj_h); cudaGetSymbolAddress((void**)&tpl, t_proj_l);
    cudaGetSymbolAddress((void**)&tfh, t_fc_h);   cudaGetSymbolAddress((void**)&tfl, t_fc_l);
    cudaGetSymbolAddress((void**)&t2h, t_fc2_h);  cudaGetSymbolAddress((void**)&t2l, t_fc2_l);

    cudaFuncSetAttribute(gemm_mma<1>, cudaFuncAttributeMaxDynamicSharedMemorySize, SMEM_GEMM);
    cudaFuncSetAttribute(gemm_mma<2>, cudaFuncAttributeMaxDynamicSharedMemorySize, SMEM_GEMM);
    cudaFuncSetAttribute(gemm_mma<3>, cudaFuncAttributeMaxDynamicSharedMemorySize, SMEM_GEMM);
    cudaFuncSetAttribute(flash_kernel, cudaFuncAttributeMaxDynamicSharedMemorySize, SMEM_FLASH);

    // launch 0: fused weight split
    wsplit_all_kernel<<<TILES_PER_LAYER * L_, dim3(32, 8)>>>(
        attn_w, proj_w, fc_w, fc2_w, tah, tal, tph, tpl, tfh, tfl, t2h, t2l);
    // launch 1: fused embed + layer0 ln1
    embed_ln_kernel<<<NT_, 256>>>(ids, rfi, wte, wte_rf, wpe, ln1_g, ln1_b, h, ah, al);

    for (int l = 0; l < L_; l++) {
        if (l > 0)
            ln_kernel<true><<<NT_, 256>>>(h, ln1_g + l * D_, ln1_b + l * D_, nullptr, ah, al);
        // launch 2 on first iteration = QKV GEMM (ncu capture target)
        gemm_mma<3><<<dim3(D3_/128, NT_/128), 256, SMEM_GEMM>>>(
            ah, al, tah + (size_t)l * D3_ * D_, tal + (size_t)l * D3_ * D_,
            attn_b + l * D3_, nullptr, nullptr, nullptr, nullptr,
            qh, ql, kh, kl, vh, vl, NT_, D3_, D_);
        flash_kernel<<<dim3(S_/64, B_*H_), 128, SMEM_FLASH>>>(qh, ql, kh, kl, vh, vl, oh, ol);
        gemm_mma<1><<<dim3(D_/128, NT_/128), 256, SMEM_GEMM>>>(
            oh, ol, tph + (size_t)l * D_ * D_, tpl + (size_t)l * D_ * D_,
            proj_b + l * D_, h, h, nullptr, nullptr,
            nullptr, nullptr, nullptr, nullptr, nullptr, nullptr, NT_, D_, D_);
        ln_kernel<true><<<NT_, 256>>>(h, ln2_g + l * D_, ln2_b + l * D_, nullptr, ah, al);
        gemm_mma<2><<<dim3(DF_/128, NT_/128), 256, SMEM_GEMM>>>(
            ah, al, tfh + (size_t)l * DF_ * D_, tfl + (size_t)l * DF_ * D_,
            fc_b + l * DF_, nullptr, nullptr, mh, ml,
            nullptr, nullptr, nullptr, nullptr, nullptr, nullptr, NT_, DF_, D_);
        gemm_mma<1><<<dim3(D_/128, NT_/128), 256, SMEM_GEMM>>>(
            mh, ml, t2h + (size_t)l * D_ * DF_, t2l + (size_t)l * D_ * DF_,
            fc2_b + l * D_, h, h, nullptr, nullptr,
            nullptr, nullptr, nullptr, nullptr, nullptr, nullptr, NT_, D_, DF_);
    }
    ln_kernel<false><<<NT_, 256>>>(h, lnf_g, lnf_b, out, nullptr, nullptr);
}

// round 7
// speedup vs baseline: 3.8309x; 1.3828x over previous
#include <cuda_runtime.h>
#include <cuda_fp16.h>
#include <math.h>
#include <stdint.h>

#define B_  4
#define S_  1024
#define D_  768
#define H_  12
#define L_  6
#define DF_ 3072
#define DH_ 64
#define NT_ (B_*S_)        // 4096
#define D3_ (3*D_)         // 2304

// ---------------- scratch (static device globals) ----------------------------
static __device__ float g_h[NT_*D_];
static __device__ __half g_ah[NT_*D_],  g_al[NT_*D_];
static __device__ __half g_mh[NT_*DF_], g_ml[NT_*DF_];
static __device__ __half g_oh[NT_*D_],  g_ol[NT_*D_];
static __device__ __half g_qh[NT_*D_],  g_ql[NT_*D_];
static __device__ __half g_kh[NT_*D_];
static __device__ __half g_vh[NT_*D_];
static __device__ __half t_attn_h[(size_t)L_*D3_*D_];
static __device__ __half t_proj_h[(size_t)L_*D_*D_];
static __device__ __half t_fc_h[(size_t)L_*DF_*D_];
static __device__ __half t_fc2_h[(size_t)L_*D_*DF_];

// ---------------- helpers ----------------------------------------------------
__device__ __forceinline__ uint32_t smem_u32(const void* p) {
    uint32_t a;
    asm("{ .reg .u64 t; cvta.to.shared.u64 t, %1; cvt.u32.u64 %0, t; }" : "=r"(a) : "l"(p));
    return a;
}
__device__ __forceinline__ float gelu_f(float x) {
    const float c = 0.7978845608028654f;
    return 0.5f * x * (1.0f + tanhf(c * (x + 0.044715f * x * x * x)));
}
__device__ __forceinline__ void split_h(float v, __half& hi, __half& lo) {
    hi = __float2half_rn(v);
    lo = __float2half_rn(v - __half2float(hi));
}
__device__ __forceinline__ uint32_t pack2h(float x, float y) {
    __half2 p; p.x = __float2half_rn(x); p.y = __float2half_rn(y);
    return *(uint32_t*)&p;
}
__device__ __forceinline__ void pack_split_h(float x, float y, uint32_t& hp, uint32_t& lp) {
    __half hx, lx, hy, ly;
    split_h(x, hx, lx); split_h(y, hy, ly);
    __half2 h2; h2.x = hx; h2.y = hy;
    __half2 l2; l2.x = lx; l2.y = ly;
    hp = *(uint32_t*)&h2; lp = *(uint32_t*)&l2;
}

#define CP16(dst, src) \
    asm volatile("cp.async.cg.shared.global [%0], [%1], 16;" :: "r"(dst), "l"(src))
#define CP_COMMIT() asm volatile("cp.async.commit_group;")
#define CP_WAIT(n)  asm volatile("cp.async.wait_group %0;" :: "n"(n))

#define LDSM_X4(r0, r1, r2, r3, a) \
    asm volatile("ldmatrix.sync.aligned.m8n8.x4.shared.b16 {%0,%1,%2,%3}, [%4];" \
                 : "=r"(r0), "=r"(r1), "=r"(r2), "=r"(r3) : "r"(a))
#define LDSM_X2(r0, r1, a) \
    asm volatile("ldmatrix.sync.aligned.m8n8.x2.shared.b16 {%0,%1}, [%2];" \
                 : "=r"(r0), "=r"(r1) : "r"(a))
#define LDSM_X2_T(r0, r1, a) \
    asm volatile("ldmatrix.sync.aligned.m8n8.x2.trans.shared.b16 {%0,%1}, [%2];" \
                 : "=r"(r0), "=r"(r1) : "r"(a))
#define MMA16816(d, a0, a1, a2, a3, b0, b1) \
    asm volatile("mma.sync.aligned.m16n8k16.row.col.f32.f16.f16.f32 " \
                 "{%0,%1,%2,%3},{%4,%5,%6,%7},{%8,%9},{%0,%1,%2,%3};" \
                 : "+f"((d)[0]), "+f"((d)[1]), "+f"((d)[2]), "+f"((d)[3]) \
                 : "r"(a0), "r"(a1), "r"(a2), "r"(a3), "r"(b0), "r"(b1))

// gemm smem tile geometry: 128 rows x 32 fp16, stride 80B; 3 matrices/stage
#define TSTRIDE 80
#define MATBYTES 10240
#define STAGEBYTES 30720
#define SMEM_GEMM (2*STAGEBYTES)

// flash smem: rows of 64 fp16 (128B) padded to 144B
#define FSTR 144
#define QOFF_H 0
#define QOFF_L 9216
#define KOFF   18432
#define VOFF   36864
#define SMEM_FLASH 55296

// ---------------- fused weight transpose + fp16 convert ----------------------
#define TILES_PER_LAYER 6912
__global__ void wsplit_all_kernel(const float* __restrict__ attn_w, const float* __restrict__ proj_w,
                                  const float* __restrict__ fc_w,   const float* __restrict__ fc2_w,
                                  __half* __restrict__ tah, __half* __restrict__ tph,
                                  __half* __restrict__ tfh, __half* __restrict__ t2h) {
    __shared__ float t[32][33];
    int bid = blockIdx.x;
    int l = bid / TILES_PER_LAYER;
    int r = bid % TILES_PER_LAYER;
    const float* W; __half* Oh; int K, N, tile;
    if (r < 1728)      { W = attn_w; Oh = tah; K = D_;  N = D3_; tile = r; }
    else if (r < 2304) { W = proj_w; Oh = tph; K = D_;  N = D_;  tile = r - 1728; }
    else if (r < 4608) { W = fc_w;   Oh = tfh; K = D_;  N = DF_; tile = r - 2304; }
    else               { W = fc2_w;  Oh = t2h; K = DF_; N = D_;  tile = r - 4608; }
    int nx = N >> 5;
    int n0 = (tile % nx) << 5, k0 = (tile / nx) << 5;
    const float* Wl = W + (size_t)l * K * N;
    __half* OhL = Oh + (size_t)l * K * N;
    int tx = threadIdx.x, ty = threadIdx.y;    // (32,8)
    for (int i = ty; i < 32; i += 8)
        t[i][tx] = Wl[(size_t)(k0 + i) * N + n0 + tx];
    __syncthreads();
    for (int i = ty; i < 32; i += 8)
        OhL[(size_t)(n0 + i) * K + k0 + tx] = __float2half_rn(t[tx][i]);
}

// ---------------- fused embedding + layer-0 ln1 -------------------------------
__global__ void embed_ln_kernel(const int* __restrict__ ids, const int* __restrict__ rfi,
                                const float* __restrict__ wte, const float* __restrict__ wte_rf,
                                const float* __restrict__ wpe,
                                const float* __restrict__ g, const float* __restrict__ b,
                                float* __restrict__ h,
                                __half* __restrict__ yh, __half* __restrict__ yl) {
    int row = blockIdx.x;
    int s = row & (S_ - 1);
    int t = threadIdx.x;
    const float* e1 = wte    + (size_t)ids[row] * D_;
    const float* e2 = wte_rf + (size_t)rfi[row] * D_;
    const float* e3 = wpe    + (size_t)s * D_;
    float v0 = e1[t]       + e2[t]       + e3[t];
    float v1 = e1[t + 256] + e2[t + 256] + e3[t + 256];
    float v2 = e1[t + 512] + e2[t + 512] + e3[t + 512];
    float* hr = h + (size_t)row * D_;
    hr[t] = v0; hr[t + 256] = v1; hr[t + 512] = v2;
    __shared__ float red[256];
    red[t] = v0 + v1 + v2;
    __syncthreads();
    for (int o = 128; o > 0; o >>= 1) { if (t < o) red[t] += red[t + o]; __syncthreads(); }
    float mu = red[0] * (1.0f / D_);
    __syncthreads();
    float d0 = v0 - mu, d1 = v1 - mu, d2 = v2 - mu;
    red[t] = d0*d0 + d1*d1 + d2*d2;
    __syncthreads();
    for (int o = 128; o > 0; o >>= 1) { if (t < o) red[t] += red[t + o]; __syncthreads(); }
    float inv = rsqrtf(red[0] * (1.0f / D_) + 1e-5f);
    float r0 = d0 * inv * g[t]       + b[t];
    float r1 = d1 * inv * g[t + 256] + b[t + 256];
    float r2 = d2 * inv * g[t + 512] + b[t + 512];
    __half hi, lo;
    size_t base = (size_t)row * D_;
    split_h(r0, hi, lo); yh[base + t]       = hi; yl[base + t]       = lo;
    split_h(r1, hi, lo); yh[base + t + 256] = hi; yl[base + t + 256] = lo;
    split_h(r2, hi, lo); yh[base + t + 512] = hi; yl[base + t + 512] = lo;
}

// ---------------- layernorm --------------------------------------------------
template<bool HF>
__global__ void ln_kernel(const float* __restrict__ x, const float* __restrict__ g,
                          const float* __restrict__ b, float* __restrict__ y,
                          __half* __restrict__ yh, __half* __restrict__ yl) {
    int row = blockIdx.x;
    int t = threadIdx.x;
    const float* xr = x + (size_t)row * D_;
    float v0 = xr[t], v1 = xr[t + 256], v2 = xr[t + 512];
    __shared__ float red[256];
    red[t] = v0 + v1 + v2;
    __syncthreads();
    for (int o = 128; o > 0; o >>= 1) { if (t < o) red[t] += red[t + o]; __syncthreads(); }
    float mu = red[0] * (1.0f / D_);
    __syncthreads();
    float d0 = v0 - mu, d1 = v1 - mu, d2 = v2 - mu;
    red[t] = d0*d0 + d1*d1 + d2*d2;
    __syncthreads();
    for (int o = 128; o > 0; o >>= 1) { if (t < o) red[t] += red[t + o]; __syncthreads(); }
    float inv = rsqrtf(red[0] * (1.0f / D_) + 1e-5f);
    float r0 = d0 * inv * g[t]       + b[t];
    float r1 = d1 * inv * g[t + 256] + b[t + 256];
    float r2 = d2 * inv * g[t + 512] + b[t + 512];
    if (HF) {
        __half hi, lo;
        size_t base = (size_t)row * D_;
        split_h(r0, hi, lo); yh[base + t]       = hi; yl[base + t]       = lo;
        split_h(r1, hi, lo); yh[base + t + 256] = hi; yl[base + t + 256] = lo;
        split_h(r2, hi, lo); yh[base + t + 512] = hi; yl[base + t + 512] = lo;
    } else {
        float* yr = y + (size_t)row * D_;
        yr[t] = r0; yr[t + 256] = r1; yr[t + 512] = r2;
    }
}

// ---------------- mma.sync GEMM (fp16 2-pass) ---------------------------------
// acc = Ah*Bh + Al*Bh (fp32 accumulate); A exact in fp16 hi/lo, B fp16 rounded.
// EPI 0: Cf = acc+bias.  EPI 1: Cf = acc+bias+resid.
// EPI 2: Ch/Cl = split(gelu(acc+bias)).  EPI 3: head-major Q(hi/lo) K(hi) V(hi).
template<int EPI>
__global__ void __launch_bounds__(256, 2)
gemm_mma(const __half* __restrict__ Ah, const __half* __restrict__ Al,
         const __half* __restrict__ Bh,
         const float* __restrict__ bias, const float* __restrict__ resid,
         float* __restrict__ Cf, __half* __restrict__ Ch, __half* __restrict__ Cl,
         __half* __restrict__ Qh_, __half* __restrict__ Ql_,
         __half* __restrict__ Kh_, __half* __restrict__ Vh_,
         int M, int N, int K) {
    extern __shared__ char smem[];
    uint32_t sbase = smem_u32(smem);
    int tid = threadIdx.x;
    int wid = tid >> 5, lane = tid & 31;
    int wm = wid >> 2, wn = wid & 3;
    int m0 = blockIdx.y << 7, n0 = blockIdx.x << 7;
    int ldb = K * 2;

    const char* srcs[3];
    srcs[0] = (const char*)(Ah + (size_t)m0 * K);
    srcs[1] = (const char*)(Al + (size_t)m0 * K);
    srcs[2] = (const char*)(Bh + (size_t)n0 * K);

    float acc[4][4][4] = {};
    int nk = K >> 5;

#define PREFETCH(c, s)                                                        \
    {                                                                         \
        size_t ko = (size_t)(c) << 6;                                         \
        uint32_t stb = sbase + (s) * STAGEBYTES;                              \
        _Pragma("unroll")                                                     \
        for (int j = 0; j < 6; j++) {                                         \
            int q = tid + j * 256;                                            \
            int mat = q >> 9, w = q & 511, row = w >> 2, cc = w & 3;          \
            uint32_t dst = stb + mat * MATBYTES + row * TSTRIDE + cc * 16;    \
            const char* sp = srcs[mat] + (size_t)row * ldb + ko + cc * 16;    \
            CP16(dst, sp);                                                    \
        }                                                                     \
        CP_COMMIT();                                                          \
    }

    PREFETCH(0, 0);

    int aRow = wm * 64 + (lane & 7) + ((lane >> 3) & 1) * 8;
    uint32_t aKoff = ((lane >> 4) & 1) * 16;
    int lb = lane & 15;
    int bRow = wn * 32 + (lb & 7);
    uint32_t bKoff = ((lb >> 3) & 1) * 16;

    for (int c = 0; c < nk; c++) {
        int s = c & 1;
        if (c + 1 < nk) PREFETCH(c + 1, s ^ 1);
        if (c + 1 < nk) { CP_WAIT(1); } else { CP_WAIT(0); }
        __syncthreads();

        uint32_t stb = sbase + s * STAGEBYTES;
        #pragma unroll
        for (int kk = 0; kk < 2; kk++) {
            uint32_t bh[4][2];
            #pragma unroll
            for (int nj = 0; nj < 4; nj++) {
                uint32_t addr = stb + 2 * MATBYTES + (bRow + nj * 8) * TSTRIDE + kk * 32 + bKoff;
                LDSM_X2(bh[nj][0], bh[nj][1], addr);
            }
            uint32_t af[4][4];
            #pragma unroll
            for (int mi = 0; mi < 4; mi++) {
                uint32_t addr = stb + (aRow + mi * 16) * TSTRIDE + kk * 32 + aKoff;
                LDSM_X4(af[mi][0], af[mi][1], af[mi][2], af[mi][3], addr);
            }
            #pragma unroll
            for (int mi = 0; mi < 4; mi++)
                #pragma unroll
                for (int nj = 0; nj < 4; nj++)
                    MMA16816(acc[mi][nj], af[mi][0], af[mi][1], af[mi][2], af[mi][3],
                             bh[nj][0], bh[nj][1]);
            #pragma unroll
            for (int mi = 0; mi < 4; mi++) {
                uint32_t addr = stb + MATBYTES + (aRow + mi * 16) * TSTRIDE + kk * 32 + aKoff;
                LDSM_X4(af[mi][0], af[mi][1], af[mi][2], af[mi][3], addr);
            }
            #pragma unroll
            for (int mi = 0; mi < 4; mi++)
                #pragma unroll
                for (int nj = 0; nj < 4; nj++)
                    MMA16816(acc[mi][nj], af[mi][0], af[mi][1], af[mi][2], af[mi][3],
                             bh[nj][0], bh[nj][1]);
        }
        __syncthreads();
    }

    int rbase = m0 + wm * 64 + (lane >> 2);
    int cbase = n0 + wn * 32 + (lane & 3) * 2;
    #pragma unroll
    for (int mi = 0; mi < 4; mi++) {
        #pragma unroll
        for (int nj = 0; nj < 4; nj++) {
            int r = rbase + mi * 16;
            int col = cbase + nj * 8;
            float b0 = bias[col], b1 = bias[col + 1];
            float v00 = acc[mi][nj][0] + b0, v01 = acc[mi][nj][1] + b1;
            float v10 = acc[mi][nj][2] + b0, v11 = acc[mi][nj][3] + b1;
            size_t i0 = (size_t)r * N + col;
            size_t i1 = (size_t)(r + 8) * N + col;
            if (EPI == 0) {
                *(float2*)&Cf[i0] = make_float2(v00, v01);
                *(float2*)&Cf[i1] = make_float2(v10, v11);
            } else if (EPI == 1) {
                float2 r0 = *(const float2*)&resid[i0];
                float2 r1 = *(const float2*)&resid[i1];
                *(float2*)&Cf[i0] = make_float2(v00 + r0.x, v01 + r0.y);
                *(float2*)&Cf[i1] = make_float2(v10 + r1.x, v11 + r1.y);
            } else if (EPI == 2) {
                v00 = gelu_f(v00); v01 = gelu_f(v01);
                v10 = gelu_f(v10); v11 = gelu_f(v11);
                uint32_t hp, lp;
                pack_split_h(v00, v01, hp, lp);
                *(uint32_t*)&Ch[i0] = hp; *(uint32_t*)&Cl[i0] = lp;
                pack_split_h(v10, v11, hp, lp);
                *(uint32_t*)&Ch[i1] = hp; *(uint32_t*)&Cl[i1] = lp;
            } else {
                int which = col / D_;
                int hh = (col % D_) / DH_;
                int dd = col % DH_;
                int bi = r >> 10, si = r & 1023;
                size_t j0 = (((size_t)(bi * H_ + hh)) * S_ + si) * DH_ + dd;
                size_t j1 = j0 + 8 * DH_;
                if (which == 0) {
                    uint32_t hp, lp;
                    pack_split_h(v00, v01, hp, lp);
                    *(uint32_t*)&Qh_[j0] = hp; *(uint32_t*)&Ql_[j0] = lp;
                    pack_split_h(v10, v11, hp, lp);
                    *(uint32_t*)&Qh_[j1] = hp; *(uint32_t*)&Ql_[j1] = lp;
                } else {
                    __half* d_ = which == 1 ? Kh_ : Vh_;
                    *(uint32_t*)&d_[j0] = pack2h(v00, v01);
                    *(uint32_t*)&d_[j1] = pack2h(v10, v11);
                }
            }
        }
    }
#undef PREFETCH
}

// ---------------- fused flash attention (fp16 2-pass) -------------------------
// grid (S/64, B*H), 128 threads. q-tiles processed high-causal-length-first.
__global__ void __launch_bounds__(128)
flash_kernel(const __half* __restrict__ qh, const __half* __restrict__ ql,
             const __half* __restrict__ kh, const __half* __restrict__ vh,
             __half* __restrict__ oh, __half* __restrict__ ol) {
    extern __shared__ char fsm[];
    uint32_t sb = smem_u32(fsm);
    int bh = blockIdx.y;
    int q0 = (gridDim.x - 1 - blockIdx.x) << 6;   // long CTAs first
    int tid = threadIdx.x, wid = tid >> 5, lane = tid & 31;

    {   // Q tile load (64 rows x 128B), hi+lo
        const char* srcH = (const char*)(qh + ((size_t)bh * S_ + q0) * DH_);
        const char* srcL = (const char*)(ql + ((size_t)bh * S_ + q0) * DH_);
        #pragma unroll
        for (int i = tid; i < 512; i += 128) {
            int r = i >> 3, c = (i & 7) << 4;
            CP16(sb + QOFF_H + r * FSTR + c, srcH + r * 128 + c);
            CP16(sb + QOFF_L + r * FSTR + c, srcL + r * 128 + c);
        }
        CP_COMMIT();
    }

    float m0 = -1e30f, m1 = -1e30f, l0 = 0.f, l1 = 0.f;
    float oacc[8][4];
    #pragma unroll
    for (int d = 0; d < 8; d++)
        oacc[d][0] = oacc[d][1] = oacc[d][2] = oacc[d][3] = 0.f;

    int rA = q0 + wid * 16 + (lane >> 2);
    int nj = (q0 >> 7) + 1;

    uint32_t aAddrBase = sb + (wid * 16 + (lane & 15)) * FSTR + (((lane >> 4) & 1) << 4);
    uint32_t bRowOff = (uint32_t)((lane & 7) * FSTR) + (((lane >> 3) & 1) << 4);

    for (int j = 0; j < nj; j++) {
        __syncthreads();
        {   // K/V tile load (128 rows x 128B), hi only
            const char* kH = (const char*)(kh + ((size_t)bh * S_ + (j << 7)) * DH_);
            const char* vH = (const char*)(vh + ((size_t)bh * S_ + (j << 7)) * DH_);
            #pragma unroll
            for (int i = tid; i < 1024; i += 128) {
                int r = i >> 3, c = (i & 7) << 4;
                uint32_t so = r * FSTR + c;
                size_t go = (size_t)r * 128 + c;
                CP16(sb + KOFF + so, kH + go);
                CP16(sb + VOFF + so, vH + go);
            }
            CP_COMMIT();
            CP_WAIT(0);
        }
        __syncthreads();

        float sf[16][4];
        #pragma unroll
        for (int nt = 0; nt < 16; nt++)
            sf[nt][0] = sf[nt][1] = sf[nt][2] = sf[nt][3] = 0.f;

        #pragma unroll
        for (int kc = 0; kc < 4; kc++) {
            uint32_t qa = aAddrBase + kc * 32;
            uint32_t q_h0,q_h1,q_h2,q_h3, q_l0,q_l1,q_l2,q_l3;
            LDSM_X4(q_h0,q_h1,q_h2,q_h3, qa + QOFF_H);
            LDSM_X4(q_l0,q_l1,q_l2,q_l3, qa + QOFF_L);
            #pragma unroll
            for (int nt = 0; nt < 16; nt++) {
                uint32_t ka = sb + KOFF + nt * 8 * FSTR + bRowOff + kc * 32;
                uint32_t k_h0,k_h1;
                LDSM_X2(k_h0,k_h1, ka);
                MMA16816(sf[nt], q_h0,q_h1,q_h2,q_h3, k_h0,k_h1);
                MMA16816(sf[nt], q_l0,q_l1,q_l2,q_l3, k_h0,k_h1);
            }
        }

        int cb = (j << 7) + (lane & 3) * 2;
        float mx0 = -1e30f, mx1 = -1e30f;
        #pragma unroll
        for (int nt = 0; nt < 16; nt++) {
            int c0 = cb + nt * 8;
            sf[nt][0] = (c0     <= rA)     ? sf[nt][0] * 0.125f : -1e30f;
            sf[nt][1] = (c0 + 1 <= rA)     ? sf[nt][1] * 0.125f : -1e30f;
            sf[nt][2] = (c0     <= rA + 8) ? sf[nt][2] * 0.125f : -1e30f;
            sf[nt][3] = (c0 + 1 <= rA + 8) ? sf[nt][3] * 0.125f : -1e30f;
            mx0 = fmaxf(mx0, fmaxf(sf[nt][0], sf[nt][1]));
            mx1 = fmaxf(mx1, fmaxf(sf[nt][2], sf[nt][3]));
        }
        mx0 = fmaxf(mx0, __shfl_xor_sync(0xffffffffu, mx0, 1));
        mx0 = fmaxf(mx0, __shfl_xor_sync(0xffffffffu, mx0, 2));
        mx1 = fmaxf(mx1, __shfl_xor_sync(0xffffffffu, mx1, 1));
        mx1 = fmaxf(mx1, __shfl_xor_sync(0xffffffffu, mx1, 2));
        float mn0 = fmaxf(m0, mx0), mn1 = fmaxf(m1, mx1);
        float sc0 = expf(m0 - mn0), sc1 = expf(m1 - mn1);
        m0 = mn0; m1 = mn1;
        l0 *= sc0; l1 *= sc1;
        #pragma unroll
        for (int d = 0; d < 8; d++) {
            oacc[d][0] *= sc0; oacc[d][1] *= sc0;
            oacc[d][2] *= sc1; oacc[d][3] *= sc1;
        }
        float s0 = 0.f, s1 = 0.f;
        uint32_t ph[16][2], pl[16][2];
        #pragma unroll
        for (int nt = 0; nt < 16; nt++) {
            float p0 = expf(sf[nt][0] - m0), p1 = expf(sf[nt][1] - m0);
            float p2 = expf(sf[nt][2] - m1), p3 = expf(sf[nt][3] - m1);
            s0 += p0 + p1; s1 += p2 + p3;
            pack_split_h(p0, p1, ph[nt][0], pl[nt][0]);
            pack_split_h(p2, p3, ph[nt][1], pl[nt][1]);
        }
        s0 += __shfl_xor_sync(0xffffffffu, s0, 1);
        s0 += __shfl_xor_sync(0xffffffffu, s0, 2);
        s1 += __shfl_xor_sync(0xffffffffu, s1, 1);
        s1 += __shfl_xor_sync(0xffffffffu, s1, 2);
        l0 += s0; l1 += s1;

        #pragma unroll
        for (int kc = 0; kc < 8; kc++) {
            uint32_t va = sb + VOFF + (kc * 16 + (lane & 15)) * FSTR;
            #pragma unroll
            for (int dt = 0; dt < 8; dt++) {
                uint32_t v_h0,v_h1;
                LDSM_X2_T(v_h0,v_h1, va + dt * 16);
                MMA16816(oacc[dt], ph[2*kc][0], ph[2*kc][1], ph[2*kc+1][0], ph[2*kc+1][1], v_h0, v_h1);
                MMA16816(oacc[dt], pl[2*kc][0], pl[2*kc][1], pl[2*kc+1][0], pl[2*kc+1][1], v_h0, v_h1);
            }
        }
    }

    float inv0 = 1.f / l0, inv1 = 1.f / l1;
    int bb = bh / H_, hH = bh % H_;
    size_t baseA = ((size_t)bb * S_ + rA) * D_ + hH * DH_;
    size_t baseB = baseA + 8 * D_;
    #pragma unroll
    for (int dt = 0; dt < 8; dt++) {
        int c = dt * 8 + (lane & 3) * 2;
        uint32_t hp, lp;
        pack_split_h(oacc[dt][0] * inv0, oacc[dt][1] * inv0, hp, lp);
        *(uint32_t*)&oh[baseA + c] = hp;
        *(uint32_t*)&ol[baseA + c] = lp;
        pack_split_h(oacc[dt][2] * inv1, oacc[dt][3] * inv1, hp, lp);
        *(uint32_t*)&oh[baseB + c] = hp;
        *(uint32_t*)&ol[baseB + c] = lp;
    }
}

// ---------------- host orchestration -----------------------------------------
extern "C" void kernel_launch(void* const* d_in, const int* in_sizes, int n_in,
                              void* d_out, int out_size) {
    const int*   ids    = (const int*)d_in[0];
    const int*   rfi    = (const int*)d_in[1];
    const float* wte    = (const float*)d_in[2];
    const float* wte_rf = (const float*)d_in[3];
    const float* wpe    = (const float*)d_in[4];
    const float* ln1_g  = (const float*)d_in[5];
    const float* ln1_b  = (const float*)d_in[6];
    const float* attn_w = (const float*)d_in[7];
    const float* attn_b = (const float*)d_in[8];
    const float* proj_w = (const float*)d_in[9];
    const float* proj_b = (const float*)d_in[10];
    const float* ln2_g  = (const float*)d_in[11];
    const float* ln2_b  = (const float*)d_in[12];
    const float* fc_w   = (const float*)d_in[13];
    const float* fc_b   = (const float*)d_in[14];
    const float* fc2_w  = (const float*)d_in[15];
    const float* fc2_b  = (const float*)d_in[16];
    const float* lnf_g  = (const float*)d_in[17];
    const float* lnf_b  = (const float*)d_in[18];
    float* out = (float*)d_out;

    float *h;
    __half *ah, *al, *mh, *ml, *oh, *ol;
    __half *qh, *ql, *kh, *vh;
    __half *tah, *tph, *tfh, *t2h;
    cudaGetSymbolAddress((void**)&h,   g_h);
    cudaGetSymbolAddress((void**)&ah,  g_ah);  cudaGetSymbolAddress((void**)&al,  g_al);
    cudaGetSymbolAddress((void**)&mh,  g_mh);  cudaGetSymbolAddress((void**)&ml,  g_ml);
    cudaGetSymbolAddress((void**)&oh,  g_oh);  cudaGetSymbolAddress((void**)&ol,  g_ol);
    cudaGetSymbolAddress((void**)&qh,  g_qh);  cudaGetSymbolAddress((void**)&ql,  g_ql);
    cudaGetSymbolAddress((void**)&kh,  g_kh);  cudaGetSymbolAddress((void**)&vh,  g_vh);
    cudaGetSymbolAddress((void**)&tah, t_attn_h);
    cudaGetSymbolAddress((void**)&tph, t_proj_h);
    cudaGetSymbolAddress((void**)&tfh, t_fc_h);
    cudaGetSymbolAddress((void**)&t2h, t_fc2_h);

    cudaFuncSetAttribute(gemm_mma<1>, cudaFuncAttributeMaxDynamicSharedMemorySize, SMEM_GEMM);
    cudaFuncSetAttribute(gemm_mma<2>, cudaFuncAttributeMaxDynamicSharedMemorySize, SMEM_GEMM);
    cudaFuncSetAttribute(gemm_mma<3>, cudaFuncAttributeMaxDynamicSharedMemorySize, SMEM_GEMM);
    cudaFuncSetAttribute(flash_kernel, cudaFuncAttributeMaxDynamicSharedMemorySize, SMEM_FLASH);

    wsplit_all_kernel<<<TILES_PER_LAYER * L_, dim3(32, 8)>>>(
        attn_w, proj_w, fc_w, fc2_w, tah, tph, tfh, t2h);
    embed_ln_kernel<<<NT_, 256>>>(ids, rfi, wte, wte_rf, wpe, ln1_g, ln1_b, h, ah, al);

    for (int l = 0; l < L_; l++) {
        if (l > 0)
            ln_kernel<true><<<NT_, 256>>>(h, ln1_g + l * D_, ln1_b + l * D_, nullptr, ah, al);
        gemm_mma<3><<<dim3(D3_/128, NT_/128), 256, SMEM_GEMM>>>(
            ah, al, tah + (size_t)l * D3_ * D_,
            attn_b + l * D3_, nullptr, nullptr, nullptr, nullptr,
            qh, ql, kh, vh, NT_, D3_, D_);
        flash_kernel<<<dim3(S_/64, B_*H_), 128, SMEM_FLASH>>>(qh, ql, kh, vh, oh, ol);
        gemm_mma<1><<<dim3(D_/128, NT_/128), 256, SMEM_GEMM>>>(
            oh, ol, tph + (size_t)l * D_ * D_,
            proj_b + l * D_, h, h, nullptr, nullptr,
            nullptr, nullptr, nullptr, nullptr, NT_, D_, D_);
        ln_kernel<true><<<NT_, 256>>>(h, ln2_g + l * D_, ln2_b + l * D_, nullptr, ah, al);
        gemm_mma<2><<<dim3(DF_/128, NT_/128), 256, SMEM_GEMM>>>(
            ah, al, tfh + (size_t)l * DF_ * D_,
            fc_b + l * DF_, nullptr, nullptr, mh, ml,
            nullptr, nullptr, nullptr, nullptr, NT_, DF_, D_);
        gemm_mma<1><<<dim3(D_/128, NT_/128), 256, SMEM_GEMM>>>(
            mh, ml, t2h + (size_t)l * D_ * DF_,
            fc2_b + l * D_, h, h, nullptr, nullptr,
            nullptr, nullptr, nullptr, nullptr, NT_, D_, DF_);
    }
    ln_kernel<false><<<NT_, 256>>>(h, lnf_g, lnf_b, out, nullptr, nullptr);
}

// round 8
// speedup vs baseline: 4.0265x; 1.0511x over previous
#include <cuda_runtime.h>
#include <cuda_fp16.h>
#include <math.h>
#include <stdint.h>

#define B_  4
#define S_  1024
#define D_  768
#define H_  12
#define L_  6
#define DF_ 3072
#define DH_ 64
#define NT_ (B_*S_)        // 4096
#define D3_ (3*D_)         // 2304

// ---------------- scratch (static device globals) ----------------------------
static __device__ float g_h[NT_*D_];
static __device__ __half g_ah[NT_*D_],  g_al[NT_*D_];
static __device__ __half g_mh[NT_*DF_], g_ml[NT_*DF_];
static __device__ __half g_oh[NT_*D_],  g_ol[NT_*D_];
static __device__ __half g_qh[NT_*D_],  g_ql[NT_*D_];
static __device__ __half g_kh[NT_*D_];
static __device__ __half g_vh[NT_*D_];
static __device__ __half t_attn_h[(size_t)L_*D3_*D_];
static __device__ __half t_proj_h[(size_t)L_*D_*D_];
static __device__ __half t_fc_h[(size_t)L_*DF_*D_];
static __device__ __half t_fc2_h[(size_t)L_*D_*DF_];

// ---------------- helpers ----------------------------------------------------
__device__ __forceinline__ uint32_t smem_u32(const void* p) {
    uint32_t a;
    asm("{ .reg .u64 t; cvta.to.shared.u64 t, %1; cvt.u32.u64 %0, t; }" : "=r"(a) : "l"(p));
    return a;
}
__device__ __forceinline__ float gelu_f(float x) {
    const float c = 0.7978845608028654f;
    return 0.5f * x * (1.0f + tanhf(c * (x + 0.044715f * x * x * x)));
}
__device__ __forceinline__ void split_h(float v, __half& hi, __half& lo) {
    hi = __float2half_rn(v);
    lo = __float2half_rn(v - __half2float(hi));
}
__device__ __forceinline__ uint32_t pack2h(float x, float y) {
    __half2 p; p.x = __float2half_rn(x); p.y = __float2half_rn(y);
    return *(uint32_t*)&p;
}
__device__ __forceinline__ void pack_split_h(float x, float y, uint32_t& hp, uint32_t& lp) {
    __half hx, lx, hy, ly;
    split_h(x, hx, lx); split_h(y, hy, ly);
    __half2 h2; h2.x = hx; h2.y = hy;
    __half2 l2; l2.x = lx; l2.y = ly;
    hp = *(uint32_t*)&h2; lp = *(uint32_t*)&l2;
}

#define CP16(dst, src) \
    asm volatile("cp.async.cg.shared.global [%0], [%1], 16;" :: "r"(dst), "l"(src))
#define CP_COMMIT() asm volatile("cp.async.commit_group;")
#define CP_WAIT(n)  asm volatile("cp.async.wait_group %0;" :: "n"(n))

#define LDSM_X4(r0, r1, r2, r3, a) \
    asm volatile("ldmatrix.sync.aligned.m8n8.x4.shared.b16 {%0,%1,%2,%3}, [%4];" \
                 : "=r"(r0), "=r"(r1), "=r"(r2), "=r"(r3) : "r"(a))
#define LDSM_X2(r0, r1, a) \
    asm volatile("ldmatrix.sync.aligned.m8n8.x2.shared.b16 {%0,%1}, [%2];" \
                 : "=r"(r0), "=r"(r1) : "r"(a))
#define LDSM_X2_T(r0, r1, a) \
    asm volatile("ldmatrix.sync.aligned.m8n8.x2.trans.shared.b16 {%0,%1}, [%2];" \
                 : "=r"(r0), "=r"(r1) : "r"(a))
#define MMA16816(d, a0, a1, a2, a3, b0, b1) \
    asm volatile("mma.sync.aligned.m16n8k16.row.col.f32.f16.f16.f32 " \
                 "{%0,%1,%2,%3},{%4,%5,%6,%7},{%8,%9},{%0,%1,%2,%3};" \
                 : "+f"((d)[0]), "+f"((d)[1]), "+f"((d)[2]), "+f"((d)[3]) \
                 : "r"(a0), "r"(a1), "r"(a2), "r"(a3), "r"(b0), "r"(b1))

// gemm smem: 128 rows x 64 fp16 (128B) padded to 144B; 3 matrices per stage
#define TSTRIDE 144
#define MATBYTES 18432
#define STAGEBYTES 55296
#define SMEM_GEMM (2*STAGEBYTES)

// flash smem: rows of 64 fp16 (128B) padded to 144B; Q is 128 rows now
#define FSTR 144
#define QOFF_H 0
#define QOFF_L 18432
#define KOFF   36864
#define VOFF   55296
#define SMEM_FLASH 73728

// ---------------- fused weight transpose + fp16 convert ----------------------
#define TILES_PER_LAYER 6912
__global__ void wsplit_all_kernel(const float* __restrict__ attn_w, const float* __restrict__ proj_w,
                                  const float* __restrict__ fc_w,   const float* __restrict__ fc2_w,
                                  __half* __restrict__ tah, __half* __restrict__ tph,
                                  __half* __restrict__ tfh, __half* __restrict__ t2h) {
    __shared__ float t[32][33];
    int bid = blockIdx.x;
    int l = bid / TILES_PER_LAYER;
    int r = bid % TILES_PER_LAYER;
    const float* W; __half* Oh; int K, N, tile;
    if (r < 1728)      { W = attn_w; Oh = tah; K = D_;  N = D3_; tile = r; }
    else if (r < 2304) { W = proj_w; Oh = tph; K = D_;  N = D_;  tile = r - 1728; }
    else if (r < 4608) { W = fc_w;   Oh = tfh; K = D_;  N = DF_; tile = r - 2304; }
    else               { W = fc2_w;  Oh = t2h; K = DF_; N = D_;  tile = r - 4608; }
    int nx = N >> 5;
    int n0 = (tile % nx) << 5, k0 = (tile / nx) << 5;
    const float* Wl = W + (size_t)l * K * N;
    __half* OhL = Oh + (size_t)l * K * N;
    int tx = threadIdx.x, ty = threadIdx.y;    // (32,8)
    for (int i = ty; i < 32; i += 8)
        t[i][tx] = Wl[(size_t)(k0 + i) * N + n0 + tx];
    __syncthreads();
    for (int i = ty; i < 32; i += 8)
        OhL[(size_t)(n0 + i) * K + k0 + tx] = __float2half_rn(t[tx][i]);
}

// ---------------- fused embedding + layer-0 ln1 -------------------------------
__global__ void embed_ln_kernel(const int* __restrict__ ids, const int* __restrict__ rfi,
                                const float* __restrict__ wte, const float* __restrict__ wte_rf,
                                const float* __restrict__ wpe,
                                const float* __restrict__ g, const float* __restrict__ b,
                                float* __restrict__ h,
                                __half* __restrict__ yh, __half* __restrict__ yl) {
    int row = blockIdx.x;
    int s = row & (S_ - 1);
    int t = threadIdx.x;
    const float* e1 = wte    + (size_t)ids[row] * D_;
    const float* e2 = wte_rf + (size_t)rfi[row] * D_;
    const float* e3 = wpe    + (size_t)s * D_;
    float v0 = e1[t]       + e2[t]       + e3[t];
    float v1 = e1[t + 256] + e2[t + 256] + e3[t + 256];
    float v2 = e1[t + 512] + e2[t + 512] + e3[t + 512];
    float* hr = h + (size_t)row * D_;
    hr[t] = v0; hr[t + 256] = v1; hr[t + 512] = v2;
    __shared__ float red[256];
    red[t] = v0 + v1 + v2;
    __syncthreads();
    for (int o = 128; o > 0; o >>= 1) { if (t < o) red[t] += red[t + o]; __syncthreads(); }
    float mu = red[0] * (1.0f / D_);
    __syncthreads();
    float d0 = v0 - mu, d1 = v1 - mu, d2 = v2 - mu;
    red[t] = d0*d0 + d1*d1 + d2*d2;
    __syncthreads();
    for (int o = 128; o > 0; o >>= 1) { if (t < o) red[t] += red[t + o]; __syncthreads(); }
    float inv = rsqrtf(red[0] * (1.0f / D_) + 1e-5f);
    float r0 = d0 * inv * g[t]       + b[t];
    float r1 = d1 * inv * g[t + 256] + b[t + 256];
    float r2 = d2 * inv * g[t + 512] + b[t + 512];
    __half hi, lo;
    size_t base = (size_t)row * D_;
    split_h(r0, hi, lo); yh[base + t]       = hi; yl[base + t]       = lo;
    split_h(r1, hi, lo); yh[base + t + 256] = hi; yl[base + t + 256] = lo;
    split_h(r2, hi, lo); yh[base + t + 512] = hi; yl[base + t + 512] = lo;
}

// ---------------- layernorm --------------------------------------------------
template<bool HF>
__global__ void ln_kernel(const float* __restrict__ x, const float* __restrict__ g,
                          const float* __restrict__ b, float* __restrict__ y,
                          __half* __restrict__ yh, __half* __restrict__ yl) {
    int row = blockIdx.x;
    int t = threadIdx.x;
    const float* xr = x + (size_t)row * D_;
    float v0 = xr[t], v1 = xr[t + 256], v2 = xr[t + 512];
    __shared__ float red[256];
    red[t] = v0 + v1 + v2;
    __syncthreads();
    for (int o = 128; o > 0; o >>= 1) { if (t < o) red[t] += red[t + o]; __syncthreads(); }
    float mu = red[0] * (1.0f / D_);
    __syncthreads();
    float d0 = v0 - mu, d1 = v1 - mu, d2 = v2 - mu;
    red[t] = d0*d0 + d1*d1 + d2*d2;
    __syncthreads();
    for (int o = 128; o > 0; o >>= 1) { if (t < o) red[t] += red[t + o]; __syncthreads(); }
    float inv = rsqrtf(red[0] * (1.0f / D_) + 1e-5f);
    float r0 = d0 * inv * g[t]       + b[t];
    float r1 = d1 * inv * g[t + 256] + b[t + 256];
    float r2 = d2 * inv * g[t + 512] + b[t + 512];
    if (HF) {
        __half hi, lo;
        size_t base = (size_t)row * D_;
        split_h(r0, hi, lo); yh[base + t]       = hi; yl[base + t]       = lo;
        split_h(r1, hi, lo); yh[base + t + 256] = hi; yl[base + t + 256] = lo;
        split_h(r2, hi, lo); yh[base + t + 512] = hi; yl[base + t + 512] = lo;
    } else {
        float* yr = y + (size_t)row * D_;
        yr[t] = r0; yr[t + 256] = r1; yr[t + 512] = r2;
    }
}

// ---------------- mma.sync GEMM (fp16 2-pass, K-chunk 64) ---------------------
// acc = Ah*Bh + Al*Bh (fp32 accumulate)
template<int EPI>
__global__ void __launch_bounds__(256, 2)
gemm_mma(const __half* __restrict__ Ah, const __half* __restrict__ Al,
         const __half* __restrict__ Bh,
         const float* __restrict__ bias, const float* __restrict__ resid,
         float* __restrict__ Cf, __half* __restrict__ Ch, __half* __restrict__ Cl,
         __half* __restrict__ Qh_, __half* __restrict__ Ql_,
         __half* __restrict__ Kh_, __half* __restrict__ Vh_,
         int M, int N, int K) {
    extern __shared__ char smem[];
    uint32_t sbase = smem_u32(smem);
    int tid = threadIdx.x;
    int wid = tid >> 5, lane = tid & 31;
    int wm = wid >> 2, wn = wid & 3;
    int m0 = blockIdx.y << 7, n0 = blockIdx.x << 7;
    int ldb = K * 2;

    const char* srcs[3];
    srcs[0] = (const char*)(Ah + (size_t)m0 * K);
    srcs[1] = (const char*)(Al + (size_t)m0 * K);
    srcs[2] = (const char*)(Bh + (size_t)n0 * K);

    float acc[4][4][4] = {};
    int nk = K >> 6;        // 64-wide K chunks

#define PREFETCH(c, s)                                                        \
    {                                                                         \
        size_t ko = (size_t)(c) << 7; /* c*64 elems * 2B */                   \
        uint32_t stb = sbase + (s) * STAGEBYTES;                              \
        _Pragma("unroll")                                                     \
        for (int j = 0; j < 12; j++) {                                        \
            int q = tid + j * 256;                                            \
            int mat = q >> 10, w = q & 1023, row = w >> 3, cc = w & 7;        \
            uint32_t dst = stb + mat * MATBYTES + row * TSTRIDE + cc * 16;    \
            const char* sp = srcs[mat] + (size_t)row * ldb + ko + cc * 16;    \
            CP16(dst, sp);                                                    \
        }                                                                     \
        CP_COMMIT();                                                          \
    }

    PREFETCH(0, 0);

    int aRow = wm * 64 + (lane & 7) + ((lane >> 3) & 1) * 8;
    uint32_t aKoff = ((lane >> 4) & 1) * 16;
    int lb = lane & 15;
    int bRow = wn * 32 + (lb & 7);
    uint32_t bKoff = ((lb >> 3) & 1) * 16;

    for (int c = 0; c < nk; c++) {
        int s = c & 1;
        if (c + 1 < nk) PREFETCH(c + 1, s ^ 1);
        if (c + 1 < nk) { CP_WAIT(1); } else { CP_WAIT(0); }
        __syncthreads();

        uint32_t stb = sbase + s * STAGEBYTES;
        #pragma unroll
        for (int kk = 0; kk < 4; kk++) {
            uint32_t bh[4][2];
            #pragma unroll
            for (int nj = 0; nj < 4; nj++) {
                uint32_t addr = stb + 2 * MATBYTES + (bRow + nj * 8) * TSTRIDE + kk * 32 + bKoff;
                LDSM_X2(bh[nj][0], bh[nj][1], addr);
            }
            uint32_t af[4][4];
            #pragma unroll
            for (int mi = 0; mi < 4; mi++) {
                uint32_t addr = stb + (aRow + mi * 16) * TSTRIDE + kk * 32 + aKoff;
                LDSM_X4(af[mi][0], af[mi][1], af[mi][2], af[mi][3], addr);
            }
            #pragma unroll
            for (int mi = 0; mi < 4; mi++)
                #pragma unroll
                for (int nj = 0; nj < 4; nj++)
                    MMA16816(acc[mi][nj], af[mi][0], af[mi][1], af[mi][2], af[mi][3],
                             bh[nj][0], bh[nj][1]);
            #pragma unroll
            for (int mi = 0; mi < 4; mi++) {
                uint32_t addr = stb + MATBYTES + (aRow + mi * 16) * TSTRIDE + kk * 32 + aKoff;
                LDSM_X4(af[mi][0], af[mi][1], af[mi][2], af[mi][3], addr);
            }
            #pragma unroll
            for (int mi = 0; mi < 4; mi++)
                #pragma unroll
                for (int nj = 0; nj < 4; nj++)
                    MMA16816(acc[mi][nj], af[mi][0], af[mi][1], af[mi][2], af[mi][3],
                             bh[nj][0], bh[nj][1]);
        }
        __syncthreads();
    }

    int rbase = m0 + wm * 64 + (lane >> 2);
    int cbase = n0 + wn * 32 + (lane & 3) * 2;
    #pragma unroll
    for (int mi = 0; mi < 4; mi++) {
        #pragma unroll
        for (int nj = 0; nj < 4; nj++) {
            int r = rbase + mi * 16;
            int col = cbase + nj * 8;
            float b0 = bias[col], b1 = bias[col + 1];
            float v00 = acc[mi][nj][0] + b0, v01 = acc[mi][nj][1] + b1;
            float v10 = acc[mi][nj][2] + b0, v11 = acc[mi][nj][3] + b1;
            size_t i0 = (size_t)r * N + col;
            size_t i1 = (size_t)(r + 8) * N + col;
            if (EPI == 0) {
                *(float2*)&Cf[i0] = make_float2(v00, v01);
                *(float2*)&Cf[i1] = make_float2(v10, v11);
            } else if (EPI == 1) {
                float2 r0 = *(const float2*)&resid[i0];
                float2 r1 = *(const float2*)&resid[i1];
                *(float2*)&Cf[i0] = make_float2(v00 + r0.x, v01 + r0.y);
                *(float2*)&Cf[i1] = make_float2(v10 + r1.x, v11 + r1.y);
            } else if (EPI == 2) {
                v00 = gelu_f(v00); v01 = gelu_f(v01);
                v10 = gelu_f(v10); v11 = gelu_f(v11);
                uint32_t hp, lp;
                pack_split_h(v00, v01, hp, lp);
                *(uint32_t*)&Ch[i0] = hp; *(uint32_t*)&Cl[i0] = lp;
                pack_split_h(v10, v11, hp, lp);
                *(uint32_t*)&Ch[i1] = hp; *(uint32_t*)&Cl[i1] = lp;
            } else {
                int which = col / D_;
                int hh = (col % D_) / DH_;
                int dd = col % DH_;
                int bi = r >> 10, si = r & 1023;
                size_t j0 = (((size_t)(bi * H_ + hh)) * S_ + si) * DH_ + dd;
                size_t j1 = j0 + 8 * DH_;
                if (which == 0) {
                    uint32_t hp, lp;
                    pack_split_h(v00, v01, hp, lp);
                    *(uint32_t*)&Qh_[j0] = hp; *(uint32_t*)&Ql_[j0] = lp;
                    pack_split_h(v10, v11, hp, lp);
                    *(uint32_t*)&Qh_[j1] = hp; *(uint32_t*)&Ql_[j1] = lp;
                } else {
                    __half* d_ = which == 1 ? Kh_ : Vh_;
                    *(uint32_t*)&d_[j0] = pack2h(v00, v01);
                    *(uint32_t*)&d_[j1] = pack2h(v10, v11);
                }
            }
        }
    }
#undef PREFETCH
}

// ---------------- fused flash attention (fp16 2-pass, 128-row Q tiles) --------
// grid (S/128, B*H), 256 threads (8 warps). KV tiles of 128.
__global__ void __launch_bounds__(256)
flash_kernel(const __half* __restrict__ qh, const __half* __restrict__ ql,
             const __half* __restrict__ kh, const __half* __restrict__ vh,
             __half* __restrict__ oh, __half* __restrict__ ol) {
    extern __shared__ char fsm[];
    uint32_t sb = smem_u32(fsm);
    int bh = blockIdx.y;
    int q0 = (gridDim.x - 1 - blockIdx.x) << 7;   // long CTAs first
    int tid = threadIdx.x, wid = tid >> 5, lane = tid & 31;

    {   // Q tile load (128 rows x 128B), hi+lo
        const char* srcH = (const char*)(qh + ((size_t)bh * S_ + q0) * DH_);
        const char* srcL = (const char*)(ql + ((size_t)bh * S_ + q0) * DH_);
        #pragma unroll
        for (int i = tid; i < 1024; i += 256) {
            int r = i >> 3, c = (i & 7) << 4;
            CP16(sb + QOFF_H + r * FSTR + c, srcH + r * 128 + c);
            CP16(sb + QOFF_L + r * FSTR + c, srcL + r * 128 + c);
        }
        CP_COMMIT();
    }

    float m0 = -1e30f, m1 = -1e30f, l0 = 0.f, l1 = 0.f;
    float oacc[8][4];
    #pragma unroll
    for (int d = 0; d < 8; d++)
        oacc[d][0] = oacc[d][1] = oacc[d][2] = oacc[d][3] = 0.f;

    int rA = q0 + wid * 16 + (lane >> 2);
    int nj = (q0 >> 7) + 1;

    uint32_t aAddrBase = sb + (wid * 16 + (lane & 15)) * FSTR + (((lane >> 4) & 1) << 4);
    uint32_t bRowOff = (uint32_t)((lane & 7) * FSTR) + (((lane >> 3) & 1) << 4);

    for (int j = 0; j < nj; j++) {
        __syncthreads();
        {   // K/V tile load (128 rows x 128B)
            const char* kH = (const char*)(kh + ((size_t)bh * S_ + (j << 7)) * DH_);
            const char* vH = (const char*)(vh + ((size_t)bh * S_ + (j << 7)) * DH_);
            #pragma unroll
            for (int i = tid; i < 1024; i += 256) {
                int r = i >> 3, c = (i & 7) << 4;
                uint32_t so = r * FSTR + c;
                size_t go = (size_t)r * 128 + c;
                CP16(sb + KOFF + so, kH + go);
                CP16(sb + VOFF + so, vH + go);
            }
            CP_COMMIT();
            CP_WAIT(0);
        }
        __syncthreads();

        float sf[16][4];
        #pragma unroll
        for (int nt = 0; nt < 16; nt++)
            sf[nt][0] = sf[nt][1] = sf[nt][2] = sf[nt][3] = 0.f;

        #pragma unroll
        for (int kc = 0; kc < 4; kc++) {
            uint32_t qa = aAddrBase + kc * 32;
            uint32_t q_h0,q_h1,q_h2,q_h3, q_l0,q_l1,q_l2,q_l3;
            LDSM_X4(q_h0,q_h1,q_h2,q_h3, qa + QOFF_H);
            LDSM_X4(q_l0,q_l1,q_l2,q_l3, qa + QOFF_L);
            #pragma unroll
            for (int nt = 0; nt < 16; nt++) {
                uint32_t ka = sb + KOFF + nt * 8 * FSTR + bRowOff + kc * 32;
                uint32_t k_h0,k_h1;
                LDSM_X2(k_h0,k_h1, ka);
                MMA16816(sf[nt], q_h0,q_h1,q_h2,q_h3, k_h0,k_h1);
                MMA16816(sf[nt], q_l0,q_l1,q_l2,q_l3, k_h0,k_h1);
            }
        }

        int cb = (j << 7) + (lane & 3) * 2;
        float mx0 = -1e30f, mx1 = -1e30f;
        #pragma unroll
        for (int nt = 0; nt < 16; nt++) {
            int c0 = cb + nt * 8;
            sf[nt][0] = (c0     <= rA)     ? sf[nt][0] * 0.125f : -1e30f;
            sf[nt][1] = (c0 + 1 <= rA)     ? sf[nt][1] * 0.125f : -1e30f;
            sf[nt][2] = (c0     <= rA + 8) ? sf[nt][2] * 0.125f : -1e30f;
            sf[nt][3] = (c0 + 1 <= rA + 8) ? sf[nt][3] * 0.125f : -1e30f;
            mx0 = fmaxf(mx0, fmaxf(sf[nt][0], sf[nt][1]));
            mx1 = fmaxf(mx1, fmaxf(sf[nt][2], sf[nt][3]));
        }
        mx0 = fmaxf(mx0, __shfl_xor_sync(0xffffffffu, mx0, 1));
        mx0 = fmaxf(mx0, __shfl_xor_sync(0xffffffffu, mx0, 2));
        mx1 = fmaxf(mx1, __shfl_xor_sync(0xffffffffu, mx1, 1));
        mx1 = fmaxf(mx1, __shfl_xor_sync(0xffffffffu, mx1, 2));
        float mn0 = fmaxf(m0, mx0), mn1 = fmaxf(m1, mx1);
        float sc0 = expf(m0 - mn0), sc1 = expf(m1 - mn1);
        m0 = mn0; m1 = mn1;
        l0 *= sc0; l1 *= sc1;
        #pragma unroll
        for (int d = 0; d < 8; d++) {
            oacc[d][0] *= sc0; oacc[d][1] *= sc0;
            oacc[d][2] *= sc1; oacc[d][3] *= sc1;
        }
        float s0 = 0.f, s1 = 0.f;
        uint32_t ph[16][2], pl[16][2];
        #pragma unroll
        for (int nt = 0; nt < 16; nt++) {
            float p0 = expf(sf[nt][0] - m0), p1 = expf(sf[nt][1] - m0);
            float p2 = expf(sf[nt][2] - m1), p3 = expf(sf[nt][3] - m1);
            s0 += p0 + p1; s1 += p2 + p3;
            pack_split_h(p0, p1, ph[nt][0], pl[nt][0]);
            pack_split_h(p2, p3, ph[nt][1], pl[nt][1]);
        }
        s0 += __shfl_xor_sync(0xffffffffu, s0, 1);
        s0 += __shfl_xor_sync(0xffffffffu, s0, 2);
        s1 += __shfl_xor_sync(0xffffffffu, s1, 1);
        s1 += __shfl_xor_sync(0xffffffffu, s1, 2);
        l0 += s0; l1 += s1;

        #pragma unroll
        for (int kc = 0; kc < 8; kc++) {
            uint32_t va = sb + VOFF + (kc * 16 + (lane & 15)) * FSTR;
            #pragma unroll
            for (int dt = 0; dt < 8; dt++) {
                uint32_t v_h0,v_h1;
                LDSM_X2_T(v_h0,v_h1, va + dt * 16);
                MMA16816(oacc[dt], ph[2*kc][0], ph[2*kc][1], ph[2*kc+1][0], ph[2*kc+1][1], v_h0, v_h1);
                MMA16816(oacc[dt], pl[2*kc][0], pl[2*kc][1], pl[2*kc+1][0], pl[2*kc+1][1], v_h0, v_h1);
            }
        }
    }

    float inv0 = 1.f / l0, inv1 = 1.f / l1;
    int bb = bh / H_, hH = bh % H_;
    size_t baseA = ((size_t)bb * S_ + rA) * D_ + hH * DH_;
    size_t baseB = baseA + 8 * D_;
    #pragma unroll
    for (int dt = 0; dt < 8; dt++) {
        int c = dt * 8 + (lane & 3) * 2;
        uint32_t hp, lp;
        pack_split_h(oacc[dt][0] * inv0, oacc[dt][1] * inv0, hp, lp);
        *(uint32_t*)&oh[baseA + c] = hp;
        *(uint32_t*)&ol[baseA + c] = lp;
        pack_split_h(oacc[dt][2] * inv1, oacc[dt][3] * inv1, hp, lp);
        *(uint32_t*)&oh[baseB + c] = hp;
        *(uint32_t*)&ol[baseB + c] = lp;
    }
}

// ---------------- host orchestration -----------------------------------------
extern "C" void kernel_launch(void* const* d_in, const int* in_sizes, int n_in,
                              void* d_out, int out_size) {
    const int*   ids    = (const int*)d_in[0];
    const int*   rfi    = (const int*)d_in[1];
    const float* wte    = (const float*)d_in[2];
    const float* wte_rf = (const float*)d_in[3];
    const float* wpe    = (const float*)d_in[4];
    const float* ln1_g  = (const float*)d_in[5];
    const float* ln1_b  = (const float*)d_in[6];
    const float* attn_w = (const float*)d_in[7];
    const float* attn_b = (const float*)d_in[8];
    const float* proj_w = (const float*)d_in[9];
    const float* proj_b = (const float*)d_in[10];
    const float* ln2_g  = (const float*)d_in[11];
    const float* ln2_b  = (const float*)d_in[12];
    const float* fc_w   = (const float*)d_in[13];
    const float* fc_b   = (const float*)d_in[14];
    const float* fc2_w  = (const float*)d_in[15];
    const float* fc2_b  = (const float*)d_in[16];
    const float* lnf_g  = (const float*)d_in[17];
    const float* lnf_b  = (const float*)d_in[18];
    float* out = (float*)d_out;

    float *h;
    __half *ah, *al, *mh, *ml, *oh, *ol;
    __half *qh, *ql, *kh, *vh;
    __half *tah, *tph, *tfh, *t2h;
    cudaGetSymbolAddress((void**)&h,   g_h);
    cudaGetSymbolAddress((void**)&ah,  g_ah);  cudaGetSymbolAddress((void**)&al,  g_al);
    cudaGetSymbolAddress((void**)&mh,  g_mh);  cudaGetSymbolAddress((void**)&ml,  g_ml);
    cudaGetSymbolAddress((void**)&oh,  g_oh);  cudaGetSymbolAddress((void**)&ol,  g_ol);
    cudaGetSymbolAddress((void**)&qh,  g_qh);  cudaGetSymbolAddress((void**)&ql,  g_ql);
    cudaGetSymbolAddress((void**)&kh,  g_kh);  cudaGetSymbolAddress((void**)&vh,  g_vh);
    cudaGetSymbolAddress((void**)&tah, t_attn_h);
    cudaGetSymbolAddress((void**)&tph, t_proj_h);
    cudaGetSymbolAddress((void**)&tfh, t_fc_h);
    cudaGetSymbolAddress((void**)&t2h, t_fc2_h);

    cudaFuncSetAttribute(gemm_mma<1>, cudaFuncAttributeMaxDynamicSharedMemorySize, SMEM_GEMM);
    cudaFuncSetAttribute(gemm_mma<2>, cudaFuncAttributeMaxDynamicSharedMemorySize, SMEM_GEMM);
    cudaFuncSetAttribute(gemm_mma<3>, cudaFuncAttributeMaxDynamicSharedMemorySize, SMEM_GEMM);
    cudaFuncSetAttribute(flash_kernel, cudaFuncAttributeMaxDynamicSharedMemorySize, SMEM_FLASH);

    wsplit_all_kernel<<<TILES_PER_LAYER * L_, dim3(32, 8)>>>(
        attn_w, proj_w, fc_w, fc2_w, tah, tph, tfh, t2h);
    embed_ln_kernel<<<NT_, 256>>>(ids, rfi, wte, wte_rf, wpe, ln1_g, ln1_b, h, ah, al);

    for (int l = 0; l < L_; l++) {
        if (l > 0)
            ln_kernel<true><<<NT_, 256>>>(h, ln1_g + l * D_, ln1_b + l * D_, nullptr, ah, al);
        gemm_mma<3><<<dim3(D3_/128, NT_/128), 256, SMEM_GEMM>>>(
            ah, al, tah + (size_t)l * D3_ * D_,
            attn_b + l * D3_, nullptr, nullptr, nullptr, nullptr,
            qh, ql, kh, vh, NT_, D3_, D_);
        flash_kernel<<<dim3(S_/128, B_*H_), 256, SMEM_FLASH>>>(qh, ql, kh, vh, oh, ol);
        gemm_mma<1><<<dim3(D_/128, NT_/128), 256, SMEM_GEMM>>>(
            oh, ol, tph + (size_t)l * D_ * D_,
            proj_b + l * D_, h, h, nullptr, nullptr,
            nullptr, nullptr, nullptr, nullptr, NT_, D_, D_);
        ln_kernel<true><<<NT_, 256>>>(h, ln2_g + l * D_, ln2_b + l * D_, nullptr, ah, al);
        gemm_mma<2><<<dim3(DF_/128, NT_/128), 256, SMEM_GEMM>>>(
            ah, al, tfh + (size_t)l * DF_ * D_,
            fc_b + l * DF_, nullptr, nullptr, mh, ml,
            nullptr, nullptr, nullptr, nullptr, NT_, DF_, D_);
        gemm_mma<1><<<dim3(D_/128, NT_/128), 256, SMEM_GEMM>>>(
            mh, ml, t2h + (size_t)l * D_ * DF_,
            fc2_b + l * D_, h, h, nullptr, nullptr,
            nullptr, nullptr, nullptr, nullptr, NT_, D_, DF_);
    }
    ln_kernel<false><<<NT_, 256>>>(h, lnf_g, lnf_b, out, nullptr, nullptr);
}

// round 9
// speedup vs baseline: 4.0458x; 1.0048x over previous
#include <cuda_runtime.h>
#include <cuda_fp16.h>
#include <math.h>
#include <stdint.h>

#define B_  4
#define S_  1024
#define D_  768
#define H_  12
#define L_  6
#define DF_ 3072
#define DH_ 64
#define NT_ (B_*S_)        // 4096
#define D3_ (3*D_)         // 2304

// ---------------- scratch (static device globals) ----------------------------
static __device__ float g_h[NT_*D_];
static __device__ __half g_ah[NT_*D_],  g_al[NT_*D_];
static __device__ __half g_mh[NT_*DF_], g_ml[NT_*DF_];
static __device__ __half g_oh[NT_*D_],  g_ol[NT_*D_];
static __device__ __half g_qh[NT_*D_],  g_ql[NT_*D_];
static __device__ __half g_kh[NT_*D_];
static __device__ __half g_vh[NT_*D_];
static __device__ __half t_attn_h[(size_t)L_*D3_*D_];
static __device__ __half t_proj_h[(size_t)L_*D_*D_];
static __device__ __half t_fc_h[(size_t)L_*DF_*D_];
static __device__ __half t_fc2_h[(size_t)L_*D_*DF_];

// ---------------- helpers ----------------------------------------------------
__device__ __forceinline__ uint32_t smem_u32(const void* p) {
    uint32_t a;
    asm("{ .reg .u64 t; cvta.to.shared.u64 t, %1; cvt.u32.u64 %0, t; }" : "=r"(a) : "l"(p));
    return a;
}
__device__ __forceinline__ float gelu_f(float x) {
    const float c = 0.7978845608028654f;
    return 0.5f * x * (1.0f + tanhf(c * (x + 0.044715f * x * x * x)));
}
__device__ __forceinline__ void split_h(float v, __half& hi, __half& lo) {
    hi = __float2half_rn(v);
    lo = __float2half_rn(v - __half2float(hi));
}
__device__ __forceinline__ uint32_t pack2h(float x, float y) {
    __half2 p; p.x = __float2half_rn(x); p.y = __float2half_rn(y);
    return *(uint32_t*)&p;
}
__device__ __forceinline__ void pack_split_h(float x, float y, uint32_t& hp, uint32_t& lp) {
    __half hx, lx, hy, ly;
    split_h(x, hx, lx); split_h(y, hy, ly);
    __half2 h2; h2.x = hx; h2.y = hy;
    __half2 l2; l2.x = lx; l2.y = ly;
    hp = *(uint32_t*)&h2; lp = *(uint32_t*)&l2;
}

#define CP16(dst, src) \
    asm volatile("cp.async.cg.shared.global [%0], [%1], 16;" :: "r"(dst), "l"(src))
#define CP_COMMIT() asm volatile("cp.async.commit_group;")
#define CP_WAIT(n)  asm volatile("cp.async.wait_group %0;" :: "n"(n))

#define LDSM_X4(r0, r1, r2, r3, a) \
    asm volatile("ldmatrix.sync.aligned.m8n8.x4.shared.b16 {%0,%1,%2,%3}, [%4];" \
                 : "=r"(r0), "=r"(r1), "=r"(r2), "=r"(r3) : "r"(a))
#define LDSM_X2(r0, r1, a) \
    asm volatile("ldmatrix.sync.aligned.m8n8.x2.shared.b16 {%0,%1}, [%2];" \
                 : "=r"(r0), "=r"(r1) : "r"(a))
#define LDSM_X2_T(r0, r1, a) \
    asm volatile("ldmatrix.sync.aligned.m8n8.x2.trans.shared.b16 {%0,%1}, [%2];" \
                 : "=r"(r0), "=r"(r1) : "r"(a))
#define MMA16816(d, a0, a1, a2, a3, b0, b1) \
    asm volatile("mma.sync.aligned.m16n8k16.row.col.f32.f16.f16.f32 " \
                 "{%0,%1,%2,%3},{%4,%5,%6,%7},{%8,%9},{%0,%1,%2,%3};" \
                 : "+f"((d)[0]), "+f"((d)[1]), "+f"((d)[2]), "+f"((d)[3]) \
                 : "r"(a0), "r"(a1), "r"(a2), "r"(a3), "r"(b0), "r"(b1))

// gemm smem: 128 rows x 64 fp16 (128B) padded to 144B; 3 matrices per stage
#define TSTRIDE 144
#define MATBYTES 18432
#define STAGEBYTES 55296
#define SMEM_GEMM (2*STAGEBYTES)

// flash smem: 64-row Q (hi/lo) + double-buffered 128-row K,V tiles; 144B stride
#define FSTR 144
#define QOFF_H 0
#define QOFF_L 9216
#define KV0    18432           // stage0: K at +0, V at +18432
#define KVSTG  36864           // bytes per KV stage (K+V)
#define SMEM_FLASH 92160       // 18432 + 2*36864

// ---------------- fused weight transpose + fp16 convert ----------------------
#define TILES_PER_LAYER 6912
__global__ void wsplit_all_kernel(const float* __restrict__ attn_w, const float* __restrict__ proj_w,
                                  const float* __restrict__ fc_w,   const float* __restrict__ fc2_w,
                                  __half* __restrict__ tah, __half* __restrict__ tph,
                                  __half* __restrict__ tfh, __half* __restrict__ t2h) {
    __shared__ float t[32][33];
    int bid = blockIdx.x;
    int l = bid / TILES_PER_LAYER;
    int r = bid % TILES_PER_LAYER;
    const float* W; __half* Oh; int K, N, tile;
    if (r < 1728)      { W = attn_w; Oh = tah; K = D_;  N = D3_; tile = r; }
    else if (r < 2304) { W = proj_w; Oh = tph; K = D_;  N = D_;  tile = r - 1728; }
    else if (r < 4608) { W = fc_w;   Oh = tfh; K = D_;  N = DF_; tile = r - 2304; }
    else               { W = fc2_w;  Oh = t2h; K = DF_; N = D_;  tile = r - 4608; }
    int nx = N >> 5;
    int n0 = (tile % nx) << 5, k0 = (tile / nx) << 5;
    const float* Wl = W + (size_t)l * K * N;
    __half* OhL = Oh + (size_t)l * K * N;
    int tx = threadIdx.x, ty = threadIdx.y;    // (32,8)
    for (int i = ty; i < 32; i += 8)
        t[i][tx] = Wl[(size_t)(k0 + i) * N + n0 + tx];
    __syncthreads();
    for (int i = ty; i < 32; i += 8)
        OhL[(size_t)(n0 + i) * K + k0 + tx] = __float2half_rn(t[tx][i]);
}

// ---------------- fused embedding + layer-0 ln1 -------------------------------
__global__ void embed_ln_kernel(const int* __restrict__ ids, const int* __restrict__ rfi,
                                const float* __restrict__ wte, const float* __restrict__ wte_rf,
                                const float* __restrict__ wpe,
                                const float* __restrict__ g, const float* __restrict__ b,
                                float* __restrict__ h,
                                __half* __restrict__ yh, __half* __restrict__ yl) {
    int row = blockIdx.x;
    int s = row & (S_ - 1);
    int t = threadIdx.x;
    const float* e1 = wte    + (size_t)ids[row] * D_;
    const float* e2 = wte_rf + (size_t)rfi[row] * D_;
    const float* e3 = wpe    + (size_t)s * D_;
    float v0 = e1[t]       + e2[t]       + e3[t];
    float v1 = e1[t + 256] + e2[t + 256] + e3[t + 256];
    float v2 = e1[t + 512] + e2[t + 512] + e3[t + 512];
    float* hr = h + (size_t)row * D_;
    hr[t] = v0; hr[t + 256] = v1; hr[t + 512] = v2;
    __shared__ float red[256];
    red[t] = v0 + v1 + v2;
    __syncthreads();
    for (int o = 128; o > 0; o >>= 1) { if (t < o) red[t] += red[t + o]; __syncthreads(); }
    float mu = red[0] * (1.0f / D_);
    __syncthreads();
    float d0 = v0 - mu, d1 = v1 - mu, d2 = v2 - mu;
    red[t] = d0*d0 + d1*d1 + d2*d2;
    __syncthreads();
    for (int o = 128; o > 0; o >>= 1) { if (t < o) red[t] += red[t + o]; __syncthreads(); }
    float inv = rsqrtf(red[0] * (1.0f / D_) + 1e-5f);
    float r0 = d0 * inv * g[t]       + b[t];
    float r1 = d1 * inv * g[t + 256] + b[t + 256];
    float r2 = d2 * inv * g[t + 512] + b[t + 512];
    __half hi, lo;
    size_t base = (size_t)row * D_;
    split_h(r0, hi, lo); yh[base + t]       = hi; yl[base + t]       = lo;
    split_h(r1, hi, lo); yh[base + t + 256] = hi; yl[base + t + 256] = lo;
    split_h(r2, hi, lo); yh[base + t + 512] = hi; yl[base + t + 512] = lo;
}

// ---------------- layernorm --------------------------------------------------
template<bool HF>
__global__ void ln_kernel(const float* __restrict__ x, const float* __restrict__ g,
                          const float* __restrict__ b, float* __restrict__ y,
                          __half* __restrict__ yh, __half* __restrict__ yl) {
    int row = blockIdx.x;
    int t = threadIdx.x;
    const float* xr = x + (size_t)row * D_;
    float v0 = xr[t], v1 = xr[t + 256], v2 = xr[t + 512];
    __shared__ float red[256];
    red[t] = v0 + v1 + v2;
    __syncthreads();
    for (int o = 128; o > 0; o >>= 1) { if (t < o) red[t] += red[t + o]; __syncthreads(); }
    float mu = red[0] * (1.0f / D_);
    __syncthreads();
    float d0 = v0 - mu, d1 = v1 - mu, d2 = v2 - mu;
    red[t] = d0*d0 + d1*d1 + d2*d2;
    __syncthreads();
    for (int o = 128; o > 0; o >>= 1) { if (t < o) red[t] += red[t + o]; __syncthreads(); }
    float inv = rsqrtf(red[0] * (1.0f / D_) + 1e-5f);
    float r0 = d0 * inv * g[t]       + b[t];
    float r1 = d1 * inv * g[t + 256] + b[t + 256];
    float r2 = d2 * inv * g[t + 512] + b[t + 512];
    if (HF) {
        __half hi, lo;
        size_t base = (size_t)row * D_;
        split_h(r0, hi, lo); yh[base + t]       = hi; yl[base + t]       = lo;
        split_h(r1, hi, lo); yh[base + t + 256] = hi; yl[base + t + 256] = lo;
        split_h(r2, hi, lo); yh[base + t + 512] = hi; yl[base + t + 512] = lo;
    } else {
        float* yr = y + (size_t)row * D_;
        yr[t] = r0; yr[t + 256] = r1; yr[t + 512] = r2;
    }
}

// ---------------- mma.sync GEMM (fp16 2-pass, K-chunk 64) ---------------------
template<int EPI>
__global__ void __launch_bounds__(256, 2)
gemm_mma(const __half* __restrict__ Ah, const __half* __restrict__ Al,
         const __half* __restrict__ Bh,
         const float* __restrict__ bias, const float* __restrict__ resid,
         float* __restrict__ Cf, __half* __restrict__ Ch, __half* __restrict__ Cl,
         __half* __restrict__ Qh_, __half* __restrict__ Ql_,
         __half* __restrict__ Kh_, __half* __restrict__ Vh_,
         int M, int N, int K) {
    extern __shared__ char smem[];
    uint32_t sbase = smem_u32(smem);
    int tid = threadIdx.x;
    int wid = tid >> 5, lane = tid & 31;
    int wm = wid >> 2, wn = wid & 3;
    int m0 = blockIdx.y << 7, n0 = blockIdx.x << 7;
    int ldb = K * 2;

    const char* srcs[3];
    srcs[0] = (const char*)(Ah + (size_t)m0 * K);
    srcs[1] = (const char*)(Al + (size_t)m0 * K);
    srcs[2] = (const char*)(Bh + (size_t)n0 * K);

    float acc[4][4][4] = {};
    int nk = K >> 6;

#define PREFETCH(c, s)                                                        \
    {                                                                         \
        size_t ko = (size_t)(c) << 7;                                         \
        uint32_t stb = sbase + (s) * STAGEBYTES;                              \
        _Pragma("unroll")                                                     \
        for (int j = 0; j < 12; j++) {                                        \
            int q = tid + j * 256;                                            \
            int mat = q >> 10, w = q & 1023, row = w >> 3, cc = w & 7;        \
            uint32_t dst = stb + mat * MATBYTES + row * TSTRIDE + cc * 16;    \
            const char* sp = srcs[mat] + (size_t)row * ldb + ko + cc * 16;    \
            CP16(dst, sp);                                                    \
        }                                                                     \
        CP_COMMIT();                                                          \
    }

    PREFETCH(0, 0);

    int aRow = wm * 64 + (lane & 7) + ((lane >> 3) & 1) * 8;
    uint32_t aKoff = ((lane >> 4) & 1) * 16;
    int lb = lane & 15;
    int bRow = wn * 32 + (lb & 7);
    uint32_t bKoff = ((lb >> 3) & 1) * 16;

    for (int c = 0; c < nk; c++) {
        int s = c & 1;
        if (c + 1 < nk) PREFETCH(c + 1, s ^ 1);
        if (c + 1 < nk) { CP_WAIT(1); } else { CP_WAIT(0); }
        __syncthreads();

        uint32_t stb = sbase + s * STAGEBYTES;
        #pragma unroll
        for (int kk = 0; kk < 4; kk++) {
            uint32_t bh[4][2];
            #pragma unroll
            for (int nj = 0; nj < 4; nj++) {
                uint32_t addr = stb + 2 * MATBYTES + (bRow + nj * 8) * TSTRIDE + kk * 32 + bKoff;
                LDSM_X2(bh[nj][0], bh[nj][1], addr);
            }
            uint32_t af[4][4];
            #pragma unroll
            for (int mi = 0; mi < 4; mi++) {
                uint32_t addr = stb + (aRow + mi * 16) * TSTRIDE + kk * 32 + aKoff;
                LDSM_X4(af[mi][0], af[mi][1], af[mi][2], af[mi][3], addr);
            }
            #pragma unroll
            for (int mi = 0; mi < 4; mi++)
                #pragma unroll
                for (int nj = 0; nj < 4; nj++)
                    MMA16816(acc[mi][nj], af[mi][0], af[mi][1], af[mi][2], af[mi][3],
                             bh[nj][0], bh[nj][1]);
            #pragma unroll
            for (int mi = 0; mi < 4; mi++) {
                uint32_t addr = stb + MATBYTES + (aRow + mi * 16) * TSTRIDE + kk * 32 + aKoff;
                LDSM_X4(af[mi][0], af[mi][1], af[mi][2], af[mi][3], addr);
            }
            #pragma unroll
            for (int mi = 0; mi < 4; mi++)
                #pragma unroll
                for (int nj = 0; nj < 4; nj++)
                    MMA16816(acc[mi][nj], af[mi][0], af[mi][1], af[mi][2], af[mi][3],
                             bh[nj][0], bh[nj][1]);
        }
        __syncthreads();
    }

    int rbase = m0 + wm * 64 + (lane >> 2);
    int cbase = n0 + wn * 32 + (lane & 3) * 2;
    #pragma unroll
    for (int mi = 0; mi < 4; mi++) {
        #pragma unroll
        for (int nj = 0; nj < 4; nj++) {
            int r = rbase + mi * 16;
            int col = cbase + nj * 8;
            float b0 = bias[col], b1 = bias[col + 1];
            float v00 = acc[mi][nj][0] + b0, v01 = acc[mi][nj][1] + b1;
            float v10 = acc[mi][nj][2] + b0, v11 = acc[mi][nj][3] + b1;
            size_t i0 = (size_t)r * N + col;
            size_t i1 = (size_t)(r + 8) * N + col;
            if (EPI == 0) {
                *(float2*)&Cf[i0] = make_float2(v00, v01);
                *(float2*)&Cf[i1] = make_float2(v10, v11);
            } else if (EPI == 1) {
                float2 r0 = *(const float2*)&resid[i0];
                float2 r1 = *(const float2*)&resid[i1];
                *(float2*)&Cf[i0] = make_float2(v00 + r0.x, v01 + r0.y);
                *(float2*)&Cf[i1] = make_float2(v10 + r1.x, v11 + r1.y);
            } else if (EPI == 2) {
                v00 = gelu_f(v00); v01 = gelu_f(v01);
                v10 = gelu_f(v10); v11 = gelu_f(v11);
                uint32_t hp, lp;
                pack_split_h(v00, v01, hp, lp);
                *(uint32_t*)&Ch[i0] = hp; *(uint32_t*)&Cl[i0] = lp;
                pack_split_h(v10, v11, hp, lp);
                *(uint32_t*)&Ch[i1] = hp; *(uint32_t*)&Cl[i1] = lp;
            } else {
                int which = col / D_;
                int hh = (col % D_) / DH_;
                int dd = col % DH_;
                int bi = r >> 10, si = r & 1023;
                size_t j0 = (((size_t)(bi * H_ + hh)) * S_ + si) * DH_ + dd;
                size_t j1 = j0 + 8 * DH_;
                if (which == 0) {
                    uint32_t hp, lp;
                    pack_split_h(v00, v01, hp, lp);
                    *(uint32_t*)&Qh_[j0] = hp; *(uint32_t*)&Ql_[j0] = lp;
                    pack_split_h(v10, v11, hp, lp);
                    *(uint32_t*)&Qh_[j1] = hp; *(uint32_t*)&Ql_[j1] = lp;
                } else {
                    __half* d_ = which == 1 ? Kh_ : Vh_;
                    *(uint32_t*)&d_[j0] = pack2h(v00, v01);
                    *(uint32_t*)&d_[j1] = pack2h(v10, v11);
                }
            }
        }
    }
#undef PREFETCH
}

// ---------------- fused flash attention (64-row Q, double-buffered KV) --------
// grid (S/64, B*H), 128 threads (4 warps).
__global__ void __launch_bounds__(128)
flash_kernel(const __half* __restrict__ qh, const __half* __restrict__ ql,
             const __half* __restrict__ kh, const __half* __restrict__ vh,
             __half* __restrict__ oh, __half* __restrict__ ol) {
    extern __shared__ char fsm[];
    uint32_t sb = smem_u32(fsm);
    int bh = blockIdx.y;
    int q0 = (gridDim.x - 1 - blockIdx.x) << 6;   // long CTAs first
    int tid = threadIdx.x, wid = tid >> 5, lane = tid & 31;
    int nj = (q0 >> 7) + 1;

    {   // Q tile load (64 rows x 128B), hi+lo
        const char* srcH = (const char*)(qh + ((size_t)bh * S_ + q0) * DH_);
        const char* srcL = (const char*)(ql + ((size_t)bh * S_ + q0) * DH_);
        #pragma unroll
        for (int i = tid; i < 512; i += 128) {
            int r = i >> 3, c = (i & 7) << 4;
            CP16(sb + QOFF_H + r * FSTR + c, srcH + r * 128 + c);
            CP16(sb + QOFF_L + r * FSTR + c, srcL + r * 128 + c);
        }
        CP_COMMIT();
    }

#define PREFETCH_KV(j, s)                                                      \
    {                                                                          \
        const char* kH = (const char*)(kh + ((size_t)bh * S_ + ((j) << 7)) * DH_); \
        const char* vH = (const char*)(vh + ((size_t)bh * S_ + ((j) << 7)) * DH_); \
        uint32_t stb = sb + KV0 + (s) * KVSTG;                                 \
        _Pragma("unroll")                                                      \
        for (int i = tid; i < 1024; i += 128) {                                \
            int r = i >> 3, c = (i & 7) << 4;                                  \
            uint32_t so = r * FSTR + c;                                        \
            size_t go = (size_t)r * 128 + c;                                   \
            CP16(stb + so, kH + go);                                           \
            CP16(stb + 18432 + so, vH + go);                                   \
        }                                                                      \
        CP_COMMIT();                                                           \
    }

    PREFETCH_KV(0, 0);

    float m0 = -1e30f, m1 = -1e30f, l0 = 0.f, l1 = 0.f;
    float oacc[8][4];
    #pragma unroll
    for (int d = 0; d < 8; d++)
        oacc[d][0] = oacc[d][1] = oacc[d][2] = oacc[d][3] = 0.f;

    int rA = q0 + wid * 16 + (lane >> 2);
    uint32_t aAddrBase = sb + (wid * 16 + (lane & 15)) * FSTR + (((lane >> 4) & 1) << 4);
    uint32_t bRowOff = (uint32_t)((lane & 7) * FSTR) + (((lane >> 3) & 1) << 4);

    for (int j = 0; j < nj; j++) {
        int s = j & 1;
        if (j + 1 < nj) PREFETCH_KV(j + 1, s ^ 1);
        if (j + 1 < nj) { CP_WAIT(1); } else { CP_WAIT(0); }
        __syncthreads();
        uint32_t kbase = sb + KV0 + s * KVSTG;
        uint32_t vbase = kbase + 18432;

        float sf[16][4];
        #pragma unroll
        for (int nt = 0; nt < 16; nt++)
            sf[nt][0] = sf[nt][1] = sf[nt][2] = sf[nt][3] = 0.f;

        #pragma unroll
        for (int kc = 0; kc < 4; kc++) {
            uint32_t qa = aAddrBase + kc * 32;
            uint32_t q_h0,q_h1,q_h2,q_h3, q_l0,q_l1,q_l2,q_l3;
            LDSM_X4(q_h0,q_h1,q_h2,q_h3, qa + QOFF_H);
            LDSM_X4(q_l0,q_l1,q_l2,q_l3, qa + QOFF_L);
            #pragma unroll
            for (int nt = 0; nt < 16; nt++) {
                uint32_t ka = kbase + nt * 8 * FSTR + bRowOff + kc * 32;
                uint32_t k_h0,k_h1;
                LDSM_X2(k_h0,k_h1, ka);
                MMA16816(sf[nt], q_h0,q_h1,q_h2,q_h3, k_h0,k_h1);
                MMA16816(sf[nt], q_l0,q_l1,q_l2,q_l3, k_h0,k_h1);
            }
        }

        int cb = (j << 7) + (lane & 3) * 2;
        float mx0 = -1e30f, mx1 = -1e30f;
        #pragma unroll
        for (int nt = 0; nt < 16; nt++) {
            int c0 = cb + nt * 8;
            sf[nt][0] = (c0     <= rA)     ? sf[nt][0] * 0.125f : -1e30f;
            sf[nt][1] = (c0 + 1 <= rA)     ? sf[nt][1] * 0.125f : -1e30f;
            sf[nt][2] = (c0     <= rA + 8) ? sf[nt][2] * 0.125f : -1e30f;
            sf[nt][3] = (c0 + 1 <= rA + 8) ? sf[nt][3] * 0.125f : -1e30f;
            mx0 = fmaxf(mx0, fmaxf(sf[nt][0], sf[nt][1]));
            mx1 = fmaxf(mx1, fmaxf(sf[nt][2], sf[nt][3]));
        }
        mx0 = fmaxf(mx0, __shfl_xor_sync(0xffffffffu, mx0, 1));
        mx0 = fmaxf(mx0, __shfl_xor_sync(0xffffffffu, mx0, 2));
        mx1 = fmaxf(mx1, __shfl_xor_sync(0xffffffffu, mx1, 1));
        mx1 = fmaxf(mx1, __shfl_xor_sync(0xffffffffu, mx1, 2));
        float mn0 = fmaxf(m0, mx0), mn1 = fmaxf(m1, mx1);
        float sc0 = expf(m0 - mn0), sc1 = expf(m1 - mn1);
        m0 = mn0; m1 = mn1;
        l0 *= sc0; l1 *= sc1;
        #pragma unroll
        for (int d = 0; d < 8; d++) {
            oacc[d][0] *= sc0; oacc[d][1] *= sc0;
            oacc[d][2] *= sc1; oacc[d][3] *= sc1;
        }
        float s0 = 0.f, s1 = 0.f;
        uint32_t ph[16][2], pl[16][2];
        #pragma unroll
        for (int nt = 0; nt < 16; nt++) {
            float p0 = expf(sf[nt][0] - m0), p1 = expf(sf[nt][1] - m0);
            float p2 = expf(sf[nt][2] - m1), p3 = expf(sf[nt][3] - m1);
            s0 += p0 + p1; s1 += p2 + p3;
            pack_split_h(p0, p1, ph[nt][0], pl[nt][0]);
            pack_split_h(p2, p3, ph[nt][1], pl[nt][1]);
        }
        s0 += __shfl_xor_sync(0xffffffffu, s0, 1);
        s0 += __shfl_xor_sync(0xffffffffu, s0, 2);
        s1 += __shfl_xor_sync(0xffffffffu, s1, 1);
        s1 += __shfl_xor_sync(0xffffffffu, s1, 2);
        l0 += s0; l1 += s1;

        #pragma unroll
        for (int kc = 0; kc < 8; kc++) {
            uint32_t va = vbase + (kc * 16 + (lane & 15)) * FSTR;
            #pragma unroll
            for (int dt = 0; dt < 8; dt++) {
                uint32_t v_h0,v_h1;
                LDSM_X2_T(v_h0,v_h1, va + dt * 16);
                MMA16816(oacc[dt], ph[2*kc][0], ph[2*kc][1], ph[2*kc+1][0], ph[2*kc+1][1], v_h0, v_h1);
                MMA16816(oacc[dt], pl[2*kc][0], pl[2*kc][1], pl[2*kc+1][0], pl[2*kc+1][1], v_h0, v_h1);
            }
        }
        __syncthreads();
    }
#undef PREFETCH_KV

    float inv0 = 1.f / l0, inv1 = 1.f / l1;
    int bb = bh / H_, hH = bh % H_;
    size_t baseA = ((size_t)bb * S_ + rA) * D_ + hH * DH_;
    size_t baseB = baseA + 8 * D_;
    #pragma unroll
    for (int dt = 0; dt < 8; dt++) {
        int c = dt * 8 + (lane & 3) * 2;
        uint32_t hp, lp;
        pack_split_h(oacc[dt][0] * inv0, oacc[dt][1] * inv0, hp, lp);
        *(uint32_t*)&oh[baseA + c] = hp;
        *(uint32_t*)&ol[baseA + c] = lp;
        pack_split_h(oacc[dt][2] * inv1, oacc[dt][3] * inv1, hp, lp);
        *(uint32_t*)&oh[baseB + c] = hp;
        *(uint32_t*)&ol[baseB + c] = lp;
    }
}

// ---------------- host orchestration -----------------------------------------
extern "C" void kernel_launch(void* const* d_in, const int* in_sizes, int n_in,
                              void* d_out, int out_size) {
    const int*   ids    = (const int*)d_in[0];
    const int*   rfi    = (const int*)d_in[1];
    const float* wte    = (const float*)d_in[2];
    const float* wte_rf = (const float*)d_in[3];
    const float* wpe    = (const float*)d_in[4];
    const float* ln1_g  = (const float*)d_in[5];
    const float* ln1_b  = (const float*)d_in[6];
    const float* attn_w = (const float*)d_in[7];
    const float* attn_b = (const float*)d_in[8];
    const float* proj_w = (const float*)d_in[9];
    const float* proj_b = (const float*)d_in[10];
    const float* ln2_g  = (const float*)d_in[11];
    const float* ln2_b  = (const float*)d_in[12];
    const float* fc_w   = (const float*)d_in[13];
    const float* fc_b   = (const float*)d_in[14];
    const float* fc2_w  = (const float*)d_in[15];
    const float* fc2_b  = (const float*)d_in[16];
    const float* lnf_g  = (const float*)d_in[17];
    const float* lnf_b  = (const float*)d_in[18];
    float* out = (float*)d_out;

    float *h;
    __half *ah, *al, *mh, *ml, *oh, *ol;
    __half *qh, *ql, *kh, *vh;
    __half *tah, *tph, *tfh, *t2h;
    cudaGetSymbolAddress((void**)&h,   g_h);
    cudaGetSymbolAddress((void**)&ah,  g_ah);  cudaGetSymbolAddress((void**)&al,  g_al);
    cudaGetSymbolAddress((void**)&mh,  g_mh);  cudaGetSymbolAddress((void**)&ml,  g_ml);
    cudaGetSymbolAddress((void**)&oh,  g_oh);  cudaGetSymbolAddress((void**)&ol,  g_ol);
    cudaGetSymbolAddress((void**)&qh,  g_qh);  cudaGetSymbolAddress((void**)&ql,  g_ql);
    cudaGetSymbolAddress((void**)&kh,  g_kh);  cudaGetSymbolAddress((void**)&vh,  g_vh);
    cudaGetSymbolAddress((void**)&tah, t_attn_h);
    cudaGetSymbolAddress((void**)&tph, t_proj_h);
    cudaGetSymbolAddress((void**)&tfh, t_fc_h);
    cudaGetSymbolAddress((void**)&t2h, t_fc2_h);

    cudaFuncSetAttribute(gemm_mma<1>, cudaFuncAttributeMaxDynamicSharedMemorySize, SMEM_GEMM);
    cudaFuncSetAttribute(gemm_mma<2>, cudaFuncAttributeMaxDynamicSharedMemorySize, SMEM_GEMM);
    cudaFuncSetAttribute(gemm_mma<3>, cudaFuncAttributeMaxDynamicSharedMemorySize, SMEM_GEMM);
    cudaFuncSetAttribute(flash_kernel, cudaFuncAttributeMaxDynamicSharedMemorySize, SMEM_FLASH);

    wsplit_all_kernel<<<TILES_PER_LAYER * L_, dim3(32, 8)>>>(
        attn_w, proj_w, fc_w, fc2_w, tah, tph, tfh, t2h);
    embed_ln_kernel<<<NT_, 256>>>(ids, rfi, wte, wte_rf, wpe, ln1_g, ln1_b, h, ah, al);

    for (int l = 0; l < L_; l++) {
        if (l > 0)
            ln_kernel<true><<<NT_, 256>>>(h, ln1_g + l * D_, ln1_b + l * D_, nullptr, ah, al);
        gemm_mma<3><<<dim3(D3_/128, NT_/128), 256, SMEM_GEMM>>>(
            ah, al, tah + (size_t)l * D3_ * D_,
            attn_b + l * D3_, nullptr, nullptr, nullptr, nullptr,
            qh, ql, kh, vh, NT_, D3_, D_);
        flash_kernel<<<dim3(S_/64, B_*H_), 128, SMEM_FLASH>>>(qh, ql, kh, vh, oh, ol);
        gemm_mma<1><<<dim3(D_/128, NT_/128), 256, SMEM_GEMM>>>(
            oh, ol, tph + (size_t)l * D_ * D_,
            proj_b + l * D_, h, h, nullptr, nullptr,
            nullptr, nullptr, nullptr, nullptr, NT_, D_, D_);
        ln_kernel<true><<<NT_, 256>>>(h, ln2_g + l * D_, ln2_b + l * D_, nullptr, ah, al);
        gemm_mma<2><<<dim3(DF_/128, NT_/128), 256, SMEM_GEMM>>>(
            ah, al, tfh + (size_t)l * DF_ * D_,
            fc_b + l * DF_, nullptr, nullptr, mh, ml,
            nullptr, nullptr, nullptr, nullptr, NT_, DF_, D_);
        gemm_mma<1><<<dim3(D_/128, NT_/128), 256, SMEM_GEMM>>>(
            mh, ml, t2h + (size_t)l * D_ * DF_,
            fc2_b + l * D_, h, h, nullptr, nullptr,
            nullptr, nullptr, nullptr, nullptr, NT_, D_, DF_);
    }
    ln_kernel<false><<<NT_, 256>>>(h, lnf_g, lnf_b, out, nullptr, nullptr);
}

// round 10
// speedup vs baseline: 4.2292x; 1.0453x over previous
#include <cuda_runtime.h>
#include <cuda_fp16.h>
#include <math.h>
#include <stdint.h>

#define B_  4
#define S_  1024
#define D_  768
#define H_  12
#define L_  6
#define DF_ 3072
#define DH_ 64
#define NT_ (B_*S_)        // 4096
#define D3_ (3*D_)         // 2304

// ---------------- scratch (static device globals) ----------------------------
static __device__ float g_h[NT_*D_];
static __device__ __half g_ah[NT_*D_],  g_al[NT_*D_];
static __device__ __half g_mh[NT_*DF_], g_ml[NT_*DF_];
static __device__ __half g_oh[NT_*D_],  g_ol[NT_*D_];
static __device__ __half g_qh[NT_*D_],  g_ql[NT_*D_];
static __device__ __half g_kh[NT_*D_];
static __device__ __half g_vh[NT_*D_];
static __device__ __half t_attn_h[(size_t)L_*D3_*D_];
static __device__ __half t_proj_h[(size_t)L_*D_*D_];
static __device__ __half t_fc_h[(size_t)L_*DF_*D_];
static __device__ __half t_fc2_h[(size_t)L_*D_*DF_];

// ---------------- helpers ----------------------------------------------------
__device__ __forceinline__ uint32_t smem_u32(const void* p) {
    uint32_t a;
    asm("{ .reg .u64 t; cvta.to.shared.u64 t, %1; cvt.u32.u64 %0, t; }" : "=r"(a) : "l"(p));
    return a;
}
__device__ __forceinline__ float gelu_f(float x) {
    const float c = 0.7978845608028654f;
    return 0.5f * x * (1.0f + tanhf(c * (x + 0.044715f * x * x * x)));
}
__device__ __forceinline__ void split_h(float v, __half& hi, __half& lo) {
    hi = __float2half_rn(v);
    lo = __float2half_rn(v - __half2float(hi));
}
__device__ __forceinline__ uint32_t pack2h(float x, float y) {
    __half2 p; p.x = __float2half_rn(x); p.y = __float2half_rn(y);
    return *(uint32_t*)&p;
}
__device__ __forceinline__ void pack_split_h(float x, float y, uint32_t& hp, uint32_t& lp) {
    __half hx, lx, hy, ly;
    split_h(x, hx, lx); split_h(y, hy, ly);
    __half2 h2; h2.x = hx; h2.y = hy;
    __half2 l2; l2.x = lx; l2.y = ly;
    hp = *(uint32_t*)&h2; lp = *(uint32_t*)&l2;
}
__device__ __forceinline__ float warp_sum(float v) {
    #pragma unroll
    for (int o = 16; o > 0; o >>= 1) v += __shfl_xor_sync(0xffffffffu, v, o);
    return v;
}

#define CP16(dst, src) \
    asm volatile("cp.async.cg.shared.global [%0], [%1], 16;" :: "r"(dst), "l"(src))
#define CP_COMMIT() asm volatile("cp.async.commit_group;")
#define CP_WAIT(n)  asm volatile("cp.async.wait_group %0;" :: "n"(n))

#define LDSM_X4(r0, r1, r2, r3, a) \
    asm volatile("ldmatrix.sync.aligned.m8n8.x4.shared.b16 {%0,%1,%2,%3}, [%4];" \
                 : "=r"(r0), "=r"(r1), "=r"(r2), "=r"(r3) : "r"(a))
#define LDSM_X2(r0, r1, a) \
    asm volatile("ldmatrix.sync.aligned.m8n8.x2.shared.b16 {%0,%1}, [%2];" \
                 : "=r"(r0), "=r"(r1) : "r"(a))
#define LDSM_X2_T(r0, r1, a) \
    asm volatile("ldmatrix.sync.aligned.m8n8.x2.trans.shared.b16 {%0,%1}, [%2];" \
                 : "=r"(r0), "=r"(r1) : "r"(a))
#define MMA16816(d, a0, a1, a2, a3, b0, b1) \
    asm volatile("mma.sync.aligned.m16n8k16.row.col.f32.f16.f16.f32 " \
                 "{%0,%1,%2,%3},{%4,%5,%6,%7},{%8,%9},{%0,%1,%2,%3};" \
                 : "+f"((d)[0]), "+f"((d)[1]), "+f"((d)[2]), "+f"((d)[3]) \
                 : "r"(a0), "r"(a1), "r"(a2), "r"(a3), "r"(b0), "r"(b1))

// gemm smem: 128 rows x 64 fp16 (128B) padded to 144B; 3 matrices per stage
#define TSTRIDE 144
#define MATBYTES 18432
#define STAGEBYTES 55296
#define SMEM_GEMM (2*STAGEBYTES)

// flash smem (R7 layout): rows of 64 fp16 (128B) padded to 144B
#define FSTR 144
#define QOFF_H 0
#define QOFF_L 9216
#define KOFF   18432
#define VOFF   36864
#define SMEM_FLASH 55296

// ---------------- fused weight transpose + fp16 convert ----------------------
#define TILES_PER_LAYER 6912
__global__ void wsplit_all_kernel(const float* __restrict__ attn_w, const float* __restrict__ proj_w,
                                  const float* __restrict__ fc_w,   const float* __restrict__ fc2_w,
                                  __half* __restrict__ tah, __half* __restrict__ tph,
                                  __half* __restrict__ tfh, __half* __restrict__ t2h) {
    __shared__ float t[32][33];
    int bid = blockIdx.x;
    int l = bid / TILES_PER_LAYER;
    int r = bid % TILES_PER_LAYER;
    const float* W; __half* Oh; int K, N, tile;
    if (r < 1728)      { W = attn_w; Oh = tah; K = D_;  N = D3_; tile = r; }
    else if (r < 2304) { W = proj_w; Oh = tph; K = D_;  N = D_;  tile = r - 1728; }
    else if (r < 4608) { W = fc_w;   Oh = tfh; K = D_;  N = DF_; tile = r - 2304; }
    else               { W = fc2_w;  Oh = t2h; K = DF_; N = D_;  tile = r - 4608; }
    int nx = N >> 5;
    int n0 = (tile % nx) << 5, k0 = (tile / nx) << 5;
    const float* Wl = W + (size_t)l * K * N;
    __half* OhL = Oh + (size_t)l * K * N;
    int tx = threadIdx.x, ty = threadIdx.y;    // (32,8)
    for (int i = ty; i < 32; i += 8)
        t[i][tx] = Wl[(size_t)(k0 + i) * N + n0 + tx];
    __syncthreads();
    for (int i = ty; i < 32; i += 8)
        OhL[(size_t)(n0 + i) * K + k0 + tx] = __float2half_rn(t[tx][i]);
}

// ---------------- warp-per-row layernorms -------------------------------------
// 256 threads = 8 warps = 8 rows/block; pure shfl reductions, no smem.
#define LNROWS 8
__global__ void embed_ln_kernel(const int* __restrict__ ids, const int* __restrict__ rfi,
                                const float* __restrict__ wte, const float* __restrict__ wte_rf,
                                const float* __restrict__ wpe,
                                const float* __restrict__ g, const float* __restrict__ b,
                                float* __restrict__ h,
                                __half* __restrict__ yh, __half* __restrict__ yl) {
    int w = threadIdx.x >> 5, lane = threadIdx.x & 31;
    int row = blockIdx.x * LNROWS + w;
    int s = row & (S_ - 1);
    const float* e1 = wte    + (size_t)ids[row] * D_;
    const float* e2 = wte_rf + (size_t)rfi[row] * D_;
    const float* e3 = wpe    + (size_t)s * D_;
    float* hr = h + (size_t)row * D_;
    float v[24];
    float sum = 0.f;
    #pragma unroll
    for (int i = 0; i < 24; i++) {
        int c = lane + (i << 5);
        float x = e1[c] + e2[c] + e3[c];
        hr[c] = x;
        v[i] = x; sum += x;
    }
    sum = warp_sum(sum);
    float mu = sum * (1.0f / D_);
    float q = 0.f;
    #pragma unroll
    for (int i = 0; i < 24; i++) { v[i] -= mu; q += v[i] * v[i]; }
    q = warp_sum(q);
    float inv = rsqrtf(q * (1.0f / D_) + 1e-5f);
    size_t base = (size_t)row * D_;
    #pragma unroll
    for (int i = 0; i < 24; i++) {
        int c = lane + (i << 5);
        float r = v[i] * inv * g[c] + b[c];
        __half hi, lo; split_h(r, hi, lo);
        yh[base + c] = hi; yl[base + c] = lo;
    }
}

template<bool HF>
__global__ void ln_kernel(const float* __restrict__ x, const float* __restrict__ g,
                          const float* __restrict__ b, float* __restrict__ y,
                          __half* __restrict__ yh, __half* __restrict__ yl) {
    int w = threadIdx.x >> 5, lane = threadIdx.x & 31;
    int row = blockIdx.x * LNROWS + w;
    const float* xr = x + (size_t)row * D_;
    float v[24];
    float sum = 0.f;
    #pragma unroll
    for (int i = 0; i < 24; i++) { v[i] = xr[lane + (i << 5)]; sum += v[i]; }
    sum = warp_sum(sum);
    float mu = sum * (1.0f / D_);
    float q = 0.f;
    #pragma unroll
    for (int i = 0; i < 24; i++) { v[i] -= mu; q += v[i] * v[i]; }
    q = warp_sum(q);
    float inv = rsqrtf(q * (1.0f / D_) + 1e-5f);
    size_t base = (size_t)row * D_;
    #pragma unroll
    for (int i = 0; i < 24; i++) {
        int c = lane + (i << 5);
        float r = v[i] * inv * g[c] + b[c];
        if (HF) {
            __half hi, lo; split_h(r, hi, lo);
            yh[base + c] = hi; yl[base + c] = lo;
        } else {
            y[base + c] = r;
        }
    }
}

// ---------------- mma.sync GEMM (fp16 2-pass, K-chunk 64) ---------------------
template<int EPI>
__global__ void __launch_bounds__(256, 2)
gemm_mma(const __half* __restrict__ Ah, const __half* __restrict__ Al,
         const __half* __restrict__ Bh,
         const float* __restrict__ bias, const float* __restrict__ resid,
         float* __restrict__ Cf, __half* __restrict__ Ch, __half* __restrict__ Cl,
         __half* __restrict__ Qh_, __half* __restrict__ Ql_,
         __half* __restrict__ Kh_, __half* __restrict__ Vh_,
         int M, int N, int K) {
    extern __shared__ char smem[];
    uint32_t sbase = smem_u32(smem);
    int tid = threadIdx.x;
    int wid = tid >> 5, lane = tid & 31;
    int wm = wid >> 2, wn = wid & 3;
    int m0 = blockIdx.y << 7, n0 = blockIdx.x << 7;
    int ldb = K * 2;

    const char* srcs[3];
    srcs[0] = (const char*)(Ah + (size_t)m0 * K);
    srcs[1] = (const char*)(Al + (size_t)m0 * K);
    srcs[2] = (const char*)(Bh + (size_t)n0 * K);

    float acc[4][4][4] = {};
    int nk = K >> 6;

#define PREFETCH(c, s)                                                        \
    {                                                                         \
        size_t ko = (size_t)(c) << 7;                                         \
        uint32_t stb = sbase + (s) * STAGEBYTES;                              \
        _Pragma("unroll")                                                     \
        for (int j = 0; j < 12; j++) {                                        \
            int q = tid + j * 256;                                            \
            int mat = q >> 10, w = q & 1023, row = w >> 3, cc = w & 7;        \
            uint32_t dst = stb + mat * MATBYTES + row * TSTRIDE + cc * 16;    \
            const char* sp = srcs[mat] + (size_t)row * ldb + ko + cc * 16;    \
            CP16(dst, sp);                                                    \
        }                                                                     \
        CP_COMMIT();                                                          \
    }

    PREFETCH(0, 0);

    int aRow = wm * 64 + (lane & 7) + ((lane >> 3) & 1) * 8;
    uint32_t aKoff = ((lane >> 4) & 1) * 16;
    int lb = lane & 15;
    int bRow = wn * 32 + (lb & 7);
    uint32_t bKoff = ((lb >> 3) & 1) * 16;

    for (int c = 0; c < nk; c++) {
        int s = c & 1;
        if (c + 1 < nk) PREFETCH(c + 1, s ^ 1);
        if (c + 1 < nk) { CP_WAIT(1); } else { CP_WAIT(0); }
        __syncthreads();

        uint32_t stb = sbase + s * STAGEBYTES;
        #pragma unroll
        for (int kk = 0; kk < 4; kk++) {
            uint32_t bh[4][2];
            #pragma unroll
            for (int nj = 0; nj < 4; nj++) {
                uint32_t addr = stb + 2 * MATBYTES + (bRow + nj * 8) * TSTRIDE + kk * 32 + bKoff;
                LDSM_X2(bh[nj][0], bh[nj][1], addr);
            }
            uint32_t af[4][4];
            #pragma unroll
            for (int mi = 0; mi < 4; mi++) {
                uint32_t addr = stb + (aRow + mi * 16) * TSTRIDE + kk * 32 + aKoff;
                LDSM_X4(af[mi][0], af[mi][1], af[mi][2], af[mi][3], addr);
            }
            #pragma unroll
            for (int mi = 0; mi < 4; mi++)
                #pragma unroll
                for (int nj = 0; nj < 4; nj++)
                    MMA16816(acc[mi][nj], af[mi][0], af[mi][1], af[mi][2], af[mi][3],
                             bh[nj][0], bh[nj][1]);
            #pragma unroll
            for (int mi = 0; mi < 4; mi++) {
                uint32_t addr = stb + MATBYTES + (aRow + mi * 16) * TSTRIDE + kk * 32 + aKoff;
                LDSM_X4(af[mi][0], af[mi][1], af[mi][2], af[mi][3], addr);
            }
            #pragma unroll
            for (int mi = 0; mi < 4; mi++)
                #pragma unroll
                for (int nj = 0; nj < 4; nj++)
                    MMA16816(acc[mi][nj], af[mi][0], af[mi][1], af[mi][2], af[mi][3],
                             bh[nj][0], bh[nj][1]);
        }
        __syncthreads();
    }

    int rbase = m0 + wm * 64 + (lane >> 2);
    int cbase = n0 + wn * 32 + (lane & 3) * 2;
    #pragma unroll
    for (int mi = 0; mi < 4; mi++) {
        #pragma unroll
        for (int nj = 0; nj < 4; nj++) {
            int r = rbase + mi * 16;
            int col = cbase + nj * 8;
            float b0 = bias[col], b1 = bias[col + 1];
            float v00 = acc[mi][nj][0] + b0, v01 = acc[mi][nj][1] + b1;
            float v10 = acc[mi][nj][2] + b0, v11 = acc[mi][nj][3] + b1;
            size_t i0 = (size_t)r * N + col;
            size_t i1 = (size_t)(r + 8) * N + col;
            if (EPI == 0) {
                *(float2*)&Cf[i0] = make_float2(v00, v01);
                *(float2*)&Cf[i1] = make_float2(v10, v11);
            } else if (EPI == 1) {
                float2 r0 = *(const float2*)&resid[i0];
                float2 r1 = *(const float2*)&resid[i1];
                *(float2*)&Cf[i0] = make_float2(v00 + r0.x, v01 + r0.y);
                *(float2*)&Cf[i1] = make_float2(v10 + r1.x, v11 + r1.y);
            } else if (EPI == 2) {
                v00 = gelu_f(v00); v01 = gelu_f(v01);
                v10 = gelu_f(v10); v11 = gelu_f(v11);
                uint32_t hp, lp;
                pack_split_h(v00, v01, hp, lp);
                *(uint32_t*)&Ch[i0] = hp; *(uint32_t*)&Cl[i0] = lp;
                pack_split_h(v10, v11, hp, lp);
                *(uint32_t*)&Ch[i1] = hp; *(uint32_t*)&Cl[i1] = lp;
            } else {
                int which = col / D_;
                int hh = (col % D_) / DH_;
                int dd = col % DH_;
                int bi = r >> 10, si = r & 1023;
                size_t j0 = (((size_t)(bi * H_ + hh)) * S_ + si) * DH_ + dd;
                size_t j1 = j0 + 8 * DH_;
                if (which == 0) {
                    uint32_t hp, lp;
                    pack_split_h(v00, v01, hp, lp);
                    *(uint32_t*)&Qh_[j0] = hp; *(uint32_t*)&Ql_[j0] = lp;
                    pack_split_h(v10, v11, hp, lp);
                    *(uint32_t*)&Qh_[j1] = hp; *(uint32_t*)&Ql_[j1] = lp;
                } else {
                    __half* d_ = which == 1 ? Kh_ : Vh_;
                    *(uint32_t*)&d_[j0] = pack2h(v00, v01);
                    *(uint32_t*)&d_[j1] = pack2h(v10, v11);
                }
            }
        }
    }
#undef PREFETCH
}

// ---------------- fused flash attention (R7 shape: 64-row Q, single KV buffer) -
__global__ void __launch_bounds__(128)
flash_kernel(const __half* __restrict__ qh, const __half* __restrict__ ql,
             const __half* __restrict__ kh, const __half* __restrict__ vh,
             __half* __restrict__ oh, __half* __restrict__ ol) {
    extern __shared__ char fsm[];
    uint32_t sb = smem_u32(fsm);
    int bh = blockIdx.y;
    int q0 = (gridDim.x - 1 - blockIdx.x) << 6;   // long CTAs first
    int tid = threadIdx.x, wid = tid >> 5, lane = tid & 31;

    {   // Q tile load (64 rows x 128B), hi+lo
        const char* srcH = (const char*)(qh + ((size_t)bh * S_ + q0) * DH_);
        const char* srcL = (const char*)(ql + ((size_t)bh * S_ + q0) * DH_);
        #pragma unroll
        for (int i = tid; i < 512; i += 128) {
            int r = i >> 3, c = (i & 7) << 4;
            CP16(sb + QOFF_H + r * FSTR + c, srcH + r * 128 + c);
            CP16(sb + QOFF_L + r * FSTR + c, srcL + r * 128 + c);
        }
        CP_COMMIT();
    }

    float m0 = -1e30f, m1 = -1e30f, l0 = 0.f, l1 = 0.f;
    float oacc[8][4];
    #pragma unroll
    for (int d = 0; d < 8; d++)
        oacc[d][0] = oacc[d][1] = oacc[d][2] = oacc[d][3] = 0.f;

    int rA = q0 + wid * 16 + (lane >> 2);
    int nj = (q0 >> 7) + 1;

    uint32_t aAddrBase = sb + (wid * 16 + (lane & 15)) * FSTR + (((lane >> 4) & 1) << 4);
    uint32_t bRowOff = (uint32_t)((lane & 7) * FSTR) + (((lane >> 3) & 1) << 4);

    for (int j = 0; j < nj; j++) {
        __syncthreads();
        {   // K/V tile load (128 rows x 128B)
            const char* kH = (const char*)(kh + ((size_t)bh * S_ + (j << 7)) * DH_);
            const char* vH = (const char*)(vh + ((size_t)bh * S_ + (j << 7)) * DH_);
            #pragma unroll
            for (int i = tid; i < 1024; i += 128) {
                int r = i >> 3, c = (i & 7) << 4;
                uint32_t so = r * FSTR + c;
                size_t go = (size_t)r * 128 + c;
                CP16(sb + KOFF + so, kH + go);
                CP16(sb + VOFF + so, vH + go);
            }
            CP_COMMIT();
            CP_WAIT(0);
        }
        __syncthreads();

        float sf[16][4];
        #pragma unroll
        for (int nt = 0; nt < 16; nt++)
            sf[nt][0] = sf[nt][1] = sf[nt][2] = sf[nt][3] = 0.f;

        #pragma unroll
        for (int kc = 0; kc < 4; kc++) {
            uint32_t qa = aAddrBase + kc * 32;
            uint32_t q_h0,q_h1,q_h2,q_h3, q_l0,q_l1,q_l2,q_l3;
            LDSM_X4(q_h0,q_h1,q_h2,q_h3, qa + QOFF_H);
            LDSM_X4(q_l0,q_l1,q_l2,q_l3, qa + QOFF_L);
            #pragma unroll
            for (int nt = 0; nt < 16; nt++) {
                uint32_t ka = sb + KOFF + nt * 8 * FSTR + bRowOff + kc * 32;
                uint32_t k_h0,k_h1;
                LDSM_X2(k_h0,k_h1, ka);
                MMA16816(sf[nt], q_h0,q_h1,q_h2,q_h3, k_h0,k_h1);
                MMA16816(sf[nt], q_l0,q_l1,q_l2,q_l3, k_h0,k_h1);
            }
        }

        int cb = (j << 7) + (lane & 3) * 2;
        float mx0 = -1e30f, mx1 = -1e30f;
        #pragma unroll
        for (int nt = 0; nt < 16; nt++) {
            int c0 = cb + nt * 8;
            sf[nt][0] = (c0     <= rA)     ? sf[nt][0] * 0.125f : -1e30f;
            sf[nt][1] = (c0 + 1 <= rA)     ? sf[nt][1] * 0.125f : -1e30f;
            sf[nt][2] = (c0     <= rA + 8) ? sf[nt][2] * 0.125f : -1e30f;
            sf[nt][3] = (c0 + 1 <= rA + 8) ? sf[nt][3] * 0.125f : -1e30f;
            mx0 = fmaxf(mx0, fmaxf(sf[nt][0], sf[nt][1]));
            mx1 = fmaxf(mx1, fmaxf(sf[nt][2], sf[nt][3]));
        }
        mx0 = fmaxf(mx0, __shfl_xor_sync(0xffffffffu, mx0, 1));
        mx0 = fmaxf(mx0, __shfl_xor_sync(0xffffffffu, mx0, 2));
        mx1 = fmaxf(mx1, __shfl_xor_sync(0xffffffffu, mx1, 1));
        mx1 = fmaxf(mx1, __shfl_xor_sync(0xffffffffu, mx1, 2));
        float mn0 = fmaxf(m0, mx0), mn1 = fmaxf(m1, mx1);
        float sc0 = expf(m0 - mn0), sc1 = expf(m1 - mn1);
        m0 = mn0; m1 = mn1;
        l0 *= sc0; l1 *= sc1;
        #pragma unroll
        for (int d = 0; d < 8; d++) {
            oacc[d][0] *= sc0; oacc[d][1] *= sc0;
            oacc[d][2] *= sc1; oacc[d][3] *= sc1;
        }
        float s0 = 0.f, s1 = 0.f;
        uint32_t ph[16][2], pl[16][2];
        #pragma unroll
        for (int nt = 0; nt < 16; nt++) {
            float p0 = expf(sf[nt][0] - m0), p1 = expf(sf[nt][1] - m0);
            float p2 = expf(sf[nt][2] - m1), p3 = expf(sf[nt][3] - m1);
            s0 += p0 + p1; s1 += p2 + p3;
            pack_split_h(p0, p1, ph[nt][0], pl[nt][0]);
            pack_split_h(p2, p3, ph[nt][1], pl[nt][1]);
        }
        s0 += __shfl_xor_sync(0xffffffffu, s0, 1);
        s0 += __shfl_xor_sync(0xffffffffu, s0, 2);
        s1 += __shfl_xor_sync(0xffffffffu, s1, 1);
        s1 += __shfl_xor_sync(0xffffffffu, s1, 2);
        l0 += s0; l1 += s1;

        #pragma unroll
        for (int kc = 0; kc < 8; kc++) {
            uint32_t va = sb + VOFF + (kc * 16 + (lane & 15)) * FSTR;
            #pragma unroll
            for (int dt = 0; dt < 8; dt++) {
                uint32_t v_h0,v_h1;
                LDSM_X2_T(v_h0,v_h1, va + dt * 16);
                MMA16816(oacc[dt], ph[2*kc][0], ph[2*kc][1], ph[2*kc+1][0], ph[2*kc+1][1], v_h0, v_h1);
                MMA16816(oacc[dt], pl[2*kc][0], pl[2*kc][1], pl[2*kc+1][0], pl[2*kc+1][1], v_h0, v_h1);
            }
        }
    }

    float inv0 = 1.f / l0, inv1 = 1.f / l1;
    int bb = bh / H_, hH = bh % H_;
    size_t baseA = ((size_t)bb * S_ + rA) * D_ + hH * DH_;
    size_t baseB = baseA + 8 * D_;
    #pragma unroll
    for (int dt = 0; dt < 8; dt++) {
        int c = dt * 8 + (lane & 3) * 2;
        uint32_t hp, lp;
        pack_split_h(oacc[dt][0] * inv0, oacc[dt][1] * inv0, hp, lp);
        *(uint32_t*)&oh[baseA + c] = hp;
        *(uint32_t*)&ol[baseA + c] = lp;
        pack_split_h(oacc[dt][2] * inv1, oacc[dt][3] * inv1, hp, lp);
        *(uint32_t*)&oh[baseB + c] = hp;
        *(uint32_t*)&ol[baseB + c] = lp;
    }
}

// ---------------- host orchestration -----------------------------------------
extern "C" void kernel_launch(void* const* d_in, const int* in_sizes, int n_in,
                              void* d_out, int out_size) {
    const int*   ids    = (const int*)d_in[0];
    const int*   rfi    = (const int*)d_in[1];
    const float* wte    = (const float*)d_in[2];
    const float* wte_rf = (const float*)d_in[3];
    const float* wpe    = (const float*)d_in[4];
    const float* ln1_g  = (const float*)d_in[5];
    const float* ln1_b  = (const float*)d_in[6];
    const float* attn_w = (const float*)d_in[7];
    const float* attn_b = (const float*)d_in[8];
    const float* proj_w = (const float*)d_in[9];
    const float* proj_b = (const float*)d_in[10];
    const float* ln2_g  = (const float*)d_in[11];
    const float* ln2_b  = (const float*)d_in[12];
    const float* fc_w   = (const float*)d_in[13];
    const float* fc_b   = (const float*)d_in[14];
    const float* fc2_w  = (const float*)d_in[15];
    const float* fc2_b  = (const float*)d_in[16];
    const float* lnf_g  = (const float*)d_in[17];
    const float* lnf_b  = (const float*)d_in[18];
    float* out = (float*)d_out;

    float *h;
    __half *ah, *al, *mh, *ml, *oh, *ol;
    __half *qh, *ql, *kh, *vh;
    __half *tah, *tph, *tfh, *t2h;
    cudaGetSymbolAddress((void**)&h,   g_h);
    cudaGetSymbolAddress((void**)&ah,  g_ah);  cudaGetSymbolAddress((void**)&al,  g_al);
    cudaGetSymbolAddress((void**)&mh,  g_mh);  cudaGetSymbolAddress((void**)&ml,  g_ml);
    cudaGetSymbolAddress((void**)&oh,  g_oh);  cudaGetSymbolAddress((void**)&ol,  g_ol);
    cudaGetSymbolAddress((void**)&qh,  g_qh);  cudaGetSymbolAddress((void**)&ql,  g_ql);
    cudaGetSymbolAddress((void**)&kh,  g_kh);  cudaGetSymbolAddress((void**)&vh,  g_vh);
    cudaGetSymbolAddress((void**)&tah, t_attn_h);
    cudaGetSymbolAddress((void**)&tph, t_proj_h);
    cudaGetSymbolAddress((void**)&tfh, t_fc_h);
    cudaGetSymbolAddress((void**)&t2h, t_fc2_h);

    cudaFuncSetAttribute(gemm_mma<1>, cudaFuncAttributeMaxDynamicSharedMemorySize, SMEM_GEMM);
    cudaFuncSetAttribute(gemm_mma<2>, cudaFuncAttributeMaxDynamicSharedMemorySize, SMEM_GEMM);
    cudaFuncSetAttribute(gemm_mma<3>, cudaFuncAttributeMaxDynamicSharedMemorySize, SMEM_GEMM);
    cudaFuncSetAttribute(flash_kernel, cudaFuncAttributeMaxDynamicSharedMemorySize, SMEM_FLASH);

    wsplit_all_kernel<<<TILES_PER_LAYER * L_, dim3(32, 8)>>>(
        attn_w, proj_w, fc_w, fc2_w, tah, tph, tfh, t2h);
    embed_ln_kernel<<<NT_/LNROWS, 256>>>(ids, rfi, wte, wte_rf, wpe, ln1_g, ln1_b, h, ah, al);

    for (int l = 0; l < L_; l++) {
        if (l > 0)
            ln_kernel<true><<<NT_/LNROWS, 256>>>(h, ln1_g + l * D_, ln1_b + l * D_, nullptr, ah, al);
        gemm_mma<3><<<dim3(D3_/128, NT_/128), 256, SMEM_GEMM>>>(
            ah, al, tah + (size_t)l * D3_ * D_,
            attn_b + l * D3_, nullptr, nullptr, nullptr, nullptr,
            qh, ql, kh, vh, NT_, D3_, D_);
        flash_kernel<<<dim3(S_/64, B_*H_), 128, SMEM_FLASH>>>(qh, ql, kh, vh, oh, ol);
        gemm_mma<1><<<dim3(D_/128, NT_/128), 256, SMEM_GEMM>>>(
            oh, ol, tph + (size_t)l * D_ * D_,
            proj_b + l * D_, h, h, nullptr, nullptr,
            nullptr, nullptr, nullptr, nullptr, NT_, D_, D_);
        ln_kernel<true><<<NT_/LNROWS, 256>>>(h, ln2_g + l * D_, ln2_b + l * D_, nullptr, ah, al);
        gemm_mma<2><<<dim3(DF_/128, NT_/128), 256, SMEM_GEMM>>>(
            ah, al, tfh + (size_t)l * DF_ * D_,
            fc_b + l * DF_, nullptr, nullptr, mh, ml,
            nullptr, nullptr, nullptr, nullptr, NT_, DF_, D_);
        gemm_mma<1><<<dim3(D_/128, NT_/128), 256, SMEM_GEMM>>>(
            mh, ml, t2h + (size_t)l * D_ * DF_,
            fc2_b + l * D_, h, h, nullptr, nullptr,
            nullptr, nullptr, nullptr, nullptr, NT_, D_, DF_);
    }
    ln_kernel<false><<<NT_/LNROWS, 256>>>(h, lnf_g, lnf_b, out, nullptr, nullptr);
}